// round 1
// baseline (speedup 1.0000x reference)
#include <cuda_runtime.h>

#define B_  2
#define S_  2048
#define DM  1024
#define H_  16
#define DK  64
#define DV  64
#define BS  (B_*S_)   // 4096 rows

// ---------------- scratch (device globals; no allocation allowed) ----------
__device__ float g_q [BS * DM];        // [4096, 1024]  (H*DK packed per row)
__device__ float g_k [BS * DK];        // [4096, 64]
__device__ float g_v [BS * DV];        // [4096, 64]
__device__ float g_ao[BS * H_ * DV];   // [4096, 1024]  row=(b*S+s), col=h*DV+d

// ---------------- generic tiled SGEMM: C[M,N] = A[M,K] @ W[K,N] ------------
// BM=BN=64, BK=16, 256 threads, 4x4 micro-tile per thread.
__global__ __launch_bounds__(256)
void sgemm64(const float* __restrict__ A, const float* __restrict__ W,
             float* __restrict__ C, int M, int N, int K)
{
    __shared__ float As[16][68];   // transposed: As[k][m], padded (16B-aligned rows)
    __shared__ float Bs[16][64];

    const int tid = threadIdx.x;
    const int tx  = tid & 15;          // 0..15 -> N
    const int ty  = tid >> 4;          // 0..15 -> M
    const int bm  = blockIdx.y * 64;
    const int bn  = blockIdx.x * 64;

    const int arow = tid >> 2;         // 0..63
    const int acol = (tid & 3) * 4;    // 0,4,8,12
    const int brow = tid >> 4;         // 0..15
    const int bcol = (tid & 15) * 4;   // 0..60

    float acc[4][4] = {};

    for (int k0 = 0; k0 < K; k0 += 16) {
        float4 a4 = *(const float4*)(A + (size_t)(bm + arow) * K + k0 + acol);
        As[acol + 0][arow] = a4.x;
        As[acol + 1][arow] = a4.y;
        As[acol + 2][arow] = a4.z;
        As[acol + 3][arow] = a4.w;
        *(float4*)&Bs[brow][bcol] =
            *(const float4*)(W + (size_t)(k0 + brow) * N + bn + bcol);
        __syncthreads();

        #pragma unroll
        for (int k = 0; k < 16; k++) {
            float4 av = *(const float4*)&As[k][ty * 4];
            float4 bv = *(const float4*)&Bs[k][tx * 4];
            float a_[4] = {av.x, av.y, av.z, av.w};
            float b_[4] = {bv.x, bv.y, bv.z, bv.w};
            #pragma unroll
            for (int i = 0; i < 4; i++)
                #pragma unroll
                for (int j = 0; j < 4; j++)
                    acc[i][j] += a_[i] * b_[j];
        }
        __syncthreads();
    }

    #pragma unroll
    for (int i = 0; i < 4; i++) {
        float4 o = make_float4(acc[i][0], acc[i][1], acc[i][2], acc[i][3]);
        *(float4*)(C + (size_t)(bm + ty * 4 + i) * N + bn + tx * 4) = o;
    }
}

// ---------------- causal MQA flash attention --------------------------------
// grid: (S/64, H, B), block: 64 threads. Thread t owns query row qb*64+t.
// q row + output acc live in registers; K/V streamed via smem in 32-row tiles;
// scores staged in padded smem (conflict-free own-row access).
#define KT 32

__global__ __launch_bounds__(64)
void mqa_attn(const float* __restrict__ gq, const float* __restrict__ gk,
              const float* __restrict__ gv, float* __restrict__ gao)
{
    __shared__ float kt[KT][64];
    __shared__ float vt[KT][64];
    __shared__ float st[64][KT + 1];

    const int qb  = blockIdx.x;
    const int h   = blockIdx.y;
    const int b   = blockIdx.z;
    const int tid = threadIdx.x;          // 0..63
    const int qi  = qb * 64 + tid;        // query row within sequence

    // load q row (64 floats) into registers
    const float* qrow = gq + ((size_t)(b * S_ + qi)) * DM + h * DK;
    float q[64];
    #pragma unroll
    for (int d = 0; d < 64; d += 4) {
        float4 t = *(const float4*)(qrow + d);
        q[d] = t.x; q[d+1] = t.y; q[d+2] = t.z; q[d+3] = t.w;
    }

    float acc[64];
    #pragma unroll
    for (int d = 0; d < 64; d++) acc[d] = 0.f;
    float m = -1e30f, l = 0.f;

    const int nkb = qb * 2 + 2;           // number of 32-row K tiles needed
    for (int kb = 0; kb < nkb; kb++) {
        // cooperative tile load: threads 0..31 -> K rows, 32..63 -> V rows
        {
            int r = tid & 31;
            int grow = kb * KT + r;
            if (tid < 32) {
                const float* src = gk + ((size_t)(b * S_ + grow)) * DK;
                #pragma unroll
                for (int d = 0; d < 64; d += 4)
                    *(float4*)&kt[r][d] = *(const float4*)(src + d);
            } else {
                const float* src = gv + ((size_t)(b * S_ + grow)) * DV;
                #pragma unroll
                for (int d = 0; d < 64; d += 4)
                    *(float4*)&vt[r][d] = *(const float4*)(src + d);
            }
        }
        __syncthreads();

        int jmax = qi - kb * KT + 1;      // causal limit within this tile
        if (jmax > KT) jmax = KT;

        // pass 1: scores for this tile (broadcast float4 reads of kt)
        float tmax = -1e30f;
        for (int j = 0; j < jmax; j++) {
            float s = 0.f;
            #pragma unroll
            for (int d = 0; d < 64; d += 4) {
                float4 k4 = *(const float4*)&kt[j][d];
                s += q[d]   * k4.x;
                s += q[d+1] * k4.y;
                s += q[d+2] * k4.z;
                s += q[d+3] * k4.w;
            }
            s *= 0.125f;                   // 1/sqrt(64)
            st[tid][j] = s;
            tmax = fmaxf(tmax, s);
        }

        if (jmax > 0) {
            float mnew = fmaxf(m, tmax);
            float corr = __expf(m - mnew);
            l *= corr;
            #pragma unroll
            for (int d = 0; d < 64; d++) acc[d] *= corr;

            // pass 2: probabilities + PV accumulation (broadcast float4 vt)
            for (int j = 0; j < jmax; j++) {
                float p = __expf(st[tid][j] - mnew);
                l += p;
                #pragma unroll
                for (int d = 0; d < 64; d += 4) {
                    float4 v4 = *(const float4*)&vt[j][d];
                    acc[d]   += p * v4.x;
                    acc[d+1] += p * v4.y;
                    acc[d+2] += p * v4.z;
                    acc[d+3] += p * v4.w;
                }
            }
            m = mnew;
        }
        __syncthreads();
    }

    const float inv = 1.f / l;
    float* orow = gao + ((size_t)(b * S_ + qi)) * (H_ * DV) + h * DV;
    #pragma unroll
    for (int d = 0; d < 64; d += 4) {
        float4 o = make_float4(acc[d] * inv, acc[d+1] * inv,
                               acc[d+2] * inv, acc[d+3] * inv);
        *(float4*)(orow + d) = o;
    }
}

// ---------------- launch ----------------------------------------------------
extern "C" void kernel_launch(void* const* d_in, const int* in_sizes, int n_in,
                              void* d_out, int out_size)
{
    const float* Q  = (const float*)d_in[0];
    const float* K  = (const float*)d_in[1];
    const float* V  = (const float*)d_in[2];
    const float* Wq = (const float*)d_in[3];
    const float* Wk = (const float*)d_in[4];
    const float* Wv = (const float*)d_in[5];
    const float* Wo = (const float*)d_in[6];
    float* out = (float*)d_out;

    float *gq, *gk, *gv, *gao;
    cudaGetSymbolAddress((void**)&gq,  g_q);
    cudaGetSymbolAddress((void**)&gk,  g_k);
    cudaGetSymbolAddress((void**)&gv,  g_v);
    cudaGetSymbolAddress((void**)&gao, g_ao);

    // projections
    sgemm64<<<dim3(DM / 64, BS / 64), 256>>>(Q, Wq, gq, BS, DM, DM);
    sgemm64<<<dim3(DK / 64, BS / 64), 256>>>(K, Wk, gk, BS, DK, DM);
    sgemm64<<<dim3(DV / 64, BS / 64), 256>>>(V, Wv, gv, BS, DV, DM);

    // causal MQA attention
    mqa_attn<<<dim3(S_ / 64, H_, B_), 64>>>(gq, gk, gv, gao);

    // output projection
    sgemm64<<<dim3(DM / 64, BS / 64), 256>>>(gao, Wo, out, BS, DM, DM);
}

// round 3
// speedup vs baseline: 1.1223x; 1.1223x over previous
#include <cuda_runtime.h>
#include <cstdint>

#define B_  2
#define S_  2048
#define DM  1024
#define H_  16
#define DK  64
#define DV  64
#define BS  (B_*S_)   // 4096

// ---------------- scratch ----------------------------------------------------
__device__ float g_q [BS * DM];
__device__ float g_k [BS * DK];
__device__ float g_v [BS * DV];
__device__ float g_ao[BS * DM];

// ---------------- tf32 helpers -----------------------------------------------
__device__ __forceinline__ void split3(float x, uint32_t &hi, uint32_t &lo) {
    uint32_t h;
    asm("cvt.rna.tf32.f32 %0, %1;" : "=r"(h) : "f"(x));
    float hf = __uint_as_float(h);
    float lf = x - hf;
    asm("cvt.rna.tf32.f32 %0, %1;" : "=r"(lo) : "f"(lf));
    hi = h;
}

__device__ __forceinline__ void mma_tf32(float* d, const uint32_t* a, const uint32_t* b) {
    asm volatile(
        "mma.sync.aligned.m16n8k8.row.col.f32.tf32.tf32.f32 "
        "{%0,%1,%2,%3},{%4,%5,%6,%7},{%8,%9},{%0,%1,%2,%3};"
        : "+f"(d[0]), "+f"(d[1]), "+f"(d[2]), "+f"(d[3])
        : "r"(a[0]), "r"(a[1]), "r"(a[2]), "r"(a[3]), "r"(b[0]), "r"(b[1]));
}

// ---------------- tf32x3 GEMM: C[M,N] = A[M,K] @ W[K,N] -----------------------
// BM=128, BN=128, BK=16, 256 threads (8 warps, 4x2), warp tile 32x64.
#define AST 20
#define BST 136

__global__ __launch_bounds__(256)
void gemm_tf32x3(const float* __restrict__ A, const float* __restrict__ W,
                 float* __restrict__ C, int M, int N, int K)
{
    __shared__ uint32_t sAh[128 * AST], sAl[128 * AST];
    __shared__ uint32_t sBh[16 * BST],  sBl[16 * BST];

    const int tid  = threadIdx.x;
    const int lane = tid & 31;
    const int wid  = tid >> 5;
    const int wm   = wid & 3;
    const int wn   = wid >> 2;
    const int bm   = blockIdx.y * 128;
    const int bn   = blockIdx.x * 128;

    float acc[2][8][4];
    #pragma unroll
    for (int i = 0; i < 2; i++)
        #pragma unroll
        for (int j = 0; j < 8; j++)
            #pragma unroll
            for (int t = 0; t < 4; t++) acc[i][j][t] = 0.f;

    for (int k0 = 0; k0 < K; k0 += 16) {
        #pragma unroll
        for (int i = 0; i < 2; i++) {
            int id = tid + 256 * i;
            int r  = id >> 2;
            int c  = (id & 3) << 2;
            float4 v = *(const float4*)(A + (size_t)(bm + r) * K + k0 + c);
            uint32_t h0,l0,h1,l1,h2,l2,h3,l3;
            split3(v.x, h0, l0); split3(v.y, h1, l1);
            split3(v.z, h2, l2); split3(v.w, h3, l3);
            uint32_t* ph = &sAh[r * AST + c];
            uint32_t* pl = &sAl[r * AST + c];
            ph[0] = h0; ph[1] = h1; ph[2] = h2; ph[3] = h3;
            pl[0] = l0; pl[1] = l1; pl[2] = l2; pl[3] = l3;
        }
        #pragma unroll
        for (int i = 0; i < 2; i++) {
            int id = tid + 256 * i;
            int r  = id >> 5;
            int c  = (id & 31) << 2;
            float4 v = *(const float4*)(W + (size_t)(k0 + r) * N + bn + c);
            uint32_t h0,l0,h1,l1,h2,l2,h3,l3;
            split3(v.x, h0, l0); split3(v.y, h1, l1);
            split3(v.z, h2, l2); split3(v.w, h3, l3);
            uint32_t* ph = &sBh[r * BST + c];
            uint32_t* pl = &sBl[r * BST + c];
            ph[0] = h0; ph[1] = h1; ph[2] = h2; ph[3] = h3;
            pl[0] = l0; pl[1] = l1; pl[2] = l2; pl[3] = l3;
        }
        __syncthreads();

        #pragma unroll
        for (int kk = 0; kk < 16; kk += 8) {
            uint32_t ah[2][4], al[2][4], bh[8][2], bl[8][2];
            #pragma unroll
            for (int mi = 0; mi < 2; mi++) {
                int r0 = wm * 32 + mi * 16 + (lane >> 2);
                int cc = kk + (lane & 3);
                ah[mi][0] = sAh[ r0      * AST + cc];
                ah[mi][1] = sAh[(r0 + 8) * AST + cc];
                ah[mi][2] = sAh[ r0      * AST + cc + 4];
                ah[mi][3] = sAh[(r0 + 8) * AST + cc + 4];
                al[mi][0] = sAl[ r0      * AST + cc];
                al[mi][1] = sAl[(r0 + 8) * AST + cc];
                al[mi][2] = sAl[ r0      * AST + cc + 4];
                al[mi][3] = sAl[(r0 + 8) * AST + cc + 4];
            }
            #pragma unroll
            for (int ni = 0; ni < 8; ni++) {
                int n = wn * 64 + ni * 8 + (lane >> 2);
                int r = kk + (lane & 3);
                bh[ni][0] = sBh[ r      * BST + n];
                bh[ni][1] = sBh[(r + 4) * BST + n];
                bl[ni][0] = sBl[ r      * BST + n];
                bl[ni][1] = sBl[(r + 4) * BST + n];
            }
            #pragma unroll
            for (int mi = 0; mi < 2; mi++)
                #pragma unroll
                for (int ni = 0; ni < 8; ni++) {
                    mma_tf32(acc[mi][ni], ah[mi], bh[ni]);
                    mma_tf32(acc[mi][ni], ah[mi], bl[ni]);
                    mma_tf32(acc[mi][ni], al[mi], bh[ni]);
                }
        }
        __syncthreads();
    }

    #pragma unroll
    for (int mi = 0; mi < 2; mi++) {
        int r0 = bm + wm * 32 + mi * 16 + (lane >> 2);
        #pragma unroll
        for (int ni = 0; ni < 8; ni++) {
            int c0 = bn + wn * 64 + ni * 8 + (lane & 3) * 2;
            *(float2*)(C + (size_t)r0 * N + c0)       = make_float2(acc[mi][ni][0], acc[mi][ni][1]);
            *(float2*)(C + (size_t)(r0 + 8) * N + c0) = make_float2(acc[mi][ni][2], acc[mi][ni][3]);
        }
    }
}

// ---------------- small fp32 SGEMM (K/V projections, N=64) --------------------
__global__ __launch_bounds__(256)
void sgemm64(const float* __restrict__ A, const float* __restrict__ W,
             float* __restrict__ C, int M, int N, int K)
{
    __shared__ float As[16][68];
    __shared__ float Bs[16][64];

    const int tid = threadIdx.x;
    const int tx  = tid & 15;
    const int ty  = tid >> 4;
    const int bm  = blockIdx.y * 64;
    const int bn  = blockIdx.x * 64;

    const int arow = tid >> 2;
    const int acol = (tid & 3) * 4;
    const int brow = tid >> 4;
    const int bcol = (tid & 15) * 4;

    float acc[4][4] = {};

    for (int k0 = 0; k0 < K; k0 += 16) {
        float4 a4 = *(const float4*)(A + (size_t)(bm + arow) * K + k0 + acol);
        As[acol + 0][arow] = a4.x;
        As[acol + 1][arow] = a4.y;
        As[acol + 2][arow] = a4.z;
        As[acol + 3][arow] = a4.w;
        *(float4*)&Bs[brow][bcol] =
            *(const float4*)(W + (size_t)(k0 + brow) * N + bn + bcol);
        __syncthreads();

        #pragma unroll
        for (int k = 0; k < 16; k++) {
            float4 av = *(const float4*)&As[k][ty * 4];
            float4 bv = *(const float4*)&Bs[k][tx * 4];
            float a_[4] = {av.x, av.y, av.z, av.w};
            float b_[4] = {bv.x, bv.y, bv.z, bv.w};
            #pragma unroll
            for (int i = 0; i < 4; i++)
                #pragma unroll
                for (int j = 0; j < 4; j++)
                    acc[i][j] += a_[i] * b_[j];
        }
        __syncthreads();
    }

    #pragma unroll
    for (int i = 0; i < 4; i++) {
        float4 o = make_float4(acc[i][0], acc[i][1], acc[i][2], acc[i][3]);
        *(float4*)(C + (size_t)(bm + ty * 4 + i) * N + bn + tx * 4) = o;
    }
}

// ---------------- causal MQA flash attention ----------------------------------
// grid: (S/64, H, B), block: 128 threads. Thread pair (2t, 2t+1) owns query
// row qb*64+t; each handles 32 of the 64 dims. Pair lanes share qi (and thus
// jmax), so the pair-restricted shuffle mask below is deadlock-free.
#define KT  32
#define KVS 72

__global__ __launch_bounds__(128)
void mqa_attn(const float* __restrict__ gq, const float* __restrict__ gk,
              const float* __restrict__ gv, float* __restrict__ gao)
{
    __shared__ float kt[KT][KVS];
    __shared__ float vt[KT][KVS];
    __shared__ float st[64][33];

    const int qb  = blockIdx.x;
    const int h   = blockIdx.y;
    const int b   = blockIdx.z;
    const int tid = threadIdx.x;
    const int lane = tid & 31;
    const int qr  = tid >> 1;
    const int hf  = tid & 1;
    const int qi  = qb * 64 + qr;
    const int hoff = hf * 36;
    // pair-restricted shuffle mask: only lanes {2k, 2k+1} participate
    const unsigned pmask = 0x3u << (lane & ~1);

    const float* qrow = gq + ((size_t)(b * S_ + qi)) * DM + h * DK + hf * 32;
    float q[32];
    #pragma unroll
    for (int d = 0; d < 32; d += 4) {
        float4 t = *(const float4*)(qrow + d);
        q[d] = t.x; q[d+1] = t.y; q[d+2] = t.z; q[d+3] = t.w;
    }

    float acc[32];
    #pragma unroll
    for (int d = 0; d < 32; d++) acc[d] = 0.f;
    float m = -1e30f, l = 0.f;

    const int nkb = qb * 2 + 2;
    for (int kb = 0; kb < nkb; kb++) {
        #pragma unroll
        for (int i = 0; i < 4; i++) {
            int id = tid + 128 * i;
            int r  = id >> 4;
            int c  = (id & 15) << 2;
            int cs = c + ((c >= 32) ? 4 : 0);
            *(float4*)&kt[r][cs] =
                *(const float4*)(gk + ((size_t)(b * S_ + kb * KT + r)) * DK + c);
            *(float4*)&vt[r][cs] =
                *(const float4*)(gv + ((size_t)(b * S_ + kb * KT + r)) * DV + c);
        }
        __syncthreads();

        int jmax = qi - kb * KT + 1;
        if (jmax > KT) jmax = KT;

        float tmax = -1e30f;
        for (int j = 0; j < jmax; j++) {
            float s0 = 0.f, s1 = 0.f, s2 = 0.f, s3 = 0.f;
            #pragma unroll
            for (int d = 0; d < 32; d += 4) {
                float4 kv = *(const float4*)&kt[j][hoff + d];
                s0 += q[d]   * kv.x;
                s1 += q[d+1] * kv.y;
                s2 += q[d+2] * kv.z;
                s3 += q[d+3] * kv.w;
            }
            float s = (s0 + s1) + (s2 + s3);
            s += __shfl_xor_sync(pmask, s, 1);
            s *= 0.125f;
            if (hf == 0) st[qr][j] = s;
            tmax = fmaxf(tmax, s);
        }
        __syncwarp();

        if (jmax > 0) {
            float mnew = fmaxf(m, tmax);
            float corr = __expf(m - mnew);
            l *= corr;
            #pragma unroll
            for (int d = 0; d < 32; d++) acc[d] *= corr;

            for (int j = 0; j < jmax; j++) {
                float p = __expf(st[qr][j] - mnew);
                l += p;
                #pragma unroll
                for (int d = 0; d < 32; d += 4) {
                    float4 vv = *(const float4*)&vt[j][hoff + d];
                    acc[d]   += p * vv.x;
                    acc[d+1] += p * vv.y;
                    acc[d+2] += p * vv.z;
                    acc[d+3] += p * vv.w;
                }
            }
            m = mnew;
        }
        __syncthreads();
    }

    const float inv = 1.f / l;
    float* orow = gao + ((size_t)(b * S_ + qi)) * DM + h * DV + hf * 32;
    #pragma unroll
    for (int d = 0; d < 32; d += 4) {
        *(float4*)(orow + d) = make_float4(acc[d] * inv, acc[d+1] * inv,
                                           acc[d+2] * inv, acc[d+3] * inv);
    }
}

// ---------------- launch -------------------------------------------------------
extern "C" void kernel_launch(void* const* d_in, const int* in_sizes, int n_in,
                              void* d_out, int out_size)
{
    const float* Q  = (const float*)d_in[0];
    const float* K  = (const float*)d_in[1];
    const float* V  = (const float*)d_in[2];
    const float* Wq = (const float*)d_in[3];
    const float* Wk = (const float*)d_in[4];
    const float* Wv = (const float*)d_in[5];
    const float* Wo = (const float*)d_in[6];
    float* out = (float*)d_out;

    float *gq, *gk, *gv, *gao;
    cudaGetSymbolAddress((void**)&gq,  g_q);
    cudaGetSymbolAddress((void**)&gk,  g_k);
    cudaGetSymbolAddress((void**)&gv,  g_v);
    cudaGetSymbolAddress((void**)&gao, g_ao);

    gemm_tf32x3<<<dim3(DM / 128, BS / 128), 256>>>(Q, Wq, gq, BS, DM, DM);
    sgemm64    <<<dim3(DK / 64,  BS / 64),  256>>>(K, Wk, gk, BS, DK, DM);
    sgemm64    <<<dim3(DV / 64,  BS / 64),  256>>>(V, Wv, gv, BS, DV, DM);

    mqa_attn<<<dim3(S_ / 64, H_, B_), 128>>>(gq, gk, gv, gao);

    gemm_tf32x3<<<dim3(DM / 128, BS / 128), 256>>>(gao, Wo, out, BS, DM, DM);
}

// round 4
// speedup vs baseline: 2.7554x; 2.4552x over previous
#include <cuda_runtime.h>
#include <cuda_bf16.h>
#include <cstdint>

#define B_  2
#define S_  2048
#define DM  1024
#define H_  16
#define DK  64
#define DV  64
#define BS  (B_*S_)   // 4096

// ---------------- scratch ----------------------------------------------------
__device__ float g_q [BS * DM];
__device__ float g_k [BS * DK];
__device__ float g_v [BS * DV];
__device__ float g_ao[BS * DM];
// bf16 hi/lo interleaved pairs: one uint2 = {hi(bf16 x2), lo(bf16 x2)} for 2 elems
__device__ uint2 g_kc[BS * DK / 2];            // K: row=(b,s), 32 uint2/row
__device__ uint2 g_vc[B_ * DV * (S_ / 2)];     // V^T: row=(b,d), 1024 uint2/row

// ---------------- tf32 helpers -----------------------------------------------
__device__ __forceinline__ void split3(float x, uint32_t &hi, uint32_t &lo) {
    uint32_t h;
    asm("cvt.rna.tf32.f32 %0, %1;" : "=r"(h) : "f"(x));
    float hf = __uint_as_float(h);
    float lf = x - hf;
    asm("cvt.rna.tf32.f32 %0, %1;" : "=r"(lo) : "f"(lf));
    hi = h;
}

__device__ __forceinline__ void mma_tf32(float* d, const uint32_t* a, const uint32_t* b) {
    asm volatile(
        "mma.sync.aligned.m16n8k8.row.col.f32.tf32.tf32.f32 "
        "{%0,%1,%2,%3},{%4,%5,%6,%7},{%8,%9},{%0,%1,%2,%3};"
        : "+f"(d[0]), "+f"(d[1]), "+f"(d[2]), "+f"(d[3])
        : "r"(a[0]), "r"(a[1]), "r"(a[2]), "r"(a[3]), "r"(b[0]), "r"(b[1]));
}

// ---------------- bf16 helpers -----------------------------------------------
__device__ __forceinline__ void mma_bf16(float* d, const uint32_t* a, const uint32_t* b) {
    asm volatile(
        "mma.sync.aligned.m16n8k16.row.col.f32.bf16.bf16.f32 "
        "{%0,%1,%2,%3},{%4,%5,%6,%7},{%8,%9},{%0,%1,%2,%3};"
        : "+f"(d[0]), "+f"(d[1]), "+f"(d[2]), "+f"(d[3])
        : "r"(a[0]), "r"(a[1]), "r"(a[2]), "r"(a[3]), "r"(b[0]), "r"(b[1]));
}

// pack (x,y) to bf16x2 hi; residual to bf16x2 lo
__device__ __forceinline__ uint32_t packsplit(float x, float y, uint32_t &lo) {
    __nv_bfloat162 h = __floats2bfloat162_rn(x, y);
    float hx = __bfloat162float(__low2bfloat16(h));
    float hy = __bfloat162float(__high2bfloat16(h));
    __nv_bfloat162 l2 = __floats2bfloat162_rn(x - hx, y - hy);
    lo = *reinterpret_cast<uint32_t*>(&l2);
    return *reinterpret_cast<uint32_t*>(&h);
}

// ---------------- tf32x3 GEMM (unchanged from R3) -----------------------------
#define AST 20
#define BST 136

__global__ __launch_bounds__(256)
void gemm_tf32x3(const float* __restrict__ A, const float* __restrict__ W,
                 float* __restrict__ C, int M, int N, int K)
{
    __shared__ uint32_t sAh[128 * AST], sAl[128 * AST];
    __shared__ uint32_t sBh[16 * BST],  sBl[16 * BST];

    const int tid  = threadIdx.x;
    const int lane = tid & 31;
    const int wid  = tid >> 5;
    const int wm   = wid & 3;
    const int wn   = wid >> 2;
    const int bm   = blockIdx.y * 128;
    const int bn   = blockIdx.x * 128;

    float acc[2][8][4];
    #pragma unroll
    for (int i = 0; i < 2; i++)
        #pragma unroll
        for (int j = 0; j < 8; j++)
            #pragma unroll
            for (int t = 0; t < 4; t++) acc[i][j][t] = 0.f;

    for (int k0 = 0; k0 < K; k0 += 16) {
        #pragma unroll
        for (int i = 0; i < 2; i++) {
            int id = tid + 256 * i;
            int r  = id >> 2;
            int c  = (id & 3) << 2;
            float4 v = *(const float4*)(A + (size_t)(bm + r) * K + k0 + c);
            uint32_t h0,l0,h1,l1,h2,l2,h3,l3;
            split3(v.x, h0, l0); split3(v.y, h1, l1);
            split3(v.z, h2, l2); split3(v.w, h3, l3);
            uint32_t* ph = &sAh[r * AST + c];
            uint32_t* pl = &sAl[r * AST + c];
            ph[0] = h0; ph[1] = h1; ph[2] = h2; ph[3] = h3;
            pl[0] = l0; pl[1] = l1; pl[2] = l2; pl[3] = l3;
        }
        #pragma unroll
        for (int i = 0; i < 2; i++) {
            int id = tid + 256 * i;
            int r  = id >> 5;
            int c  = (id & 31) << 2;
            float4 v = *(const float4*)(W + (size_t)(k0 + r) * N + bn + c);
            uint32_t h0,l0,h1,l1,h2,l2,h3,l3;
            split3(v.x, h0, l0); split3(v.y, h1, l1);
            split3(v.z, h2, l2); split3(v.w, h3, l3);
            uint32_t* ph = &sBh[r * BST + c];
            uint32_t* pl = &sBl[r * BST + c];
            ph[0] = h0; ph[1] = h1; ph[2] = h2; ph[3] = h3;
            pl[0] = l0; pl[1] = l1; pl[2] = l2; pl[3] = l3;
        }
        __syncthreads();

        #pragma unroll
        for (int kk = 0; kk < 16; kk += 8) {
            uint32_t ah[2][4], al[2][4], bh[8][2], bl[8][2];
            #pragma unroll
            for (int mi = 0; mi < 2; mi++) {
                int r0 = wm * 32 + mi * 16 + (lane >> 2);
                int cc = kk + (lane & 3);
                ah[mi][0] = sAh[ r0      * AST + cc];
                ah[mi][1] = sAh[(r0 + 8) * AST + cc];
                ah[mi][2] = sAh[ r0      * AST + cc + 4];
                ah[mi][3] = sAh[(r0 + 8) * AST + cc + 4];
                al[mi][0] = sAl[ r0      * AST + cc];
                al[mi][1] = sAl[(r0 + 8) * AST + cc];
                al[mi][2] = sAl[ r0      * AST + cc + 4];
                al[mi][3] = sAl[(r0 + 8) * AST + cc + 4];
            }
            #pragma unroll
            for (int ni = 0; ni < 8; ni++) {
                int n = wn * 64 + ni * 8 + (lane >> 2);
                int r = kk + (lane & 3);
                bh[ni][0] = sBh[ r      * BST + n];
                bh[ni][1] = sBh[(r + 4) * BST + n];
                bl[ni][0] = sBl[ r      * BST + n];
                bl[ni][1] = sBl[(r + 4) * BST + n];
            }
            #pragma unroll
            for (int mi = 0; mi < 2; mi++)
                #pragma unroll
                for (int ni = 0; ni < 8; ni++) {
                    mma_tf32(acc[mi][ni], ah[mi], bh[ni]);
                    mma_tf32(acc[mi][ni], ah[mi], bl[ni]);
                    mma_tf32(acc[mi][ni], al[mi], bh[ni]);
                }
        }
        __syncthreads();
    }

    #pragma unroll
    for (int mi = 0; mi < 2; mi++) {
        int r0 = bm + wm * 32 + mi * 16 + (lane >> 2);
        #pragma unroll
        for (int ni = 0; ni < 8; ni++) {
            int c0 = bn + wn * 64 + ni * 8 + (lane & 3) * 2;
            *(float2*)(C + (size_t)r0 * N + c0)       = make_float2(acc[mi][ni][0], acc[mi][ni][1]);
            *(float2*)(C + (size_t)(r0 + 8) * N + c0) = make_float2(acc[mi][ni][2], acc[mi][ni][3]);
        }
    }
}

// ---------------- small fp32 SGEMM (K/V projections, N=64) --------------------
__global__ __launch_bounds__(256)
void sgemm64(const float* __restrict__ A, const float* __restrict__ W,
             float* __restrict__ C, int M, int N, int K)
{
    __shared__ float As[16][68];
    __shared__ float Bs[16][64];

    const int tid = threadIdx.x;
    const int tx  = tid & 15;
    const int ty  = tid >> 4;
    const int bm  = blockIdx.y * 64;
    const int bn  = blockIdx.x * 64;

    const int arow = tid >> 2;
    const int acol = (tid & 3) * 4;
    const int brow = tid >> 4;
    const int bcol = (tid & 15) * 4;

    float acc[4][4] = {};

    for (int k0 = 0; k0 < K; k0 += 16) {
        float4 a4 = *(const float4*)(A + (size_t)(bm + arow) * K + k0 + acol);
        As[acol + 0][arow] = a4.x;
        As[acol + 1][arow] = a4.y;
        As[acol + 2][arow] = a4.z;
        As[acol + 3][arow] = a4.w;
        *(float4*)&Bs[brow][bcol] =
            *(const float4*)(W + (size_t)(k0 + brow) * N + bn + bcol);
        __syncthreads();

        #pragma unroll
        for (int k = 0; k < 16; k++) {
            float4 av = *(const float4*)&As[k][ty * 4];
            float4 bv = *(const float4*)&Bs[k][tx * 4];
            float a_[4] = {av.x, av.y, av.z, av.w};
            float b_[4] = {bv.x, bv.y, bv.z, bv.w};
            #pragma unroll
            for (int i = 0; i < 4; i++)
                #pragma unroll
                for (int j = 0; j < 4; j++)
                    acc[i][j] += a_[i] * b_[j];
        }
        __syncthreads();
    }

    #pragma unroll
    for (int i = 0; i < 4; i++) {
        float4 o = make_float4(acc[i][0], acc[i][1], acc[i][2], acc[i][3]);
        *(float4*)(C + (size_t)(bm + ty * 4 + i) * N + bn + tx * 4) = o;
    }
}

// ---------------- K/V bf16 hi/lo prep (V transposed) --------------------------
__global__ __launch_bounds__(256)
void conv_kv(const float* __restrict__ gk, const float* __restrict__ gv,
             uint2* __restrict__ kc, uint2* __restrict__ vc)
{
    int idx = blockIdx.x * blockDim.x + threadIdx.x;  // 0 .. BS*DK/2-1 (131072)
    if (idx >= BS * DK / 2) return;

    // K: straight pairs, coalesced
    float2 kp = ((const float2*)gk)[idx];
    uint32_t klo;
    uint32_t khi = packsplit(kp.x, kp.y, klo);
    kc[idx] = make_uint2(khi, klo);

    // V^T: idx -> (b, d, s-pair p); vc row = (b*DV + d), col = p
    int b = idx >> 16;            // 65536 per batch (64 * 1024)
    int r = idx & 65535;
    int d = r >> 10;
    int p = r & 1023;
    int s0 = 2 * p;
    float vx = gv[((size_t)(b * S_ + s0))     * DV + d];
    float vy = gv[((size_t)(b * S_ + s0 + 1)) * DV + d];
    uint32_t vlo;
    uint32_t vhi = packsplit(vx, vy, vlo);
    vc[idx] = make_uint2(vhi, vlo);
}

// ---------------- mma flash attention (bf16x3) --------------------------------
// grid (16, H, B): block handles 128 q-rows of one (b,h). 8 warps x 16 rows.
// KV tiles of 64. K smem [kv][dpair], V^T smem [d][kvpair], XOR-swizzled,
// {hi,lo} interleaved so one LDS.64 yields both halves of a B-frag element.
#define QB 128
#define KB 64

__global__ __launch_bounds__(256)
void mqa_attn_mma(const float* __restrict__ gq, float* __restrict__ gao)
{
    __shared__ __align__(16) uint2 sK[64 * 32];
    __shared__ __align__(16) uint2 sV[64 * 32];

    const int tid = threadIdx.x;
    const int l   = tid & 31;
    const int w   = tid >> 5;
    const int qb  = (S_ / QB - 1) - blockIdx.x;   // big workloads first
    const int h   = blockIdx.y;
    const int b   = blockIdx.z;

    const int rowbase = qb * QB + w * 16;
    const int r0 = rowbase + (l >> 2);
    const int r1 = r0 + 8;
    const int Xl = (l >> 2) << 2;   // swizzle term (row&7 == l>>2 for frag rows)

    // ---- persistent Q fragments (scaled by 1/sqrt(DK)), bf16 hi/lo ----
    uint32_t qh[4][4], ql[4][4];
    {
        const float* qbase = gq + ((size_t)(b * S_)) * DM + h * DK;
        #pragma unroll
        for (int ck = 0; ck < 4; ck++) {
            int d0 = 16 * ck + (l & 3) * 2;
            float2 v00 = *(const float2*)(qbase + (size_t)r0 * DM + d0);
            float2 v10 = *(const float2*)(qbase + (size_t)r1 * DM + d0);
            float2 v01 = *(const float2*)(qbase + (size_t)r0 * DM + d0 + 8);
            float2 v11 = *(const float2*)(qbase + (size_t)r1 * DM + d0 + 8);
            qh[ck][0] = packsplit(v00.x * 0.125f, v00.y * 0.125f, ql[ck][0]);
            qh[ck][1] = packsplit(v10.x * 0.125f, v10.y * 0.125f, ql[ck][1]);
            qh[ck][2] = packsplit(v01.x * 0.125f, v01.y * 0.125f, ql[ck][2]);
            qh[ck][3] = packsplit(v11.x * 0.125f, v11.y * 0.125f, ql[ck][3]);
        }
    }

    float O[8][4];
    #pragma unroll
    for (int t = 0; t < 8; t++)
        #pragma unroll
        for (int i = 0; i < 4; i++) O[t][i] = 0.f;
    float m0 = -1e30f, m1 = -1e30f, l0 = 0.f, l1 = 0.f;

    const uint4* ksrc = (const uint4*)g_kc;
    const uint4* vsrc = (const uint4*)g_vc;

    const int nkb = qb * 2 + 2;
    for (int kb = 0; kb < nkb; kb++) {
        // ---- stage K, V tiles (swizzled) ----
        #pragma unroll
        for (int i = 0; i < 4; i++) {
            int id = tid + 256 * i;        // 0..1023
            int r  = id >> 4;              // kv row (K) / d row (V)
            int j  = id & 15;              // uint4 within row
            int X  = (r & 7) << 2;
            int dg = (2 * j) ^ X;          // uint2 dst index (even)
            uint4 kq = ksrc[((size_t)(b * S_ + kb * KB + r)) * 16 + j];
            *(uint4*)&sK[r * 32 + dg] = kq;
            uint4 vq = vsrc[((size_t)(b * DV + r)) * (S_ / 4) + kb * 16 + j];
            *(uint4*)&sV[r * 32 + dg] = vq;
        }
        __syncthreads();

        // ---- S = Q K^T (bf16x3) ----
        float Sf[8][4];
        #pragma unroll
        for (int t = 0; t < 8; t++)
            #pragma unroll
            for (int i = 0; i < 4; i++) Sf[t][i] = 0.f;

        #pragma unroll
        for (int ck = 0; ck < 4; ck++) {
            #pragma unroll
            for (int t = 0; t < 8; t++) {
                int kv = 8 * t + (l >> 2);
                uint2 u0 = sK[kv * 32 + ((8 * ck + (l & 3)) ^ Xl)];
                uint2 u1 = sK[kv * 32 + ((8 * ck + 4 + (l & 3)) ^ Xl)];
                uint32_t bh[2] = {u0.x, u1.x};
                uint32_t bl[2] = {u0.y, u1.y};
                mma_bf16(Sf[t], qh[ck], bh);
                mma_bf16(Sf[t], ql[ck], bh);
                mma_bf16(Sf[t], qh[ck], bl);
            }
        }

        // ---- causal mask (diagonal tiles only) ----
        if (kb >= 2 * qb) {
            #pragma unroll
            for (int t = 0; t < 8; t++) {
                int c0 = kb * KB + 8 * t + (l & 3) * 2;
                if (c0     > r0) Sf[t][0] = -1e9f;
                if (c0 + 1 > r0) Sf[t][1] = -1e9f;
                if (c0     > r1) Sf[t][2] = -1e9f;
                if (c0 + 1 > r1) Sf[t][3] = -1e9f;
            }
        }

        // ---- online softmax ----
        float t0 = -1e30f, t1 = -1e30f;
        #pragma unroll
        for (int t = 0; t < 8; t++) {
            t0 = fmaxf(t0, fmaxf(Sf[t][0], Sf[t][1]));
            t1 = fmaxf(t1, fmaxf(Sf[t][2], Sf[t][3]));
        }
        t0 = fmaxf(t0, __shfl_xor_sync(0xffffffffu, t0, 1));
        t0 = fmaxf(t0, __shfl_xor_sync(0xffffffffu, t0, 2));
        t1 = fmaxf(t1, __shfl_xor_sync(0xffffffffu, t1, 1));
        t1 = fmaxf(t1, __shfl_xor_sync(0xffffffffu, t1, 2));

        float mn0 = fmaxf(m0, t0), mn1 = fmaxf(m1, t1);
        float c0 = __expf(m0 - mn0), c1 = __expf(m1 - mn1);

        float s0 = 0.f, s1 = 0.f;
        #pragma unroll
        for (int t = 0; t < 8; t++) {
            Sf[t][0] = __expf(Sf[t][0] - mn0);
            Sf[t][1] = __expf(Sf[t][1] - mn0);
            Sf[t][2] = __expf(Sf[t][2] - mn1);
            Sf[t][3] = __expf(Sf[t][3] - mn1);
            s0 += Sf[t][0] + Sf[t][1];
            s1 += Sf[t][2] + Sf[t][3];
        }
        s0 += __shfl_xor_sync(0xffffffffu, s0, 1);
        s0 += __shfl_xor_sync(0xffffffffu, s0, 2);
        s1 += __shfl_xor_sync(0xffffffffu, s1, 1);
        s1 += __shfl_xor_sync(0xffffffffu, s1, 2);

        l0 = l0 * c0 + s0;
        l1 = l1 * c1 + s1;
        m0 = mn0; m1 = mn1;

        #pragma unroll
        for (int t = 0; t < 8; t++) {
            O[t][0] *= c0; O[t][1] *= c0;
            O[t][2] *= c1; O[t][3] *= c1;
        }

        // ---- P fragments (register-exact C->A remap), bf16 hi/lo ----
        uint32_t ph[4][4], pl[4][4];
        #pragma unroll
        for (int ck = 0; ck < 4; ck++) {
            ph[ck][0] = packsplit(Sf[2*ck][0],   Sf[2*ck][1],   pl[ck][0]);
            ph[ck][1] = packsplit(Sf[2*ck][2],   Sf[2*ck][3],   pl[ck][1]);
            ph[ck][2] = packsplit(Sf[2*ck+1][0], Sf[2*ck+1][1], pl[ck][2]);
            ph[ck][3] = packsplit(Sf[2*ck+1][2], Sf[2*ck+1][3], pl[ck][3]);
        }

        // ---- O += P V (bf16x3) ----
        #pragma unroll
        for (int ck = 0; ck < 4; ck++) {
            #pragma unroll
            for (int td = 0; td < 8; td++) {
                int d = 8 * td + (l >> 2);
                uint2 u0 = sV[d * 32 + ((8 * ck + (l & 3)) ^ Xl)];
                uint2 u1 = sV[d * 32 + ((8 * ck + 4 + (l & 3)) ^ Xl)];
                uint32_t vh[2] = {u0.x, u1.x};
                uint32_t vl[2] = {u0.y, u1.y};
                mma_bf16(O[td], ph[ck], vh);
                mma_bf16(O[td], pl[ck], vh);
                mma_bf16(O[td], ph[ck], vl);
            }
        }
        __syncthreads();
    }

    // ---- epilogue ----
    const float inv0 = 1.f / l0, inv1 = 1.f / l1;
    float* ob = gao + ((size_t)(b * S_)) * DM + h * DV;
    #pragma unroll
    for (int td = 0; td < 8; td++) {
        int d0 = 8 * td + (l & 3) * 2;
        *(float2*)(ob + (size_t)r0 * DM + d0) = make_float2(O[td][0] * inv0, O[td][1] * inv0);
        *(float2*)(ob + (size_t)r1 * DM + d0) = make_float2(O[td][2] * inv1, O[td][3] * inv1);
    }
}

// ---------------- launch -------------------------------------------------------
extern "C" void kernel_launch(void* const* d_in, const int* in_sizes, int n_in,
                              void* d_out, int out_size)
{
    const float* Q  = (const float*)d_in[0];
    const float* K  = (const float*)d_in[1];
    const float* V  = (const float*)d_in[2];
    const float* Wq = (const float*)d_in[3];
    const float* Wk = (const float*)d_in[4];
    const float* Wv = (const float*)d_in[5];
    const float* Wo = (const float*)d_in[6];
    float* out = (float*)d_out;

    float *gq, *gk, *gv, *gao;
    uint2 *kc, *vc;
    cudaGetSymbolAddress((void**)&gq,  g_q);
    cudaGetSymbolAddress((void**)&gk,  g_k);
    cudaGetSymbolAddress((void**)&gv,  g_v);
    cudaGetSymbolAddress((void**)&gao, g_ao);
    cudaGetSymbolAddress((void**)&kc,  g_kc);
    cudaGetSymbolAddress((void**)&vc,  g_vc);

    gemm_tf32x3<<<dim3(DM / 128, BS / 128), 256>>>(Q, Wq, gq, BS, DM, DM);
    sgemm64    <<<dim3(DK / 64,  BS / 64),  256>>>(K, Wk, gk, BS, DK, DM);
    sgemm64    <<<dim3(DV / 64,  BS / 64),  256>>>(V, Wv, gv, BS, DV, DM);

    conv_kv<<<(BS * DK / 2 + 255) / 256, 256>>>(gk, gv, kc, vc);

    mqa_attn_mma<<<dim3(S_ / QB, H_, B_), 256>>>(gq, gao);

    gemm_tf32x3<<<dim3(DM / 128, BS / 128), 256>>>(gao, Wo, out, BS, DM, DM);
}

// round 5
// speedup vs baseline: 3.5738x; 1.2970x over previous
#include <cuda_runtime.h>
#include <cuda_bf16.h>
#include <cstdint>

#define B_  2
#define S_  2048
#define DM  1024
#define H_  16
#define DK  64
#define DV  64
#define BS  (B_*S_)   // 4096

// ---------------- scratch ----------------------------------------------------
__device__ float g_q [BS * DM];                // Q-proj output (fp32, read by attn)
__device__ float g_k [BS * DK];
__device__ float g_v [BS * DV];
__device__ uint2 g_qc [BS * DM / 2];           // input Q as bf16 hi/lo pairs
__device__ uint2 g_wqt[DM * DM / 2];           // W_q^T [N][K/2] pairs
__device__ uint2 g_wot[DM * DM / 2];           // W_o^T [N][K/2] pairs
__device__ uint2 g_aoc[BS * DM / 2];           // attention out as pairs (O-proj A)
__device__ uint2 g_kc[BS * DK / 2];            // K pairs, row=(b,s)
__device__ uint2 g_vc[B_ * DV * (S_ / 2)];     // V^T pairs, row=(b,d)

// ---------------- helpers ------------------------------------------------------
__device__ __forceinline__ void mma_bf16(float* d, const uint32_t* a, const uint32_t* b) {
    asm volatile(
        "mma.sync.aligned.m16n8k16.row.col.f32.bf16.bf16.f32 "
        "{%0,%1,%2,%3},{%4,%5,%6,%7},{%8,%9},{%0,%1,%2,%3};"
        : "+f"(d[0]), "+f"(d[1]), "+f"(d[2]), "+f"(d[3])
        : "r"(a[0]), "r"(a[1]), "r"(a[2]), "r"(a[3]), "r"(b[0]), "r"(b[1]));
}

// pack (x,y) to bf16x2 hi; residual to bf16x2 lo
__device__ __forceinline__ uint32_t packsplit(float x, float y, uint32_t &lo) {
    __nv_bfloat162 h = __floats2bfloat162_rn(x, y);
    float hx = __bfloat162float(__low2bfloat16(h));
    float hy = __bfloat162float(__high2bfloat16(h));
    __nv_bfloat162 l2 = __floats2bfloat162_rn(x - hx, y - hy);
    lo = *reinterpret_cast<uint32_t*>(&l2);
    return *reinterpret_cast<uint32_t*>(&h);
}

__device__ __forceinline__ void cp_async16(void* smem, const void* gmem) {
    uint32_t s = (uint32_t)__cvta_generic_to_shared(smem);
    asm volatile("cp.async.cg.shared.global [%0], [%1], 16;" :: "r"(s), "l"(gmem));
}

// ---------------- conversion kernels -------------------------------------------
// row-major fp32 -> row-major bf16 hi/lo pairs (coalesced both sides)
__global__ __launch_bounds__(256)
void conv_a(const float* __restrict__ A, uint2* __restrict__ Ac, int npairs)
{
    int idx = blockIdx.x * blockDim.x + threadIdx.x;
    if (idx >= npairs) return;
    float2 p = ((const float2*)A)[idx];
    uint32_t lo;
    uint32_t hi = packsplit(p.x, p.y, lo);
    Ac[idx] = make_uint2(hi, lo);
}

// W [K][N] fp32 -> Wt [N][K/2] pairs (coalesced reads, scattered 8B writes)
__global__ __launch_bounds__(256)
void conv_wt(const float* __restrict__ W, uint2* __restrict__ Wt, int K, int N)
{
    int idx = blockIdx.x * blockDim.x + threadIdx.x;   // p * N + n
    if (idx >= N * (K / 2)) return;
    int p = idx / N;
    int n = idx - p * N;
    float x = W[(size_t)(2 * p)     * N + n];
    float y = W[(size_t)(2 * p + 1) * N + n];
    uint32_t lo;
    uint32_t hi = packsplit(x, y, lo);
    Wt[(size_t)n * (K / 2) + p] = make_uint2(hi, lo);
}

// ---------------- bf16x3 double-buffered GEMM ----------------------------------
// C[M,N] = A[M,K] @ W[K,N]; A as pairs [M][K/2], W pre-transposed pairs [N][K/2].
// BM=128, BN=64, BK=32, 256 thr (8 warps 4x2, warp tile 32x32), cp.async 2-stage.
#define GBM 128
#define GBN 64
#define GBK 32

__global__ __launch_bounds__(256)
void gemm_bf16x3(const uint2* __restrict__ Ac, const uint2* __restrict__ Bt,
                 float* __restrict__ C, int M, int N, int K)
{
    __shared__ uint2 sA[2][128][16];   // [buf][m][kpair]  16KB/stage
    __shared__ uint2 sB[2][64][16];    // [buf][n][kpair]   8KB/stage

    const int tid  = threadIdx.x;
    const int lane = tid & 31;
    const int w    = tid >> 5;
    const int wm   = w & 3;
    const int wn   = w >> 2;
    const int bm   = blockIdx.y * GBM;
    const int bn   = blockIdx.x * GBN;
    const int Kp   = K >> 2;           // uint4 per row

    const uint4* Aq = (const uint4*)Ac;
    const uint4* Bq = (const uint4*)Bt;

    float acc[2][4][4];
    #pragma unroll
    for (int i = 0; i < 2; i++)
        #pragma unroll
        for (int j = 0; j < 4; j++)
            #pragma unroll
            for (int t = 0; t < 4; t++) acc[i][j][t] = 0.f;

    const int e = lane & 3;
    const int q = lane >> 2;

    #define STAGE(buf, k0)                                                        \
    {                                                                             \
        int kq = (k0) >> 2;                                                       \
        _Pragma("unroll")                                                         \
        for (int i = 0; i < 4; i++) {                                             \
            int id = tid + 256 * i;                                               \
            int r = id >> 3, j = id & 7;                                          \
            int dst = (2 * j) ^ ((r & 3) << 2);                                   \
            cp_async16(&sA[buf][r][dst], &Aq[(size_t)(bm + r) * Kp + kq + j]);    \
        }                                                                         \
        _Pragma("unroll")                                                         \
        for (int i = 0; i < 2; i++) {                                             \
            int id = tid + 256 * i;                                               \
            int r = id >> 3, j = id & 7;                                          \
            int dst = (2 * j) ^ ((r & 3) << 2);                                   \
            cp_async16(&sB[buf][r][dst], &Bq[(size_t)(bn + r) * Kp + kq + j]);    \
        }                                                                         \
        asm volatile("cp.async.commit_group;");                                   \
    }

    const int niter = K / GBK;
    STAGE(0, 0);

    for (int it = 0; it < niter; it++) {
        if (it + 1 < niter) {
            STAGE((it + 1) & 1, (it + 1) * GBK);
            asm volatile("cp.async.wait_group 1;");
        } else {
            asm volatile("cp.async.wait_group 0;");
        }
        __syncthreads();

        const int buf = it & 1;
        #pragma unroll
        for (int kk = 0; kk < 2; kk++) {
            int c0 = kk * 8 + e;
            uint32_t ah[2][4], al[2][4];
            #pragma unroll
            for (int mi = 0; mi < 2; mi++) {
                int r  = wm * 32 + mi * 16 + q;
                int r8 = r + 8;
                uint2 u0 = sA[buf][r ][ c0      ^ ((r  & 3) << 2)];
                uint2 u1 = sA[buf][r8][ c0      ^ ((r8 & 3) << 2)];
                uint2 u2 = sA[buf][r ][(c0 + 4) ^ ((r  & 3) << 2)];
                uint2 u3 = sA[buf][r8][(c0 + 4) ^ ((r8 & 3) << 2)];
                ah[mi][0] = u0.x; al[mi][0] = u0.y;
                ah[mi][1] = u1.x; al[mi][1] = u1.y;
                ah[mi][2] = u2.x; al[mi][2] = u2.y;
                ah[mi][3] = u3.x; al[mi][3] = u3.y;
            }
            #pragma unroll
            for (int ni = 0; ni < 4; ni++) {
                int n = wn * 32 + ni * 8 + q;
                uint2 v0 = sB[buf][n][ c0      ^ ((n & 3) << 2)];
                uint2 v1 = sB[buf][n][(c0 + 4) ^ ((n & 3) << 2)];
                uint32_t bh[2] = {v0.x, v1.x};
                uint32_t bl[2] = {v0.y, v1.y};
                #pragma unroll
                for (int mi = 0; mi < 2; mi++) {
                    mma_bf16(acc[mi][ni], ah[mi], bh);
                    mma_bf16(acc[mi][ni], al[mi], bh);
                    mma_bf16(acc[mi][ni], ah[mi], bl);
                }
            }
        }
        __syncthreads();
    }

    #pragma unroll
    for (int mi = 0; mi < 2; mi++) {
        int r = bm + wm * 32 + mi * 16 + q;
        #pragma unroll
        for (int ni = 0; ni < 4; ni++) {
            int c = bn + wn * 32 + ni * 8 + e * 2;
            *(float2*)(C + (size_t)r * N + c)       = make_float2(acc[mi][ni][0], acc[mi][ni][1]);
            *(float2*)(C + (size_t)(r + 8) * N + c) = make_float2(acc[mi][ni][2], acc[mi][ni][3]);
        }
    }
    #undef STAGE
}

// ---------------- fused K/V projection (fp32, N=64) ----------------------------
// blockIdx.z: 0 -> K@Wk -> g_k, 1 -> V@Wv -> g_v. One wave instead of two.
__global__ __launch_bounds__(256)
void sgemm_kv(const float* __restrict__ Kin, const float* __restrict__ Wk,
              const float* __restrict__ Vin, const float* __restrict__ Wv,
              float* __restrict__ Ck, float* __restrict__ Cv)
{
    __shared__ float As[16][68];
    __shared__ float Bs[16][64];

    const float* A = blockIdx.z ? Vin : Kin;
    const float* W = blockIdx.z ? Wv  : Wk;
    float*       C = blockIdx.z ? Cv  : Ck;
    const int N = 64, K = DM;

    const int tid = threadIdx.x;
    const int tx  = tid & 15;
    const int ty  = tid >> 4;
    const int bm  = blockIdx.y * 64;

    const int arow = tid >> 2;
    const int acol = (tid & 3) * 4;
    const int brow = tid >> 4;
    const int bcol = (tid & 15) * 4;

    float acc[4][4] = {};

    for (int k0 = 0; k0 < K; k0 += 16) {
        float4 a4 = *(const float4*)(A + (size_t)(bm + arow) * K + k0 + acol);
        As[acol + 0][arow] = a4.x;
        As[acol + 1][arow] = a4.y;
        As[acol + 2][arow] = a4.z;
        As[acol + 3][arow] = a4.w;
        *(float4*)&Bs[brow][bcol] =
            *(const float4*)(W + (size_t)(k0 + brow) * N + bcol);
        __syncthreads();

        #pragma unroll
        for (int k = 0; k < 16; k++) {
            float4 av = *(const float4*)&As[k][ty * 4];
            float4 bv = *(const float4*)&Bs[k][tx * 4];
            float a_[4] = {av.x, av.y, av.z, av.w};
            float b_[4] = {bv.x, bv.y, bv.z, bv.w};
            #pragma unroll
            for (int i = 0; i < 4; i++)
                #pragma unroll
                for (int j = 0; j < 4; j++)
                    acc[i][j] += a_[i] * b_[j];
        }
        __syncthreads();
    }

    #pragma unroll
    for (int i = 0; i < 4; i++) {
        float4 o = make_float4(acc[i][0], acc[i][1], acc[i][2], acc[i][3]);
        *(float4*)(C + (size_t)(bm + ty * 4 + i) * N + tx * 4) = o;
    }
}

// ---------------- K/V bf16 hi/lo prep (V transposed) ---------------------------
__global__ __launch_bounds__(256)
void conv_kv(const float* __restrict__ gk, const float* __restrict__ gv,
             uint2* __restrict__ kc, uint2* __restrict__ vc)
{
    int idx = blockIdx.x * blockDim.x + threadIdx.x;
    if (idx >= BS * DK / 2) return;

    float2 kp = ((const float2*)gk)[idx];
    uint32_t klo;
    uint32_t khi = packsplit(kp.x, kp.y, klo);
    kc[idx] = make_uint2(khi, klo);

    int b = idx >> 16;
    int r = idx & 65535;
    int d = r >> 10;
    int p = r & 1023;
    int s0 = 2 * p;
    float vx = gv[((size_t)(b * S_ + s0))     * DV + d];
    float vy = gv[((size_t)(b * S_ + s0 + 1)) * DV + d];
    uint32_t vlo;
    uint32_t vhi = packsplit(vx, vy, vlo);
    vc[idx] = make_uint2(vhi, vlo);
}

// ---------------- mma flash attention (bf16x3) ---------------------------------
#define QB 128
#define KB 64

__global__ __launch_bounds__(256)
void mqa_attn_mma(const float* __restrict__ gq, uint2* __restrict__ aoc)
{
    __shared__ __align__(16) uint2 sK[64 * 32];
    __shared__ __align__(16) uint2 sV[64 * 32];

    const int tid = threadIdx.x;
    const int l   = tid & 31;
    const int w   = tid >> 5;
    const int qb  = (S_ / QB - 1) - blockIdx.x;
    const int h   = blockIdx.y;
    const int b   = blockIdx.z;

    const int rowbase = qb * QB + w * 16;
    const int r0 = rowbase + (l >> 2);
    const int r1 = r0 + 8;
    const int Xl = (l >> 2) << 2;

    uint32_t qh[4][4], ql[4][4];
    {
        const float* qbase = gq + ((size_t)(b * S_)) * DM + h * DK;
        #pragma unroll
        for (int ck = 0; ck < 4; ck++) {
            int d0 = 16 * ck + (l & 3) * 2;
            float2 v00 = *(const float2*)(qbase + (size_t)r0 * DM + d0);
            float2 v10 = *(const float2*)(qbase + (size_t)r1 * DM + d0);
            float2 v01 = *(const float2*)(qbase + (size_t)r0 * DM + d0 + 8);
            float2 v11 = *(const float2*)(qbase + (size_t)r1 * DM + d0 + 8);
            qh[ck][0] = packsplit(v00.x * 0.125f, v00.y * 0.125f, ql[ck][0]);
            qh[ck][1] = packsplit(v10.x * 0.125f, v10.y * 0.125f, ql[ck][1]);
            qh[ck][2] = packsplit(v01.x * 0.125f, v01.y * 0.125f, ql[ck][2]);
            qh[ck][3] = packsplit(v11.x * 0.125f, v11.y * 0.125f, ql[ck][3]);
        }
    }

    float O[8][4];
    #pragma unroll
    for (int t = 0; t < 8; t++)
        #pragma unroll
        for (int i = 0; i < 4; i++) O[t][i] = 0.f;
    float m0 = -1e30f, m1 = -1e30f, l0 = 0.f, l1 = 0.f;

    const uint4* ksrc = (const uint4*)g_kc;
    const uint4* vsrc = (const uint4*)g_vc;

    const int nkb = qb * 2 + 2;
    for (int kb = 0; kb < nkb; kb++) {
        #pragma unroll
        for (int i = 0; i < 4; i++) {
            int id = tid + 256 * i;
            int r  = id >> 4;
            int j  = id & 15;
            int X  = (r & 7) << 2;
            int dg = (2 * j) ^ X;
            uint4 kq = ksrc[((size_t)(b * S_ + kb * KB + r)) * 16 + j];
            *(uint4*)&sK[r * 32 + dg] = kq;
            uint4 vq = vsrc[((size_t)(b * DV + r)) * (S_ / 4) + kb * 16 + j];
            *(uint4*)&sV[r * 32 + dg] = vq;
        }
        __syncthreads();

        float Sf[8][4];
        #pragma unroll
        for (int t = 0; t < 8; t++)
            #pragma unroll
            for (int i = 0; i < 4; i++) Sf[t][i] = 0.f;

        #pragma unroll
        for (int ck = 0; ck < 4; ck++) {
            #pragma unroll
            for (int t = 0; t < 8; t++) {
                int kv = 8 * t + (l >> 2);
                uint2 u0 = sK[kv * 32 + ((8 * ck + (l & 3)) ^ Xl)];
                uint2 u1 = sK[kv * 32 + ((8 * ck + 4 + (l & 3)) ^ Xl)];
                uint32_t bh[2] = {u0.x, u1.x};
                uint32_t bl[2] = {u0.y, u1.y};
                mma_bf16(Sf[t], qh[ck], bh);
                mma_bf16(Sf[t], ql[ck], bh);
                mma_bf16(Sf[t], qh[ck], bl);
            }
        }

        if (kb >= 2 * qb) {
            #pragma unroll
            for (int t = 0; t < 8; t++) {
                int c0 = kb * KB + 8 * t + (l & 3) * 2;
                if (c0     > r0) Sf[t][0] = -1e9f;
                if (c0 + 1 > r0) Sf[t][1] = -1e9f;
                if (c0     > r1) Sf[t][2] = -1e9f;
                if (c0 + 1 > r1) Sf[t][3] = -1e9f;
            }
        }

        float t0 = -1e30f, t1 = -1e30f;
        #pragma unroll
        for (int t = 0; t < 8; t++) {
            t0 = fmaxf(t0, fmaxf(Sf[t][0], Sf[t][1]));
            t1 = fmaxf(t1, fmaxf(Sf[t][2], Sf[t][3]));
        }
        t0 = fmaxf(t0, __shfl_xor_sync(0xffffffffu, t0, 1));
        t0 = fmaxf(t0, __shfl_xor_sync(0xffffffffu, t0, 2));
        t1 = fmaxf(t1, __shfl_xor_sync(0xffffffffu, t1, 1));
        t1 = fmaxf(t1, __shfl_xor_sync(0xffffffffu, t1, 2));

        float mn0 = fmaxf(m0, t0), mn1 = fmaxf(m1, t1);
        float c0 = __expf(m0 - mn0), c1 = __expf(m1 - mn1);

        float s0 = 0.f, s1 = 0.f;
        #pragma unroll
        for (int t = 0; t < 8; t++) {
            Sf[t][0] = __expf(Sf[t][0] - mn0);
            Sf[t][1] = __expf(Sf[t][1] - mn0);
            Sf[t][2] = __expf(Sf[t][2] - mn1);
            Sf[t][3] = __expf(Sf[t][3] - mn1);
            s0 += Sf[t][0] + Sf[t][1];
            s1 += Sf[t][2] + Sf[t][3];
        }
        s0 += __shfl_xor_sync(0xffffffffu, s0, 1);
        s0 += __shfl_xor_sync(0xffffffffu, s0, 2);
        s1 += __shfl_xor_sync(0xffffffffu, s1, 1);
        s1 += __shfl_xor_sync(0xffffffffu, s1, 2);

        l0 = l0 * c0 + s0;
        l1 = l1 * c1 + s1;
        m0 = mn0; m1 = mn1;

        #pragma unroll
        for (int t = 0; t < 8; t++) {
            O[t][0] *= c0; O[t][1] *= c0;
            O[t][2] *= c1; O[t][3] *= c1;
        }

        uint32_t ph[4][4], pl[4][4];
        #pragma unroll
        for (int ck = 0; ck < 4; ck++) {
            ph[ck][0] = packsplit(Sf[2*ck][0],   Sf[2*ck][1],   pl[ck][0]);
            ph[ck][1] = packsplit(Sf[2*ck][2],   Sf[2*ck][3],   pl[ck][1]);
            ph[ck][2] = packsplit(Sf[2*ck+1][0], Sf[2*ck+1][1], pl[ck][2]);
            ph[ck][3] = packsplit(Sf[2*ck+1][2], Sf[2*ck+1][3], pl[ck][3]);
        }

        #pragma unroll
        for (int ck = 0; ck < 4; ck++) {
            #pragma unroll
            for (int td = 0; td < 8; td++) {
                int d = 8 * td + (l >> 2);
                uint2 u0 = sV[d * 32 + ((8 * ck + (l & 3)) ^ Xl)];
                uint2 u1 = sV[d * 32 + ((8 * ck + 4 + (l & 3)) ^ Xl)];
                uint32_t vh[2] = {u0.x, u1.x};
                uint32_t vl[2] = {u0.y, u1.y};
                mma_bf16(O[td], ph[ck], vh);
                mma_bf16(O[td], pl[ck], vh);
                mma_bf16(O[td], ph[ck], vl);
            }
        }
        __syncthreads();
    }

    // epilogue: write bf16 hi/lo pairs directly (feeds the O-proj GEMM)
    const float inv0 = 1.f / l0, inv1 = 1.f / l1;
    #pragma unroll
    for (int td = 0; td < 8; td++) {
        int d0 = 8 * td + (l & 3) * 2;
        int cp = (h * DV + d0) >> 1;
        uint32_t lo0, lo1;
        uint32_t hi0 = packsplit(O[td][0] * inv0, O[td][1] * inv0, lo0);
        uint32_t hi1 = packsplit(O[td][2] * inv1, O[td][3] * inv1, lo1);
        aoc[(size_t)(b * S_ + r0) * (DM / 2) + cp] = make_uint2(hi0, lo0);
        aoc[(size_t)(b * S_ + r1) * (DM / 2) + cp] = make_uint2(hi1, lo1);
    }
}

// ---------------- launch ---------------------------------------------------------
extern "C" void kernel_launch(void* const* d_in, const int* in_sizes, int n_in,
                              void* d_out, int out_size)
{
    const float* Q  = (const float*)d_in[0];
    const float* K  = (const float*)d_in[1];
    const float* V  = (const float*)d_in[2];
    const float* Wq = (const float*)d_in[3];
    const float* Wk = (const float*)d_in[4];
    const float* Wv = (const float*)d_in[5];
    const float* Wo = (const float*)d_in[6];
    float* out = (float*)d_out;

    float *gq, *gk, *gv;
    uint2 *qc, *wqt, *wot, *aoc, *kc, *vc;
    cudaGetSymbolAddress((void**)&gq,  g_q);
    cudaGetSymbolAddress((void**)&gk,  g_k);
    cudaGetSymbolAddress((void**)&gv,  g_v);
    cudaGetSymbolAddress((void**)&qc,  g_qc);
    cudaGetSymbolAddress((void**)&wqt, g_wqt);
    cudaGetSymbolAddress((void**)&wot, g_wot);
    cudaGetSymbolAddress((void**)&aoc, g_aoc);
    cudaGetSymbolAddress((void**)&kc,  g_kc);
    cudaGetSymbolAddress((void**)&vc,  g_vc);

    // conversions
    conv_a <<<(BS * DM / 2 + 255) / 256, 256>>>(Q, qc, BS * DM / 2);
    conv_wt<<<(DM * DM / 2 + 255) / 256, 256>>>(Wq, wqt, DM, DM);
    conv_wt<<<(DM * DM / 2 + 255) / 256, 256>>>(Wo, wot, DM, DM);

    // Q projection (bf16x3 tensor cores)
    gemm_bf16x3<<<dim3(DM / GBN, BS / GBM), 256>>>(qc, wqt, gq, BS, DM, DM);

    // K/V projections (fused, fp32)
    sgemm_kv<<<dim3(1, BS / 64, 2), 256>>>(K, Wk, V, Wv, gk, gv);
    conv_kv<<<(BS * DK / 2 + 255) / 256, 256>>>(gk, gv, kc, vc);

    // attention (writes bf16 pairs for O-proj)
    mqa_attn_mma<<<dim3(S_ / QB, H_, B_), 256>>>(gq, aoc);

    // output projection (bf16x3 tensor cores)
    gemm_bf16x3<<<dim3(DM / GBN, BS / GBM), 256>>>(aoc, wot, out, BS, DM, DM);
}

// round 6
// speedup vs baseline: 3.8179x; 1.0683x over previous
#include <cuda_runtime.h>
#include <cuda_bf16.h>
#include <cstdint>

#define B_  2
#define S_  2048
#define DM  1024
#define H_  16
#define DK  64
#define DV  64
#define BS  (B_*S_)   // 4096

// ---------------- scratch ----------------------------------------------------
__device__ float g_q [BS * DM];                // Q-proj output (fp32, read by attn)
__device__ float g_k [BS * DK];
__device__ float g_v [BS * DV];
__device__ uint2 g_qc [BS * DM / 2];           // input Q as bf16 hi/lo pairs
__device__ uint2 g_wqt[DM * DM / 2];           // W_q^T [N][K/2] pairs
__device__ uint2 g_wot[DM * DM / 2];           // W_o^T [N][K/2] pairs
__device__ uint2 g_aoc[BS * DM / 2];           // attention out as pairs (O-proj A)
__device__ uint2 g_kc[BS * DK / 2];            // K pairs, row=(b,s)
__device__ uint2 g_vc[B_ * DV * (S_ / 2)];     // V^T pairs, row=(b,d)

// ---------------- helpers ------------------------------------------------------
__device__ __forceinline__ void mma_bf16(float* d, const uint32_t* a, const uint32_t* b) {
    asm volatile(
        "mma.sync.aligned.m16n8k16.row.col.f32.bf16.bf16.f32 "
        "{%0,%1,%2,%3},{%4,%5,%6,%7},{%8,%9},{%0,%1,%2,%3};"
        : "+f"(d[0]), "+f"(d[1]), "+f"(d[2]), "+f"(d[3])
        : "r"(a[0]), "r"(a[1]), "r"(a[2]), "r"(a[3]), "r"(b[0]), "r"(b[1]));
}

__device__ __forceinline__ uint32_t packsplit(float x, float y, uint32_t &lo) {
    __nv_bfloat162 h = __floats2bfloat162_rn(x, y);
    float hx = __bfloat162float(__low2bfloat16(h));
    float hy = __bfloat162float(__high2bfloat16(h));
    __nv_bfloat162 l2 = __floats2bfloat162_rn(x - hx, y - hy);
    lo = *reinterpret_cast<uint32_t*>(&l2);
    return *reinterpret_cast<uint32_t*>(&h);
}

__device__ __forceinline__ void cp_async16(void* smem, const void* gmem) {
    uint32_t s = (uint32_t)__cvta_generic_to_shared(smem);
    asm volatile("cp.async.cg.shared.global [%0], [%1], 16;" :: "r"(s), "l"(gmem));
}

// ---------------- conversion kernels -------------------------------------------
__global__ __launch_bounds__(256)
void conv_a(const float* __restrict__ A, uint2* __restrict__ Ac, int npairs)
{
    int idx = blockIdx.x * blockDim.x + threadIdx.x;
    if (idx >= npairs) return;
    float2 p = ((const float2*)A)[idx];
    uint32_t lo;
    uint32_t hi = packsplit(p.x, p.y, lo);
    Ac[idx] = make_uint2(hi, lo);
}

__global__ __launch_bounds__(256)
void conv_wt(const float* __restrict__ W, uint2* __restrict__ Wt, int K, int N)
{
    int idx = blockIdx.x * blockDim.x + threadIdx.x;
    if (idx >= N * (K / 2)) return;
    int p = idx / N;
    int n = idx - p * N;
    float x = W[(size_t)(2 * p)     * N + n];
    float y = W[(size_t)(2 * p + 1) * N + n];
    uint32_t lo;
    uint32_t hi = packsplit(x, y, lo);
    Wt[(size_t)n * (K / 2) + p] = make_uint2(hi, lo);
}

// ---------------- bf16x3 GEMM v2 ------------------------------------------------
// C[M,N] = A[M,K] @ W[K,N]; A pairs [M][K/2], W transposed pairs [N][K/2].
// 128 threads, 4 warps, warp tile 32x64; BM=128 BN=64 BK=32; 2-stage cp.async.
// All smem fragment indices hoisted (r&3 == q&3 for every fragment row).
#define GBM 128
#define GBN 64
#define GBK 32

__global__ __launch_bounds__(128)
void gemm_bf16x3(const uint2* __restrict__ Ac, const uint2* __restrict__ Bt,
                 float* __restrict__ C, int M, int N, int K)
{
    __shared__ uint2 sA[2][128][16];   // 32KB
    __shared__ uint2 sB[2][64][16];    // 16KB

    const int tid  = threadIdx.x;
    const int lane = tid & 31;
    const int w    = tid >> 5;         // 0..3
    const int bm   = blockIdx.y * GBM;
    const int bn   = blockIdx.x * GBN;
    const int Kp   = K >> 2;           // uint4 per row

    const uint4* Aq = (const uint4*)Ac;
    const uint4* Bq = (const uint4*)Bt;

    const int e = lane & 3;
    const int q = lane >> 2;
    const int sa = (q & 3) << 2;
    // hoisted swizzled indices: idx[kk][half] = (kk*8 + 4*half + e) ^ sa
    int idx00 = e ^ sa, idx01 = (e + 4) ^ sa;
    int idx10 = (8 + e) ^ sa, idx11 = (12 + e) ^ sa;

    float acc[2][8][4];
    #pragma unroll
    for (int i = 0; i < 2; i++)
        #pragma unroll
        for (int j = 0; j < 8; j++)
            #pragma unroll
            for (int t = 0; t < 4; t++) acc[i][j][t] = 0.f;

    #define STAGE(buf, k0)                                                        \
    {                                                                             \
        int kq = (k0) >> 2;                                                       \
        _Pragma("unroll")                                                         \
        for (int i = 0; i < 8; i++) {                                             \
            int id = tid + 128 * i;                                               \
            int r = id >> 3, j = id & 7;                                          \
            int dst = (2 * j) ^ ((r & 3) << 2);                                   \
            cp_async16(&sA[buf][r][dst], &Aq[(size_t)(bm + r) * Kp + kq + j]);    \
        }                                                                         \
        _Pragma("unroll")                                                         \
        for (int i = 0; i < 4; i++) {                                             \
            int id = tid + 128 * i;                                               \
            int r = id >> 3, j = id & 7;                                          \
            int dst = (2 * j) ^ ((r & 3) << 2);                                   \
            cp_async16(&sB[buf][r][dst], &Bq[(size_t)(bn + r) * Kp + kq + j]);    \
        }                                                                         \
        asm volatile("cp.async.commit_group;");                                   \
    }

    const int niter = K / GBK;
    STAGE(0, 0);

    for (int it = 0; it < niter; it++) {
        if (it + 1 < niter) {
            STAGE((it + 1) & 1, (it + 1) * GBK);
            asm volatile("cp.async.wait_group 1;");
        } else {
            asm volatile("cp.async.wait_group 0;");
        }
        __syncthreads();

        const int buf = it & 1;
        #pragma unroll
        for (int kk = 0; kk < 2; kk++) {
            const int i0 = kk ? idx10 : idx00;
            const int i1 = kk ? idx11 : idx01;
            uint32_t ah[2][4], al[2][4];
            #pragma unroll
            for (int mi = 0; mi < 2; mi++) {
                int r = w * 32 + mi * 16 + q;
                uint2 u0 = sA[buf][r    ][i0];
                uint2 u1 = sA[buf][r + 8][i0];
                uint2 u2 = sA[buf][r    ][i1];
                uint2 u3 = sA[buf][r + 8][i1];
                ah[mi][0] = u0.x; al[mi][0] = u0.y;
                ah[mi][1] = u1.x; al[mi][1] = u1.y;
                ah[mi][2] = u2.x; al[mi][2] = u2.y;
                ah[mi][3] = u3.x; al[mi][3] = u3.y;
            }
            #pragma unroll
            for (int ni = 0; ni < 8; ni++) {
                int n = ni * 8 + q;
                uint2 v0 = sB[buf][n][i0];
                uint2 v1 = sB[buf][n][i1];
                uint32_t bh[2] = {v0.x, v1.x};
                uint32_t bl[2] = {v0.y, v1.y};
                #pragma unroll
                for (int mi = 0; mi < 2; mi++) {
                    mma_bf16(acc[mi][ni], ah[mi], bh);
                    mma_bf16(acc[mi][ni], al[mi], bh);
                    mma_bf16(acc[mi][ni], ah[mi], bl);
                }
            }
        }
        __syncthreads();
    }

    #pragma unroll
    for (int mi = 0; mi < 2; mi++) {
        int r = bm + w * 32 + mi * 16 + q;
        #pragma unroll
        for (int ni = 0; ni < 8; ni++) {
            int c = bn + ni * 8 + e * 2;
            *(float2*)(C + (size_t)r * N + c)       = make_float2(acc[mi][ni][0], acc[mi][ni][1]);
            *(float2*)(C + (size_t)(r + 8) * N + c) = make_float2(acc[mi][ni][2], acc[mi][ni][3]);
        }
    }
    #undef STAGE
}

// ---------------- fused K/V projection (fp32, N=64) ----------------------------
__global__ __launch_bounds__(256)
void sgemm_kv(const float* __restrict__ Kin, const float* __restrict__ Wk,
              const float* __restrict__ Vin, const float* __restrict__ Wv,
              float* __restrict__ Ck, float* __restrict__ Cv)
{
    __shared__ float As[16][68];
    __shared__ float Bs[16][64];

    const float* A = blockIdx.z ? Vin : Kin;
    const float* W = blockIdx.z ? Wv  : Wk;
    float*       C = blockIdx.z ? Cv  : Ck;
    const int N = 64, K = DM;

    const int tid = threadIdx.x;
    const int tx  = tid & 15;
    const int ty  = tid >> 4;
    const int bm  = blockIdx.y * 64;

    const int arow = tid >> 2;
    const int acol = (tid & 3) * 4;
    const int brow = tid >> 4;
    const int bcol = (tid & 15) * 4;

    float acc[4][4] = {};

    for (int k0 = 0; k0 < K; k0 += 16) {
        float4 a4 = *(const float4*)(A + (size_t)(bm + arow) * K + k0 + acol);
        As[acol + 0][arow] = a4.x;
        As[acol + 1][arow] = a4.y;
        As[acol + 2][arow] = a4.z;
        As[acol + 3][arow] = a4.w;
        *(float4*)&Bs[brow][bcol] =
            *(const float4*)(W + (size_t)(k0 + brow) * N + bcol);
        __syncthreads();

        #pragma unroll
        for (int k = 0; k < 16; k++) {
            float4 av = *(const float4*)&As[k][ty * 4];
            float4 bv = *(const float4*)&Bs[k][tx * 4];
            float a_[4] = {av.x, av.y, av.z, av.w};
            float b_[4] = {bv.x, bv.y, bv.z, bv.w};
            #pragma unroll
            for (int i = 0; i < 4; i++)
                #pragma unroll
                for (int j = 0; j < 4; j++)
                    acc[i][j] += a_[i] * b_[j];
        }
        __syncthreads();
    }

    #pragma unroll
    for (int i = 0; i < 4; i++) {
        float4 o = make_float4(acc[i][0], acc[i][1], acc[i][2], acc[i][3]);
        *(float4*)(C + (size_t)(bm + ty * 4 + i) * N + tx * 4) = o;
    }
}

// ---------------- K/V bf16 hi/lo prep (V transposed) ---------------------------
__global__ __launch_bounds__(256)
void conv_kv(const float* __restrict__ gk, const float* __restrict__ gv,
             uint2* __restrict__ kc, uint2* __restrict__ vc)
{
    int idx = blockIdx.x * blockDim.x + threadIdx.x;
    if (idx >= BS * DK / 2) return;

    float2 kp = ((const float2*)gk)[idx];
    uint32_t klo;
    uint32_t khi = packsplit(kp.x, kp.y, klo);
    kc[idx] = make_uint2(khi, klo);

    int b = idx >> 16;
    int r = idx & 65535;
    int d = r >> 10;
    int p = r & 1023;
    int s0 = 2 * p;
    float vx = gv[((size_t)(b * S_ + s0))     * DV + d];
    float vy = gv[((size_t)(b * S_ + s0 + 1)) * DV + d];
    uint32_t vlo;
    uint32_t vhi = packsplit(vx, vy, vlo);
    vc[idx] = make_uint2(vhi, vlo);
}

// ---------------- mma flash attention (bf16x3, cp.async prefetch) ---------------
#define QB 128
#define KB 64

__global__ __launch_bounds__(256)
void mqa_attn_mma(const float* __restrict__ gq, uint2* __restrict__ aoc)
{
    // dynamic smem: sK[2][2048], sV[2][2048] uint2 = 64KB
    extern __shared__ __align__(16) uint2 dsm[];
    uint2* sK = dsm;
    uint2* sV = dsm + 4096;

    const int tid = threadIdx.x;
    const int l   = tid & 31;
    const int w   = tid >> 5;
    const int qb  = (S_ / QB - 1) - blockIdx.x;
    const int h   = blockIdx.y;
    const int b   = blockIdx.z;

    const int rowbase = qb * QB + w * 16;
    const int r0 = rowbase + (l >> 2);
    const int r1 = r0 + 8;
    const int e  = l & 3;
    const int Xl = (l >> 2) << 2;

    // hoisted swizzled fragment indices: fidx[ck][half] = (8*ck + 4*half + e) ^ Xl
    int fidx[4][2];
    #pragma unroll
    for (int ck = 0; ck < 4; ck++) {
        fidx[ck][0] = (8 * ck + e)     ^ Xl;
        fidx[ck][1] = (8 * ck + 4 + e) ^ Xl;
    }

    uint32_t qh[4][4], ql[4][4];
    {
        const float* qbase = gq + ((size_t)(b * S_)) * DM + h * DK;
        #pragma unroll
        for (int ck = 0; ck < 4; ck++) {
            int d0 = 16 * ck + e * 2;
            float2 v00 = *(const float2*)(qbase + (size_t)r0 * DM + d0);
            float2 v10 = *(const float2*)(qbase + (size_t)r1 * DM + d0);
            float2 v01 = *(const float2*)(qbase + (size_t)r0 * DM + d0 + 8);
            float2 v11 = *(const float2*)(qbase + (size_t)r1 * DM + d0 + 8);
            qh[ck][0] = packsplit(v00.x * 0.125f, v00.y * 0.125f, ql[ck][0]);
            qh[ck][1] = packsplit(v10.x * 0.125f, v10.y * 0.125f, ql[ck][1]);
            qh[ck][2] = packsplit(v01.x * 0.125f, v01.y * 0.125f, ql[ck][2]);
            qh[ck][3] = packsplit(v11.x * 0.125f, v11.y * 0.125f, ql[ck][3]);
        }
    }

    float O[8][4];
    #pragma unroll
    for (int t = 0; t < 8; t++)
        #pragma unroll
        for (int i = 0; i < 4; i++) O[t][i] = 0.f;
    float m0 = -1e30f, m1 = -1e30f, l0 = 0.f, l1 = 0.f;

    const uint4* ksrc = (const uint4*)g_kc;
    const uint4* vsrc = (const uint4*)g_vc;

    #define ASTAGE(buf, kb_)                                                          \
    {                                                                                 \
        _Pragma("unroll")                                                             \
        for (int i = 0; i < 4; i++) {                                                 \
            int id = tid + 256 * i;                                                   \
            int r  = id >> 4;                                                         \
            int j  = id & 15;                                                         \
            int dg = (2 * j) ^ ((r & 7) << 2);                                        \
            cp_async16(&sK[(buf) * 2048 + r * 32 + dg],                               \
                       &ksrc[((size_t)(b * S_ + (kb_) * KB + r)) * 16 + j]);          \
            cp_async16(&sV[(buf) * 2048 + r * 32 + dg],                               \
                       &vsrc[((size_t)(b * DV + r)) * (S_ / 4) + (kb_) * 16 + j]);    \
        }                                                                             \
        asm volatile("cp.async.commit_group;");                                       \
    }

    const int nkb = qb * 2 + 2;
    ASTAGE(0, 0);

    for (int kb = 0; kb < nkb; kb++) {
        if (kb + 1 < nkb) {
            ASTAGE((kb + 1) & 1, kb + 1);
            asm volatile("cp.async.wait_group 1;");
        } else {
            asm volatile("cp.async.wait_group 0;");
        }
        __syncthreads();

        const uint2* sKb = sK + (kb & 1) * 2048;
        const uint2* sVb = sV + (kb & 1) * 2048;

        float Sf[8][4];
        #pragma unroll
        for (int t = 0; t < 8; t++)
            #pragma unroll
            for (int i = 0; i < 4; i++) Sf[t][i] = 0.f;

        #pragma unroll
        for (int ck = 0; ck < 4; ck++) {
            #pragma unroll
            for (int t = 0; t < 8; t++) {
                int kv = 8 * t + (l >> 2);
                uint2 u0 = sKb[kv * 32 + fidx[ck][0]];
                uint2 u1 = sKb[kv * 32 + fidx[ck][1]];
                uint32_t bh[2] = {u0.x, u1.x};
                uint32_t bl[2] = {u0.y, u1.y};
                mma_bf16(Sf[t], qh[ck], bh);
                mma_bf16(Sf[t], ql[ck], bh);
                mma_bf16(Sf[t], qh[ck], bl);
            }
        }

        if (kb >= 2 * qb) {
            #pragma unroll
            for (int t = 0; t < 8; t++) {
                int c0 = kb * KB + 8 * t + e * 2;
                if (c0     > r0) Sf[t][0] = -1e9f;
                if (c0 + 1 > r0) Sf[t][1] = -1e9f;
                if (c0     > r1) Sf[t][2] = -1e9f;
                if (c0 + 1 > r1) Sf[t][3] = -1e9f;
            }
        }

        float t0 = -1e30f, t1 = -1e30f;
        #pragma unroll
        for (int t = 0; t < 8; t++) {
            t0 = fmaxf(t0, fmaxf(Sf[t][0], Sf[t][1]));
            t1 = fmaxf(t1, fmaxf(Sf[t][2], Sf[t][3]));
        }
        t0 = fmaxf(t0, __shfl_xor_sync(0xffffffffu, t0, 1));
        t0 = fmaxf(t0, __shfl_xor_sync(0xffffffffu, t0, 2));
        t1 = fmaxf(t1, __shfl_xor_sync(0xffffffffu, t1, 1));
        t1 = fmaxf(t1, __shfl_xor_sync(0xffffffffu, t1, 2));

        float mn0 = fmaxf(m0, t0), mn1 = fmaxf(m1, t1);
        float c0 = __expf(m0 - mn0), c1 = __expf(m1 - mn1);

        float s0 = 0.f, s1 = 0.f;
        #pragma unroll
        for (int t = 0; t < 8; t++) {
            Sf[t][0] = __expf(Sf[t][0] - mn0);
            Sf[t][1] = __expf(Sf[t][1] - mn0);
            Sf[t][2] = __expf(Sf[t][2] - mn1);
            Sf[t][3] = __expf(Sf[t][3] - mn1);
            s0 += Sf[t][0] + Sf[t][1];
            s1 += Sf[t][2] + Sf[t][3];
        }
        s0 += __shfl_xor_sync(0xffffffffu, s0, 1);
        s0 += __shfl_xor_sync(0xffffffffu, s0, 2);
        s1 += __shfl_xor_sync(0xffffffffu, s1, 1);
        s1 += __shfl_xor_sync(0xffffffffu, s1, 2);

        l0 = l0 * c0 + s0;
        l1 = l1 * c1 + s1;
        m0 = mn0; m1 = mn1;

        #pragma unroll
        for (int t = 0; t < 8; t++) {
            O[t][0] *= c0; O[t][1] *= c0;
            O[t][2] *= c1; O[t][3] *= c1;
        }

        uint32_t ph[4][4], pl[4][4];
        #pragma unroll
        for (int ck = 0; ck < 4; ck++) {
            ph[ck][0] = packsplit(Sf[2*ck][0],   Sf[2*ck][1],   pl[ck][0]);
            ph[ck][1] = packsplit(Sf[2*ck][2],   Sf[2*ck][3],   pl[ck][1]);
            ph[ck][2] = packsplit(Sf[2*ck+1][0], Sf[2*ck+1][1], pl[ck][2]);
            ph[ck][3] = packsplit(Sf[2*ck+1][2], Sf[2*ck+1][3], pl[ck][3]);
        }

        #pragma unroll
        for (int ck = 0; ck < 4; ck++) {
            #pragma unroll
            for (int td = 0; td < 8; td++) {
                int d = 8 * td + (l >> 2);
                uint2 u0 = sVb[d * 32 + fidx[ck][0]];
                uint2 u1 = sVb[d * 32 + fidx[ck][1]];
                uint32_t vh[2] = {u0.x, u1.x};
                uint32_t vl[2] = {u0.y, u1.y};
                mma_bf16(O[td], ph[ck], vh);
                mma_bf16(O[td], pl[ck], vh);
                mma_bf16(O[td], ph[ck], vl);
            }
        }
        __syncthreads();
    }
    #undef ASTAGE

    const float inv0 = 1.f / l0, inv1 = 1.f / l1;
    #pragma unroll
    for (int td = 0; td < 8; td++) {
        int d0 = 8 * td + e * 2;
        int cp = (h * DV + d0) >> 1;
        uint32_t lo0, lo1;
        uint32_t hi0 = packsplit(O[td][0] * inv0, O[td][1] * inv0, lo0);
        uint32_t hi1 = packsplit(O[td][2] * inv1, O[td][3] * inv1, lo1);
        aoc[(size_t)(b * S_ + r0) * (DM / 2) + cp] = make_uint2(hi0, lo0);
        aoc[(size_t)(b * S_ + r1) * (DM / 2) + cp] = make_uint2(hi1, lo1);
    }
}

// ---------------- launch ---------------------------------------------------------
extern "C" void kernel_launch(void* const* d_in, const int* in_sizes, int n_in,
                              void* d_out, int out_size)
{
    const float* Q  = (const float*)d_in[0];
    const float* K  = (const float*)d_in[1];
    const float* V  = (const float*)d_in[2];
    const float* Wq = (const float*)d_in[3];
    const float* Wk = (const float*)d_in[4];
    const float* Wv = (const float*)d_in[5];
    const float* Wo = (const float*)d_in[6];
    float* out = (float*)d_out;

    float *gq, *gk, *gv;
    uint2 *qc, *wqt, *wot, *aoc, *kc, *vc;
    cudaGetSymbolAddress((void**)&gq,  g_q);
    cudaGetSymbolAddress((void**)&gk,  g_k);
    cudaGetSymbolAddress((void**)&gv,  g_v);
    cudaGetSymbolAddress((void**)&qc,  g_qc);
    cudaGetSymbolAddress((void**)&wqt, g_wqt);
    cudaGetSymbolAddress((void**)&wot, g_wot);
    cudaGetSymbolAddress((void**)&aoc, g_aoc);
    cudaGetSymbolAddress((void**)&kc,  g_kc);
    cudaGetSymbolAddress((void**)&vc,  g_vc);

    static bool attr_set = false;
    if (!attr_set) {
        cudaFuncSetAttribute(mqa_attn_mma,
                             cudaFuncAttributeMaxDynamicSharedMemorySize, 65536);
        attr_set = true;
    }

    // conversions
    conv_a <<<(BS * DM / 2 + 255) / 256, 256>>>(Q, qc, BS * DM / 2);
    conv_wt<<<(DM * DM / 2 + 255) / 256, 256>>>(Wq, wqt, DM, DM);
    conv_wt<<<(DM * DM / 2 + 255) / 256, 256>>>(Wo, wot, DM, DM);

    // Q projection (bf16x3 tensor cores)
    gemm_bf16x3<<<dim3(DM / GBN, BS / GBM), 128>>>(qc, wqt, gq, BS, DM, DM);

    // K/V projections (fused, fp32)
    sgemm_kv<<<dim3(1, BS / 64, 2), 256>>>(K, Wk, V, Wv, gk, gv);
    conv_kv<<<(BS * DK / 2 + 255) / 256, 256>>>(gk, gv, kc, vc);

    // attention (cp.async prefetch, writes bf16 pairs for O-proj)
    mqa_attn_mma<<<dim3(S_ / QB, H_, B_), 256, 65536>>>(gq, aoc);

    // output projection (bf16x3 tensor cores)
    gemm_bf16x3<<<dim3(DM / GBN, BS / GBM), 128>>>(aoc, wot, out, BS, DM, DM);
}

// round 8
// speedup vs baseline: 4.1332x; 1.0826x over previous
#include <cuda_runtime.h>
#include <cuda_bf16.h>
#include <cstdint>

#define B_  2
#define S_  2048
#define DM  1024
#define H_  16
#define DK  64
#define DV  64
#define BS  (B_*S_)   // 4096

// ---------------- scratch ----------------------------------------------------
__device__ float    g_q  [BS * DM];          // Q-proj output (fp32, read by attn)
__device__ float    g_k  [BS * DK];
__device__ float    g_v  [BS * DV];
__device__ uint32_t g_qh [BS * DM / 2];      // input Q hi plane (bf16x2)
__device__ uint32_t g_ql [BS * DM / 2];      // input Q lo plane
__device__ uint32_t g_wqh[DM * DM / 2];      // W_q^T [N][K] hi plane
__device__ uint32_t g_wql[DM * DM / 2];
__device__ uint32_t g_woh[DM * DM / 2];      // W_o^T [N][K] hi plane
__device__ uint32_t g_wol[DM * DM / 2];
__device__ uint32_t g_aoh[BS * DM / 2];      // attention out hi plane
__device__ uint32_t g_aol[BS * DM / 2];
__device__ uint2    g_kc[BS * DK / 2];       // K pairs (attention), row=(b,s)
__device__ uint2    g_vc[B_ * DV * (S_ / 2)];// V^T pairs (attention), row=(b,d)

// ---------------- helpers ------------------------------------------------------
__device__ __forceinline__ uint32_t packsplit(float x, float y, uint32_t &lo) {
    __nv_bfloat162 h = __floats2bfloat162_rn(x, y);
    float hx = __bfloat162float(__low2bfloat16(h));
    float hy = __bfloat162float(__high2bfloat16(h));
    __nv_bfloat162 l2 = __floats2bfloat162_rn(x - hx, y - hy);
    lo = *reinterpret_cast<uint32_t*>(&l2);
    return *reinterpret_cast<uint32_t*>(&h);
}

__device__ __forceinline__ void cp_async16(void* smem, const void* gmem) {
    uint32_t s = (uint32_t)__cvta_generic_to_shared(smem);
    asm volatile("cp.async.cg.shared.global [%0], [%1], 16;" :: "r"(s), "l"(gmem));
}

__device__ __forceinline__ uint32_t smem_u32(const void* p) {
    return (uint32_t)__cvta_generic_to_shared(p);
}

__device__ __forceinline__ void mma_bf16(float* d, const uint32_t* a, const uint32_t* b) {
    asm volatile(
        "mma.sync.aligned.m16n8k16.row.col.f32.bf16.bf16.f32 "
        "{%0,%1,%2,%3},{%4,%5,%6,%7},{%8,%9},{%0,%1,%2,%3};"
        : "+f"(d[0]), "+f"(d[1]), "+f"(d[2]), "+f"(d[3])
        : "r"(a[0]), "r"(a[1]), "r"(a[2]), "r"(a[3]), "r"(b[0]), "r"(b[1]));
}

__device__ __forceinline__ void ldsm_x4(uint32_t* r, uint32_t addr) {
    asm volatile("ldmatrix.sync.aligned.m8n8.x4.shared.b16 {%0,%1,%2,%3}, [%4];"
                 : "=r"(r[0]), "=r"(r[1]), "=r"(r[2]), "=r"(r[3]) : "r"(addr));
}

// ---------------- conversion kernels --------------------------------------------
__global__ __launch_bounds__(256)
void conv_planes(const float* __restrict__ A, uint32_t* __restrict__ Hi,
                 uint32_t* __restrict__ Lo, int npairs)
{
    int idx = blockIdx.x * blockDim.x + threadIdx.x;
    if (idx >= npairs) return;
    float2 p = ((const float2*)A)[idx];
    uint32_t lo;
    uint32_t hi = packsplit(p.x, p.y, lo);
    Hi[idx] = hi;
    Lo[idx] = lo;
}

// W [K][N] fp32 -> W^T planes [N][K] (bf16x2 along K)
__global__ __launch_bounds__(256)
void conv_wt_planes(const float* __restrict__ W, uint32_t* __restrict__ Hi,
                    uint32_t* __restrict__ Lo, int K, int N)
{
    int idx = blockIdx.x * blockDim.x + threadIdx.x;   // p * N + n
    if (idx >= N * (K / 2)) return;
    int p = idx / N;
    int n = idx - p * N;
    float x = W[(size_t)(2 * p)     * N + n];
    float y = W[(size_t)(2 * p + 1) * N + n];
    uint32_t lo;
    uint32_t hi = packsplit(x, y, lo);
    Hi[(size_t)n * (K / 2) + p] = hi;
    Lo[(size_t)n * (K / 2) + p] = lo;
}

// ---------------- bf16x3 GEMM with ldmatrix --------------------------------------
// C[M,Ntot] = A @ W; A planes [M][K] bf16, Bt planes [Ntot][K] bf16 (= W^T).
// BM=128, BN=64, BK=64. 128 threads / 4 warps, warp tile 32x64.
// smem: rows of 128B (64 bf16), XOR swizzle u = j ^ (r&7) on 16B units.
// sA: [(buf*2+pl)*128 + r]*128 + u*16   (64KB)
// sB: 65536 + [(buf*2+pl)*64 + r]*128 + u*16  (32KB)   total 96KB dynamic.
#define GSM_TOT 98304

__global__ __launch_bounds__(128)
void gemm_ldsm(const uint4* __restrict__ Ah, const uint4* __restrict__ Al,
               const uint4* __restrict__ Bh, const uint4* __restrict__ Bl,
               float* __restrict__ C, int M, int Ntot, int K)
{
    extern __shared__ __align__(128) char dsm[];
    const uint32_t sb = smem_u32(dsm);

    const int tid = threadIdx.x;
    const int l   = tid & 31;
    const int w   = tid >> 5;
    const int bn  = blockIdx.x * 64;
    const int bm  = blockIdx.y * 128;
    const int K8  = K >> 3;            // uint4 per plane row

    const int e = l & 3;
    const int q = l >> 2;

    // ldmatrix per-thread geometry
    const int rA0 = w * 32 + (l & 7) + ((l >> 3) & 1) * 8;   // + mi*16
    const int jAh = (l >> 4) & 1;
    const int rB0 = (l & 7) + ((l >> 4) & 1) * 8;            // + ni2*16
    const int jBh = (l >> 3) & 1;
    const int cA  = rA0 & 7;                                  // invariant under +16
    const int cB  = rB0 & 7;

    float acc[2][8][4];
    #pragma unroll
    for (int i = 0; i < 2; i++)
        #pragma unroll
        for (int j = 0; j < 8; j++)
            #pragma unroll
            for (int t = 0; t < 4; t++) acc[i][j][t] = 0.f;

    #define STAGE(buf, k0)                                                          \
    {                                                                               \
        const int kq = (k0) >> 3;                                                   \
        _Pragma("unroll")                                                           \
        for (int i = 0; i < 16; i++) {                                              \
            int id = tid + 128 * i;              /* 0..2047 */                      \
            int pl = id >> 10;                                                      \
            int rem = id & 1023;                                                    \
            int r = rem >> 3, j = rem & 7;                                          \
            cp_async16(dsm + (((buf) * 2 + pl) * 128 + r) * 128                     \
                           + ((j ^ (r & 7)) << 4),                                  \
                       (pl ? Al : Ah) + (size_t)(bm + r) * K8 + kq + j);            \
        }                                                                           \
        _Pragma("unroll")                                                           \
        for (int i = 0; i < 8; i++) {                                               \
            int id = tid + 128 * i;              /* 0..1023 */                      \
            int pl = id >> 9;                                                       \
            int rem = id & 511;                                                     \
            int r = rem >> 3, j = rem & 7;                                          \
            cp_async16(dsm + 65536 + (((buf) * 2 + pl) * 64 + r) * 128              \
                           + ((j ^ (r & 7)) << 4),                                  \
                       (pl ? Bl : Bh) + (size_t)(bn + r) * K8 + kq + j);            \
        }                                                                           \
        asm volatile("cp.async.commit_group;");                                     \
    }

    const int niter = K / 64;
    STAGE(0, 0);

    for (int it = 0; it < niter; it++) {
        if (it + 1 < niter) {
            STAGE((it + 1) & 1, (it + 1) * 64);
            asm volatile("cp.async.wait_group 1;");
        } else {
            asm volatile("cp.async.wait_group 0;");
        }
        __syncthreads();

        const int buf = it & 1;
        const uint32_t aBaseH = sb + ((buf * 2 + 0) * 128) * 128;
        const uint32_t aBaseL = sb + ((buf * 2 + 1) * 128) * 128;
        const uint32_t bBaseH = sb + 65536 + ((buf * 2 + 0) * 64) * 128;
        const uint32_t bBaseL = sb + 65536 + ((buf * 2 + 1) * 64) * 128;

        #pragma unroll
        for (int kk = 0; kk < 4; kk++) {
            const uint32_t offA = (uint32_t)(((2 * kk + jAh) ^ cA) << 4);
            const uint32_t offB = (uint32_t)(((2 * kk + jBh) ^ cB) << 4);

            uint32_t ah[2][4], al_[2][4];
            #pragma unroll
            for (int mi = 0; mi < 2; mi++) {
                uint32_t rb = (uint32_t)((rA0 + mi * 16) * 128);
                ldsm_x4(ah[mi],  aBaseH + rb + offA);
                ldsm_x4(al_[mi], aBaseL + rb + offA);
            }

            #pragma unroll
            for (int ni2 = 0; ni2 < 4; ni2++) {
                uint32_t rb = (uint32_t)((rB0 + ni2 * 16) * 128);
                uint32_t bh4[4], bl4[4];
                ldsm_x4(bh4, bBaseH + rb + offB);
                ldsm_x4(bl4, bBaseL + rb + offB);
                uint32_t bhE[2] = {bh4[0], bh4[1]};   // ni = 2*ni2
                uint32_t bhO[2] = {bh4[2], bh4[3]};   // ni = 2*ni2+1
                uint32_t blE[2] = {bl4[0], bl4[1]};
                uint32_t blO[2] = {bl4[2], bl4[3]};
                #pragma unroll
                for (int mi = 0; mi < 2; mi++) {
                    mma_bf16(acc[mi][2 * ni2],     ah[mi],  bhE);
                    mma_bf16(acc[mi][2 * ni2],     al_[mi], bhE);
                    mma_bf16(acc[mi][2 * ni2],     ah[mi],  blE);
                    mma_bf16(acc[mi][2 * ni2 + 1], ah[mi],  bhO);
                    mma_bf16(acc[mi][2 * ni2 + 1], al_[mi], bhO);
                    mma_bf16(acc[mi][2 * ni2 + 1], ah[mi],  blO);
                }
            }
        }
        __syncthreads();
    }
    #undef STAGE

    #pragma unroll
    for (int mi = 0; mi < 2; mi++) {
        int r = bm + w * 32 + mi * 16 + q;
        #pragma unroll
        for (int ni = 0; ni < 8; ni++) {
            int c = bn + ni * 8 + e * 2;
            *(float2*)(C + (size_t)r * Ntot + c)       = make_float2(acc[mi][ni][0], acc[mi][ni][1]);
            *(float2*)(C + (size_t)(r + 8) * Ntot + c) = make_float2(acc[mi][ni][2], acc[mi][ni][3]);
        }
    }
}

// ---------------- fused K/V projection (fp32, N=64) -----------------------------
__global__ __launch_bounds__(256)
void sgemm_kv(const float* __restrict__ Kin, const float* __restrict__ Wk,
              const float* __restrict__ Vin, const float* __restrict__ Wv,
              float* __restrict__ Ck, float* __restrict__ Cv)
{
    __shared__ float As[16][68];
    __shared__ float Bs[16][64];

    const float* A = blockIdx.z ? Vin : Kin;
    const float* W = blockIdx.z ? Wv  : Wk;
    float*       C = blockIdx.z ? Cv  : Ck;
    const int N = 64, K = DM;

    const int tid = threadIdx.x;
    const int tx  = tid & 15;
    const int ty  = tid >> 4;
    const int bm  = blockIdx.y * 64;

    const int arow = tid >> 2;
    const int acol = (tid & 3) * 4;
    const int brow = tid >> 4;
    const int bcol = (tid & 15) * 4;

    float acc[4][4] = {};

    for (int k0 = 0; k0 < K; k0 += 16) {
        float4 a4 = *(const float4*)(A + (size_t)(bm + arow) * K + k0 + acol);
        As[acol + 0][arow] = a4.x;
        As[acol + 1][arow] = a4.y;
        As[acol + 2][arow] = a4.z;
        As[acol + 3][arow] = a4.w;
        *(float4*)&Bs[brow][bcol] =
            *(const float4*)(W + (size_t)(k0 + brow) * N + bcol);
        __syncthreads();

        #pragma unroll
        for (int k = 0; k < 16; k++) {
            float4 av = *(const float4*)&As[k][ty * 4];
            float4 bv = *(const float4*)&Bs[k][tx * 4];
            float a_[4] = {av.x, av.y, av.z, av.w};
            float b_[4] = {bv.x, bv.y, bv.z, bv.w};
            #pragma unroll
            for (int i = 0; i < 4; i++)
                #pragma unroll
                for (int j = 0; j < 4; j++)
                    acc[i][j] += a_[i] * b_[j];
        }
        __syncthreads();
    }

    #pragma unroll
    for (int i = 0; i < 4; i++) {
        float4 o = make_float4(acc[i][0], acc[i][1], acc[i][2], acc[i][3]);
        *(float4*)(C + (size_t)(bm + ty * 4 + i) * N + tx * 4) = o;
    }
}

// ---------------- K/V bf16 hi/lo prep (V transposed), for attention -------------
__global__ __launch_bounds__(256)
void conv_kv(const float* __restrict__ gk, const float* __restrict__ gv,
             uint2* __restrict__ kc, uint2* __restrict__ vc)
{
    int idx = blockIdx.x * blockDim.x + threadIdx.x;
    if (idx >= BS * DK / 2) return;

    float2 kp = ((const float2*)gk)[idx];
    uint32_t klo;
    uint32_t khi = packsplit(kp.x, kp.y, klo);
    kc[idx] = make_uint2(khi, klo);

    int b = idx >> 16;
    int r = idx & 65535;
    int d = r >> 10;
    int p = r & 1023;
    int s0 = 2 * p;
    float vx = gv[((size_t)(b * S_ + s0))     * DV + d];
    float vy = gv[((size_t)(b * S_ + s0 + 1)) * DV + d];
    uint32_t vlo;
    uint32_t vhi = packsplit(vx, vy, vlo);
    vc[idx] = make_uint2(vhi, vlo);
}

// ---------------- mma flash attention (bf16x3, cp.async prefetch) ----------------
#define QB 128
#define KB 64

__global__ __launch_bounds__(256)
void mqa_attn_mma(const float* __restrict__ gq,
                  uint32_t* __restrict__ aoh, uint32_t* __restrict__ aol)
{
    extern __shared__ __align__(16) uint2 dsma[];
    uint2* sK = dsma;
    uint2* sV = dsma + 4096;

    const int tid = threadIdx.x;
    const int l   = tid & 31;
    const int w   = tid >> 5;
    const int qb  = (S_ / QB - 1) - blockIdx.x;
    const int h   = blockIdx.y;
    const int b   = blockIdx.z;

    const int rowbase = qb * QB + w * 16;
    const int r0 = rowbase + (l >> 2);
    const int r1 = r0 + 8;
    const int e  = l & 3;
    const int Xl = (l >> 2) << 2;

    int fidx[4][2];
    #pragma unroll
    for (int ck = 0; ck < 4; ck++) {
        fidx[ck][0] = (8 * ck + e)     ^ Xl;
        fidx[ck][1] = (8 * ck + 4 + e) ^ Xl;
    }

    uint32_t qh[4][4], ql[4][4];
    {
        const float* qbase = gq + ((size_t)(b * S_)) * DM + h * DK;
        #pragma unroll
        for (int ck = 0; ck < 4; ck++) {
            int d0 = 16 * ck + e * 2;
            float2 v00 = *(const float2*)(qbase + (size_t)r0 * DM + d0);
            float2 v10 = *(const float2*)(qbase + (size_t)r1 * DM + d0);
            float2 v01 = *(const float2*)(qbase + (size_t)r0 * DM + d0 + 8);
            float2 v11 = *(const float2*)(qbase + (size_t)r1 * DM + d0 + 8);
            qh[ck][0] = packsplit(v00.x * 0.125f, v00.y * 0.125f, ql[ck][0]);
            qh[ck][1] = packsplit(v10.x * 0.125f, v10.y * 0.125f, ql[ck][1]);
            qh[ck][2] = packsplit(v01.x * 0.125f, v01.y * 0.125f, ql[ck][2]);
            qh[ck][3] = packsplit(v11.x * 0.125f, v11.y * 0.125f, ql[ck][3]);
        }
    }

    float O[8][4];
    #pragma unroll
    for (int t = 0; t < 8; t++)
        #pragma unroll
        for (int i = 0; i < 4; i++) O[t][i] = 0.f;
    float m0 = -1e30f, m1 = -1e30f, l0 = 0.f, l1 = 0.f;

    const uint4* ksrc = (const uint4*)g_kc;
    const uint4* vsrc = (const uint4*)g_vc;

    #define ASTAGE(buf, kb_)                                                          \
    {                                                                                 \
        _Pragma("unroll")                                                             \
        for (int i = 0; i < 4; i++) {                                                 \
            int id = tid + 256 * i;                                                   \
            int r  = id >> 4;                                                         \
            int j  = id & 15;                                                         \
            int dg = (2 * j) ^ ((r & 7) << 2);                                        \
            cp_async16(&sK[(buf) * 2048 + r * 32 + dg],                               \
                       &ksrc[((size_t)(b * S_ + (kb_) * KB + r)) * 16 + j]);          \
            cp_async16(&sV[(buf) * 2048 + r * 32 + dg],                               \
                       &vsrc[((size_t)(b * DV + r)) * (S_ / 4) + (kb_) * 16 + j]);    \
        }                                                                             \
        asm volatile("cp.async.commit_group;");                                       \
    }

    const int nkb = qb * 2 + 2;
    ASTAGE(0, 0);

    for (int kb = 0; kb < nkb; kb++) {
        if (kb + 1 < nkb) {
            ASTAGE((kb + 1) & 1, kb + 1);
            asm volatile("cp.async.wait_group 1;");
        } else {
            asm volatile("cp.async.wait_group 0;");
        }
        __syncthreads();

        const uint2* sKb = sK + (kb & 1) * 2048;
        const uint2* sVb = sV + (kb & 1) * 2048;

        float Sf[8][4];
        #pragma unroll
        for (int t = 0; t < 8; t++)
            #pragma unroll
            for (int i = 0; i < 4; i++) Sf[t][i] = 0.f;

        #pragma unroll
        for (int ck = 0; ck < 4; ck++) {
            #pragma unroll
            for (int t = 0; t < 8; t++) {
                int kv = 8 * t + (l >> 2);
                uint2 u0 = sKb[kv * 32 + fidx[ck][0]];
                uint2 u1 = sKb[kv * 32 + fidx[ck][1]];
                uint32_t bh[2] = {u0.x, u1.x};
                uint32_t bl[2] = {u0.y, u1.y};
                mma_bf16(Sf[t], qh[ck], bh);
                mma_bf16(Sf[t], ql[ck], bh);
                mma_bf16(Sf[t], qh[ck], bl);
            }
        }

        if (kb >= 2 * qb) {
            #pragma unroll
            for (int t = 0; t < 8; t++) {
                int c0 = kb * KB + 8 * t + e * 2;
                if (c0     > r0) Sf[t][0] = -1e9f;
                if (c0 + 1 > r0) Sf[t][1] = -1e9f;
                if (c0     > r1) Sf[t][2] = -1e9f;
                if (c0 + 1 > r1) Sf[t][3] = -1e9f;
            }
        }

        float t0 = -1e30f, t1 = -1e30f;
        #pragma unroll
        for (int t = 0; t < 8; t++) {
            t0 = fmaxf(t0, fmaxf(Sf[t][0], Sf[t][1]));
            t1 = fmaxf(t1, fmaxf(Sf[t][2], Sf[t][3]));
        }
        t0 = fmaxf(t0, __shfl_xor_sync(0xffffffffu, t0, 1));
        t0 = fmaxf(t0, __shfl_xor_sync(0xffffffffu, t0, 2));
        t1 = fmaxf(t1, __shfl_xor_sync(0xffffffffu, t1, 1));
        t1 = fmaxf(t1, __shfl_xor_sync(0xffffffffu, t1, 2));

        float mn0 = fmaxf(m0, t0), mn1 = fmaxf(m1, t1);
        float c0 = __expf(m0 - mn0), c1 = __expf(m1 - mn1);

        float s0 = 0.f, s1 = 0.f;
        #pragma unroll
        for (int t = 0; t < 8; t++) {
            Sf[t][0] = __expf(Sf[t][0] - mn0);
            Sf[t][1] = __expf(Sf[t][1] - mn0);
            Sf[t][2] = __expf(Sf[t][2] - mn1);
            Sf[t][3] = __expf(Sf[t][3] - mn1);
            s0 += Sf[t][0] + Sf[t][1];
            s1 += Sf[t][2] + Sf[t][3];
        }
        s0 += __shfl_xor_sync(0xffffffffu, s0, 1);
        s0 += __shfl_xor_sync(0xffffffffu, s0, 2);
        s1 += __shfl_xor_sync(0xffffffffu, s1, 1);
        s1 += __shfl_xor_sync(0xffffffffu, s1, 2);

        l0 = l0 * c0 + s0;
        l1 = l1 * c1 + s1;
        m0 = mn0; m1 = mn1;

        #pragma unroll
        for (int t = 0; t < 8; t++) {
            O[t][0] *= c0; O[t][1] *= c0;
            O[t][2] *= c1; O[t][3] *= c1;
        }

        uint32_t ph[4][4], pl[4][4];
        #pragma unroll
        for (int ck = 0; ck < 4; ck++) {
            ph[ck][0] = packsplit(Sf[2*ck][0],   Sf[2*ck][1],   pl[ck][0]);
            ph[ck][1] = packsplit(Sf[2*ck][2],   Sf[2*ck][3],   pl[ck][1]);
            ph[ck][2] = packsplit(Sf[2*ck+1][0], Sf[2*ck+1][1], pl[ck][2]);
            ph[ck][3] = packsplit(Sf[2*ck+1][2], Sf[2*ck+1][3], pl[ck][3]);
        }

        #pragma unroll
        for (int ck = 0; ck < 4; ck++) {
            #pragma unroll
            for (int td = 0; td < 8; td++) {
                int d = 8 * td + (l >> 2);
                uint2 u0 = sVb[d * 32 + fidx[ck][0]];
                uint2 u1 = sVb[d * 32 + fidx[ck][1]];
                uint32_t vh[2] = {u0.x, u1.x};
                uint32_t vl[2] = {u0.y, u1.y};
                mma_bf16(O[td], ph[ck], vh);
                mma_bf16(O[td], pl[ck], vh);
                mma_bf16(O[td], ph[ck], vl);
            }
        }
        __syncthreads();
    }
    #undef ASTAGE

    // epilogue: write hi/lo bf16 planes (feeds the ldsm O-proj directly)
    const float inv0 = 1.f / l0, inv1 = 1.f / l1;
    #pragma unroll
    for (int td = 0; td < 8; td++) {
        int d0 = 8 * td + e * 2;
        int cp = (h * DV + d0) >> 1;
        uint32_t lo0, lo1;
        uint32_t hi0 = packsplit(O[td][0] * inv0, O[td][1] * inv0, lo0);
        uint32_t hi1 = packsplit(O[td][2] * inv1, O[td][3] * inv1, lo1);
        aoh[(size_t)(b * S_ + r0) * (DM / 2) + cp] = hi0;
        aol[(size_t)(b * S_ + r0) * (DM / 2) + cp] = lo0;
        aoh[(size_t)(b * S_ + r1) * (DM / 2) + cp] = hi1;
        aol[(size_t)(b * S_ + r1) * (DM / 2) + cp] = lo1;
    }
}

// ---------------- launch -----------------------------------------------------------
extern "C" void kernel_launch(void* const* d_in, const int* in_sizes, int n_in,
                              void* d_out, int out_size)
{
    const float* Q  = (const float*)d_in[0];
    const float* K  = (const float*)d_in[1];
    const float* V  = (const float*)d_in[2];
    const float* Wq = (const float*)d_in[3];
    const float* Wk = (const float*)d_in[4];
    const float* Wv = (const float*)d_in[5];
    const float* Wo = (const float*)d_in[6];
    float* out = (float*)d_out;

    float *gq, *gk, *gv;
    uint32_t *qh, *ql, *wqh, *wql, *woh, *wol, *aoh, *aol;
    uint2 *kc, *vc;
    cudaGetSymbolAddress((void**)&gq,  g_q);
    cudaGetSymbolAddress((void**)&gk,  g_k);
    cudaGetSymbolAddress((void**)&gv,  g_v);
    cudaGetSymbolAddress((void**)&qh,  g_qh);
    cudaGetSymbolAddress((void**)&ql,  g_ql);
    cudaGetSymbolAddress((void**)&wqh, g_wqh);
    cudaGetSymbolAddress((void**)&wql, g_wql);
    cudaGetSymbolAddress((void**)&woh, g_woh);
    cudaGetSymbolAddress((void**)&wol, g_wol);
    cudaGetSymbolAddress((void**)&aoh, g_aoh);
    cudaGetSymbolAddress((void**)&aol, g_aol);
    cudaGetSymbolAddress((void**)&kc,  g_kc);
    cudaGetSymbolAddress((void**)&vc,  g_vc);

    cudaFuncSetAttribute(mqa_attn_mma,
                         cudaFuncAttributeMaxDynamicSharedMemorySize, 65536);
    cudaFuncSetAttribute(gemm_ldsm,
                         cudaFuncAttributeMaxDynamicSharedMemorySize, GSM_TOT);

    // conversions to bf16 planes
    conv_planes   <<<(BS * DM / 2 + 255) / 256, 256>>>(Q, qh, ql, BS * DM / 2);
    conv_wt_planes<<<(DM * DM / 2 + 255) / 256, 256>>>(Wq, wqh, wql, DM, DM);
    conv_wt_planes<<<(DM * DM / 2 + 255) / 256, 256>>>(Wo, woh, wol, DM, DM);

    // Q projection (ldmatrix + mma.sync bf16x3)
    gemm_ldsm<<<dim3(DM / 64, BS / 128), 128, GSM_TOT>>>(
        (const uint4*)qh, (const uint4*)ql, (const uint4*)wqh, (const uint4*)wql,
        gq, BS, DM, DM);

    // K/V projections (fused, fp32) + attention-format conversion
    sgemm_kv<<<dim3(1, BS / 64, 2), 256>>>(K, Wk, V, Wv, gk, gv);
    conv_kv<<<(BS * DK / 2 + 255) / 256, 256>>>(gk, gv, kc, vc);

    // attention (mma.sync flash, writes bf16 planes)
    mqa_attn_mma<<<dim3(S_ / QB, H_, B_), 256, 65536>>>(gq, aoh, aol);

    // output projection (ldmatrix + mma.sync bf16x3)
    gemm_ldsm<<<dim3(DM / 64, BS / 128), 128, GSM_TOT>>>(
        (const uint4*)aoh, (const uint4*)aol, (const uint4*)woh, (const uint4*)wol,
        out, BS, DM, DM);
}

// round 9
// speedup vs baseline: 4.2426x; 1.0265x over previous
#include <cuda_runtime.h>
#include <cuda_bf16.h>
#include <cstdint>

#define B_  2
#define S_  2048
#define DM  1024
#define H_  16
#define DK  64
#define DV  64
#define BS  (B_*S_)   // 4096

// ---------------- scratch ----------------------------------------------------
__device__ float    g_q  [BS * DM];          // Q-proj output (fp32, read by attn)
__device__ float    g_k  [BS * DK];
__device__ float    g_v  [BS * DV];
__device__ uint32_t g_qh [BS * DM / 2];      // input Q hi plane (bf16x2)
__device__ uint32_t g_ql [BS * DM / 2];      // input Q lo plane
__device__ uint32_t g_wqh[DM * DM / 2];      // W_q^T [N][K] hi plane
__device__ uint32_t g_wql[DM * DM / 2];
__device__ uint32_t g_woh[DM * DM / 2];      // W_o^T [N][K] hi plane
__device__ uint32_t g_wol[DM * DM / 2];
__device__ uint32_t g_aoh[BS * DM / 2];      // attention out hi plane
__device__ uint32_t g_aol[BS * DM / 2];
__device__ uint2    g_kc[BS * DK / 2];       // K pairs (attention), row=(b,s)
__device__ uint2    g_vc[B_ * DV * (S_ / 2)];// V^T pairs (attention), row=(b,d)

// ---------------- helpers ------------------------------------------------------
__device__ __forceinline__ uint32_t packsplit(float x, float y, uint32_t &lo) {
    __nv_bfloat162 h = __floats2bfloat162_rn(x, y);
    float hx = __bfloat162float(__low2bfloat16(h));
    float hy = __bfloat162float(__high2bfloat16(h));
    __nv_bfloat162 l2 = __floats2bfloat162_rn(x - hx, y - hy);
    lo = *reinterpret_cast<uint32_t*>(&l2);
    return *reinterpret_cast<uint32_t*>(&h);
}

__device__ __forceinline__ void cp_async16(void* smem, const void* gmem) {
    uint32_t s = (uint32_t)__cvta_generic_to_shared(smem);
    asm volatile("cp.async.cg.shared.global [%0], [%1], 16;" :: "r"(s), "l"(gmem));
}

__device__ __forceinline__ uint32_t smem_u32(const void* p) {
    return (uint32_t)__cvta_generic_to_shared(p);
}

__device__ __forceinline__ float ex2f(float x) {
    float y;
    asm("ex2.approx.f32 %0, %1;" : "=f"(y) : "f"(x));
    return y;
}

__device__ __forceinline__ void mma_bf16(float* d, const uint32_t* a, const uint32_t* b) {
    asm volatile(
        "mma.sync.aligned.m16n8k16.row.col.f32.bf16.bf16.f32 "
        "{%0,%1,%2,%3},{%4,%5,%6,%7},{%8,%9},{%0,%1,%2,%3};"
        : "+f"(d[0]), "+f"(d[1]), "+f"(d[2]), "+f"(d[3])
        : "r"(a[0]), "r"(a[1]), "r"(a[2]), "r"(a[3]), "r"(b[0]), "r"(b[1]));
}

__device__ __forceinline__ void ldsm_x4(uint32_t* r, uint32_t addr) {
    asm volatile("ldmatrix.sync.aligned.m8n8.x4.shared.b16 {%0,%1,%2,%3}, [%4];"
                 : "=r"(r[0]), "=r"(r[1]), "=r"(r[2]), "=r"(r[3]) : "r"(addr));
}

// ---------------- conversion kernels --------------------------------------------
__global__ __launch_bounds__(256)
void conv_planes(const float* __restrict__ A, uint32_t* __restrict__ Hi,
                 uint32_t* __restrict__ Lo, int npairs)
{
    int idx = blockIdx.x * blockDim.x + threadIdx.x;
    if (idx >= npairs) return;
    float2 p = ((const float2*)A)[idx];
    uint32_t lo;
    uint32_t hi = packsplit(p.x, p.y, lo);
    Hi[idx] = hi;
    Lo[idx] = lo;
}

// W [K][N] fp32 -> W^T planes [N][K] (bf16x2 along K)
__global__ __launch_bounds__(256)
void conv_wt_planes(const float* __restrict__ W, uint32_t* __restrict__ Hi,
                    uint32_t* __restrict__ Lo, int K, int N)
{
    int idx = blockIdx.x * blockDim.x + threadIdx.x;   // p * N + n
    if (idx >= N * (K / 2)) return;
    int p = idx / N;
    int n = idx - p * N;
    float x = W[(size_t)(2 * p)     * N + n];
    float y = W[(size_t)(2 * p + 1) * N + n];
    uint32_t lo;
    uint32_t hi = packsplit(x, y, lo);
    Hi[(size_t)n * (K / 2) + p] = hi;
    Lo[(size_t)n * (K / 2) + p] = lo;
}

// ---------------- bf16x3 GEMM with ldmatrix (unchanged from R8) ------------------
#define GSM_TOT 98304

__global__ __launch_bounds__(128)
void gemm_ldsm(const uint4* __restrict__ Ah, const uint4* __restrict__ Al,
               const uint4* __restrict__ Bh, const uint4* __restrict__ Bl,
               float* __restrict__ C, int M, int Ntot, int K)
{
    extern __shared__ __align__(128) char dsm[];
    const uint32_t sb = smem_u32(dsm);

    const int tid = threadIdx.x;
    const int l   = tid & 31;
    const int w   = tid >> 5;
    const int bn  = blockIdx.x * 64;
    const int bm  = blockIdx.y * 128;
    const int K8  = K >> 3;

    const int e = l & 3;
    const int q = l >> 2;

    const int rA0 = w * 32 + (l & 7) + ((l >> 3) & 1) * 8;
    const int jAh = (l >> 4) & 1;
    const int rB0 = (l & 7) + ((l >> 4) & 1) * 8;
    const int jBh = (l >> 3) & 1;
    const int cA  = rA0 & 7;
    const int cB  = rB0 & 7;

    float acc[2][8][4];
    #pragma unroll
    for (int i = 0; i < 2; i++)
        #pragma unroll
        for (int j = 0; j < 8; j++)
            #pragma unroll
            for (int t = 0; t < 4; t++) acc[i][j][t] = 0.f;

    #define STAGE(buf, k0)                                                          \
    {                                                                               \
        const int kq = (k0) >> 3;                                                   \
        _Pragma("unroll")                                                           \
        for (int i = 0; i < 16; i++) {                                              \
            int id = tid + 128 * i;                                                 \
            int pl = id >> 10;                                                      \
            int rem = id & 1023;                                                    \
            int r = rem >> 3, j = rem & 7;                                          \
            cp_async16(dsm + (((buf) * 2 + pl) * 128 + r) * 128                     \
                           + ((j ^ (r & 7)) << 4),                                  \
                       (pl ? Al : Ah) + (size_t)(bm + r) * K8 + kq + j);            \
        }                                                                           \
        _Pragma("unroll")                                                           \
        for (int i = 0; i < 8; i++) {                                               \
            int id = tid + 128 * i;                                                 \
            int pl = id >> 9;                                                       \
            int rem = id & 511;                                                     \
            int r = rem >> 3, j = rem & 7;                                          \
            cp_async16(dsm + 65536 + (((buf) * 2 + pl) * 64 + r) * 128              \
                           + ((j ^ (r & 7)) << 4),                                  \
                       (pl ? Bl : Bh) + (size_t)(bn + r) * K8 + kq + j);            \
        }                                                                           \
        asm volatile("cp.async.commit_group;");                                     \
    }

    const int niter = K / 64;
    STAGE(0, 0);

    for (int it = 0; it < niter; it++) {
        if (it + 1 < niter) {
            STAGE((it + 1) & 1, (it + 1) * 64);
            asm volatile("cp.async.wait_group 1;");
        } else {
            asm volatile("cp.async.wait_group 0;");
        }
        __syncthreads();

        const int buf = it & 1;
        const uint32_t aBaseH = sb + ((buf * 2 + 0) * 128) * 128;
        const uint32_t aBaseL = sb + ((buf * 2 + 1) * 128) * 128;
        const uint32_t bBaseH = sb + 65536 + ((buf * 2 + 0) * 64) * 128;
        const uint32_t bBaseL = sb + 65536 + ((buf * 2 + 1) * 64) * 128;

        #pragma unroll
        for (int kk = 0; kk < 4; kk++) {
            const uint32_t offA = (uint32_t)(((2 * kk + jAh) ^ cA) << 4);
            const uint32_t offB = (uint32_t)(((2 * kk + jBh) ^ cB) << 4);

            uint32_t ah[2][4], al_[2][4];
            #pragma unroll
            for (int mi = 0; mi < 2; mi++) {
                uint32_t rb = (uint32_t)((rA0 + mi * 16) * 128);
                ldsm_x4(ah[mi],  aBaseH + rb + offA);
                ldsm_x4(al_[mi], aBaseL + rb + offA);
            }

            #pragma unroll
            for (int ni2 = 0; ni2 < 4; ni2++) {
                uint32_t rb = (uint32_t)((rB0 + ni2 * 16) * 128);
                uint32_t bh4[4], bl4[4];
                ldsm_x4(bh4, bBaseH + rb + offB);
                ldsm_x4(bl4, bBaseL + rb + offB);
                uint32_t bhE[2] = {bh4[0], bh4[1]};
                uint32_t bhO[2] = {bh4[2], bh4[3]};
                uint32_t blE[2] = {bl4[0], bl4[1]};
                uint32_t blO[2] = {bl4[2], bl4[3]};
                #pragma unroll
                for (int mi = 0; mi < 2; mi++) {
                    mma_bf16(acc[mi][2 * ni2],     ah[mi],  bhE);
                    mma_bf16(acc[mi][2 * ni2],     al_[mi], bhE);
                    mma_bf16(acc[mi][2 * ni2],     ah[mi],  blE);
                    mma_bf16(acc[mi][2 * ni2 + 1], ah[mi],  bhO);
                    mma_bf16(acc[mi][2 * ni2 + 1], al_[mi], bhO);
                    mma_bf16(acc[mi][2 * ni2 + 1], ah[mi],  blO);
                }
            }
        }
        __syncthreads();
    }
    #undef STAGE

    #pragma unroll
    for (int mi = 0; mi < 2; mi++) {
        int r = bm + w * 32 + mi * 16 + q;
        #pragma unroll
        for (int ni = 0; ni < 8; ni++) {
            int c = bn + ni * 8 + e * 2;
            *(float2*)(C + (size_t)r * Ntot + c)       = make_float2(acc[mi][ni][0], acc[mi][ni][1]);
            *(float2*)(C + (size_t)(r + 8) * Ntot + c) = make_float2(acc[mi][ni][2], acc[mi][ni][3]);
        }
    }
}

// ---------------- fused K/V projection (fp32, N=64) -----------------------------
__global__ __launch_bounds__(256)
void sgemm_kv(const float* __restrict__ Kin, const float* __restrict__ Wk,
              const float* __restrict__ Vin, const float* __restrict__ Wv,
              float* __restrict__ Ck, float* __restrict__ Cv)
{
    __shared__ float As[16][68];
    __shared__ float Bs[16][64];

    const float* A = blockIdx.z ? Vin : Kin;
    const float* W = blockIdx.z ? Wv  : Wk;
    float*       C = blockIdx.z ? Cv  : Ck;
    const int N = 64, K = DM;

    const int tid = threadIdx.x;
    const int tx  = tid & 15;
    const int ty  = tid >> 4;
    const int bm  = blockIdx.y * 64;

    const int arow = tid >> 2;
    const int acol = (tid & 3) * 4;
    const int brow = tid >> 4;
    const int bcol = (tid & 15) * 4;

    float acc[4][4] = {};

    for (int k0 = 0; k0 < K; k0 += 16) {
        float4 a4 = *(const float4*)(A + (size_t)(bm + arow) * K + k0 + acol);
        As[acol + 0][arow] = a4.x;
        As[acol + 1][arow] = a4.y;
        As[acol + 2][arow] = a4.z;
        As[acol + 3][arow] = a4.w;
        *(float4*)&Bs[brow][bcol] =
            *(const float4*)(W + (size_t)(k0 + brow) * N + bcol);
        __syncthreads();

        #pragma unroll
        for (int k = 0; k < 16; k++) {
            float4 av = *(const float4*)&As[k][ty * 4];
            float4 bv = *(const float4*)&Bs[k][tx * 4];
            float a_[4] = {av.x, av.y, av.z, av.w};
            float b_[4] = {bv.x, bv.y, bv.z, bv.w};
            #pragma unroll
            for (int i = 0; i < 4; i++)
                #pragma unroll
                for (int j = 0; j < 4; j++)
                    acc[i][j] += a_[i] * b_[j];
        }
        __syncthreads();
    }

    #pragma unroll
    for (int i = 0; i < 4; i++) {
        float4 o = make_float4(acc[i][0], acc[i][1], acc[i][2], acc[i][3]);
        *(float4*)(C + (size_t)(bm + ty * 4 + i) * N + tx * 4) = o;
    }
}

// ---------------- K/V bf16 hi/lo prep (V transposed), for attention -------------
__global__ __launch_bounds__(256)
void conv_kv(const float* __restrict__ gk, const float* __restrict__ gv,
             uint2* __restrict__ kc, uint2* __restrict__ vc)
{
    int idx = blockIdx.x * blockDim.x + threadIdx.x;
    if (idx >= BS * DK / 2) return;

    float2 kp = ((const float2*)gk)[idx];
    uint32_t klo;
    uint32_t khi = packsplit(kp.x, kp.y, klo);
    kc[idx] = make_uint2(khi, klo);

    int b = idx >> 16;
    int r = idx & 65535;
    int d = r >> 10;
    int p = r & 1023;
    int s0 = 2 * p;
    float vx = gv[((size_t)(b * S_ + s0))     * DV + d];
    float vy = gv[((size_t)(b * S_ + s0 + 1)) * DV + d];
    uint32_t vlo;
    uint32_t vhi = packsplit(vx, vy, vlo);
    vc[idx] = make_uint2(vhi, vlo);
}

// ---------------- mma flash attention: fixed-max softmax -------------------------
// Scores carry log2(e)/sqrt(DK) folded into Q scale; p = ex2(s) directly.
// No running max / no rescaling (scores bounded |s| <~ 12 -> exp2 sums fit fp32
// with huge margin). Row-sum l accumulated per-lane, reduced once at the end.
#define QB 128
#define KB 64
#define QSCALE 0.1803368801111f   // (1/8) * log2(e)

__global__ __launch_bounds__(256)
void mqa_attn_mma(const float* __restrict__ gq,
                  uint32_t* __restrict__ aoh, uint32_t* __restrict__ aol)
{
    extern __shared__ __align__(16) uint2 dsma[];
    uint2* sK = dsma;
    uint2* sV = dsma + 4096;

    const int tid = threadIdx.x;
    const int l   = tid & 31;
    const int w   = tid >> 5;
    const int qb  = (S_ / QB - 1) - blockIdx.x;
    const int h   = blockIdx.y;
    const int b   = blockIdx.z;

    const int rowbase = qb * QB + w * 16;
    const int r0 = rowbase + (l >> 2);
    const int r1 = r0 + 8;
    const int e  = l & 3;
    const int Xl = (l >> 2) << 2;

    int fidx[4][2];
    #pragma unroll
    for (int ck = 0; ck < 4; ck++) {
        fidx[ck][0] = (8 * ck + e)     ^ Xl;
        fidx[ck][1] = (8 * ck + 4 + e) ^ Xl;
    }

    uint32_t qh[4][4], ql[4][4];
    {
        const float* qbase = gq + ((size_t)(b * S_)) * DM + h * DK;
        #pragma unroll
        for (int ck = 0; ck < 4; ck++) {
            int d0 = 16 * ck + e * 2;
            float2 v00 = *(const float2*)(qbase + (size_t)r0 * DM + d0);
            float2 v10 = *(const float2*)(qbase + (size_t)r1 * DM + d0);
            float2 v01 = *(const float2*)(qbase + (size_t)r0 * DM + d0 + 8);
            float2 v11 = *(const float2*)(qbase + (size_t)r1 * DM + d0 + 8);
            qh[ck][0] = packsplit(v00.x * QSCALE, v00.y * QSCALE, ql[ck][0]);
            qh[ck][1] = packsplit(v10.x * QSCALE, v10.y * QSCALE, ql[ck][1]);
            qh[ck][2] = packsplit(v01.x * QSCALE, v01.y * QSCALE, ql[ck][2]);
            qh[ck][3] = packsplit(v11.x * QSCALE, v11.y * QSCALE, ql[ck][3]);
        }
    }

    float O[8][4];
    #pragma unroll
    for (int t = 0; t < 8; t++)
        #pragma unroll
        for (int i = 0; i < 4; i++) O[t][i] = 0.f;
    float l0 = 0.f, l1 = 0.f;   // per-lane partial row sums

    const uint4* ksrc = (const uint4*)g_kc;
    const uint4* vsrc = (const uint4*)g_vc;

    #define ASTAGE(buf, kb_)                                                          \
    {                                                                                 \
        _Pragma("unroll")                                                             \
        for (int i = 0; i < 4; i++) {                                                 \
            int id = tid + 256 * i;                                                   \
            int r  = id >> 4;                                                         \
            int j  = id & 15;                                                         \
            int dg = (2 * j) ^ ((r & 7) << 2);                                        \
            cp_async16(&sK[(buf) * 2048 + r * 32 + dg],                               \
                       &ksrc[((size_t)(b * S_ + (kb_) * KB + r)) * 16 + j]);          \
            cp_async16(&sV[(buf) * 2048 + r * 32 + dg],                               \
                       &vsrc[((size_t)(b * DV + r)) * (S_ / 4) + (kb_) * 16 + j]);    \
        }                                                                             \
        asm volatile("cp.async.commit_group;");                                       \
    }

    const int nkb = qb * 2 + 2;
    ASTAGE(0, 0);

    for (int kb = 0; kb < nkb; kb++) {
        if (kb + 1 < nkb) {
            ASTAGE((kb + 1) & 1, kb + 1);
            asm volatile("cp.async.wait_group 1;");
        } else {
            asm volatile("cp.async.wait_group 0;");
        }
        __syncthreads();

        const uint2* sKb = sK + (kb & 1) * 2048;
        const uint2* sVb = sV + (kb & 1) * 2048;

        float Sf[8][4];
        #pragma unroll
        for (int t = 0; t < 8; t++)
            #pragma unroll
            for (int i = 0; i < 4; i++) Sf[t][i] = 0.f;

        #pragma unroll
        for (int ck = 0; ck < 4; ck++) {
            #pragma unroll
            for (int t = 0; t < 8; t++) {
                int kv = 8 * t + (l >> 2);
                uint2 u0 = sKb[kv * 32 + fidx[ck][0]];
                uint2 u1 = sKb[kv * 32 + fidx[ck][1]];
                uint32_t bh[2] = {u0.x, u1.x};
                uint32_t bl[2] = {u0.y, u1.y};
                mma_bf16(Sf[t], qh[ck], bh);
                mma_bf16(Sf[t], ql[ck], bh);
                mma_bf16(Sf[t], qh[ck], bl);
            }
        }

        if (kb >= 2 * qb) {
            #pragma unroll
            for (int t = 0; t < 8; t++) {
                int c0 = kb * KB + 8 * t + e * 2;
                if (c0     > r0) Sf[t][0] = -1e9f;
                if (c0 + 1 > r0) Sf[t][1] = -1e9f;
                if (c0     > r1) Sf[t][2] = -1e9f;
                if (c0 + 1 > r1) Sf[t][3] = -1e9f;
            }
        }

        // p = exp2(s); accumulate per-lane row sums (no max, no rescale)
        #pragma unroll
        for (int t = 0; t < 8; t++) {
            Sf[t][0] = ex2f(Sf[t][0]);
            Sf[t][1] = ex2f(Sf[t][1]);
            Sf[t][2] = ex2f(Sf[t][2]);
            Sf[t][3] = ex2f(Sf[t][3]);
            l0 += Sf[t][0] + Sf[t][1];
            l1 += Sf[t][2] + Sf[t][3];
        }

        uint32_t ph[4][4], pl[4][4];
        #pragma unroll
        for (int ck = 0; ck < 4; ck++) {
            ph[ck][0] = packsplit(Sf[2*ck][0],   Sf[2*ck][1],   pl[ck][0]);
            ph[ck][1] = packsplit(Sf[2*ck][2],   Sf[2*ck][3],   pl[ck][1]);
            ph[ck][2] = packsplit(Sf[2*ck+1][0], Sf[2*ck+1][1], pl[ck][2]);
            ph[ck][3] = packsplit(Sf[2*ck+1][2], Sf[2*ck+1][3], pl[ck][3]);
        }

        #pragma unroll
        for (int ck = 0; ck < 4; ck++) {
            #pragma unroll
            for (int td = 0; td < 8; td++) {
                int d = 8 * td + (l >> 2);
                uint2 u0 = sVb[d * 32 + fidx[ck][0]];
                uint2 u1 = sVb[d * 32 + fidx[ck][1]];
                uint32_t vh[2] = {u0.x, u1.x};
                uint32_t vl[2] = {u0.y, u1.y};
                mma_bf16(O[td], ph[ck], vh);
                mma_bf16(O[td], pl[ck], vh);
                mma_bf16(O[td], ph[ck], vl);
            }
        }
        __syncthreads();
    }
    #undef ASTAGE

    // single row-sum reduction at the end
    l0 += __shfl_xor_sync(0xffffffffu, l0, 1);
    l0 += __shfl_xor_sync(0xffffffffu, l0, 2);
    l1 += __shfl_xor_sync(0xffffffffu, l1, 1);
    l1 += __shfl_xor_sync(0xffffffffu, l1, 2);

    const float inv0 = 1.f / l0, inv1 = 1.f / l1;
    #pragma unroll
    for (int td = 0; td < 8; td++) {
        int d0 = 8 * td + e * 2;
        int cp = (h * DV + d0) >> 1;
        uint32_t lo0, lo1;
        uint32_t hi0 = packsplit(O[td][0] * inv0, O[td][1] * inv0, lo0);
        uint32_t hi1 = packsplit(O[td][2] * inv1, O[td][3] * inv1, lo1);
        aoh[(size_t)(b * S_ + r0) * (DM / 2) + cp] = hi0;
        aol[(size_t)(b * S_ + r0) * (DM / 2) + cp] = lo0;
        aoh[(size_t)(b * S_ + r1) * (DM / 2) + cp] = hi1;
        aol[(size_t)(b * S_ + r1) * (DM / 2) + cp] = lo1;
    }
}

// ---------------- launch -----------------------------------------------------------
extern "C" void kernel_launch(void* const* d_in, const int* in_sizes, int n_in,
                              void* d_out, int out_size)
{
    const float* Q  = (const float*)d_in[0];
    const float* K  = (const float*)d_in[1];
    const float* V  = (const float*)d_in[2];
    const float* Wq = (const float*)d_in[3];
    const float* Wk = (const float*)d_in[4];
    const float* Wv = (const float*)d_in[5];
    const float* Wo = (const float*)d_in[6];
    float* out = (float*)d_out;

    float *gq, *gk, *gv;
    uint32_t *qh, *ql, *wqh, *wql, *woh, *wol, *aoh, *aol;
    uint2 *kc, *vc;
    cudaGetSymbolAddress((void**)&gq,  g_q);
    cudaGetSymbolAddress((void**)&gk,  g_k);
    cudaGetSymbolAddress((void**)&gv,  g_v);
    cudaGetSymbolAddress((void**)&qh,  g_qh);
    cudaGetSymbolAddress((void**)&ql,  g_ql);
    cudaGetSymbolAddress((void**)&wqh, g_wqh);
    cudaGetSymbolAddress((void**)&wql, g_wql);
    cudaGetSymbolAddress((void**)&woh, g_woh);
    cudaGetSymbolAddress((void**)&wol, g_wol);
    cudaGetSymbolAddress((void**)&aoh, g_aoh);
    cudaGetSymbolAddress((void**)&aol, g_aol);
    cudaGetSymbolAddress((void**)&kc,  g_kc);
    cudaGetSymbolAddress((void**)&vc,  g_vc);

    cudaFuncSetAttribute(mqa_attn_mma,
                         cudaFuncAttributeMaxDynamicSharedMemorySize, 65536);
    cudaFuncSetAttribute(gemm_ldsm,
                         cudaFuncAttributeMaxDynamicSharedMemorySize, GSM_TOT);

    // conversions to bf16 planes
    conv_planes   <<<(BS * DM / 2 + 255) / 256, 256>>>(Q, qh, ql, BS * DM / 2);
    conv_wt_planes<<<(DM * DM / 2 + 255) / 256, 256>>>(Wq, wqh, wql, DM, DM);
    conv_wt_planes<<<(DM * DM / 2 + 255) / 256, 256>>>(Wo, woh, wol, DM, DM);

    // Q projection (ldmatrix + mma.sync bf16x3)
    gemm_ldsm<<<dim3(DM / 64, BS / 128), 128, GSM_TOT>>>(
        (const uint4*)qh, (const uint4*)ql, (const uint4*)wqh, (const uint4*)wql,
        gq, BS, DM, DM);

    // K/V projections (fused, fp32) + attention-format conversion
    sgemm_kv<<<dim3(1, BS / 64, 2), 256>>>(K, Wk, V, Wv, gk, gv);
    conv_kv<<<(BS * DK / 2 + 255) / 256, 256>>>(gk, gv, kc, vc);

    // attention (fixed-max softmax, writes bf16 planes)
    mqa_attn_mma<<<dim3(S_ / QB, H_, B_), 256, 65536>>>(gq, aoh, aol);

    // output projection (ldmatrix + mma.sync bf16x3)
    gemm_ldsm<<<dim3(DM / 64, BS / 128), 128, GSM_TOT>>>(
        (const uint4*)aoh, (const uint4*)aol, (const uint4*)woh, (const uint4*)wol,
        out, BS, DM, DM);
}

// round 10
// speedup vs baseline: 4.4038x; 1.0380x over previous
#include <cuda_runtime.h>
#include <cuda_bf16.h>
#include <cstdint>

#define B_  2
#define S_  2048
#define DM  1024
#define H_  16
#define DK  64
#define DV  64
#define BS  (B_*S_)   // 4096

// ---------------- scratch ----------------------------------------------------
__device__ float    g_q  [BS * DM];          // Q-proj output (fp32, read by attn)
__device__ float    g_k  [BS * DK];
__device__ float    g_v  [BS * DV];
__device__ uint32_t g_qh [BS * DM / 2];      // input Q hi plane (bf16x2)
__device__ uint32_t g_ql [BS * DM / 2];      // input Q lo plane
__device__ uint32_t g_wqh[DM * DM / 2];      // W_q^T [N][K] hi plane
__device__ uint32_t g_wql[DM * DM / 2];
__device__ uint32_t g_woh[DM * DM / 2];      // W_o^T [N][K] hi plane
__device__ uint32_t g_wol[DM * DM / 2];
__device__ uint32_t g_aoh[BS * DM / 2];      // attention out hi plane
__device__ uint32_t g_aol[BS * DM / 2];
__device__ uint2    g_kc[BS * DK / 2];       // K pairs (attention), row=(b,s)
__device__ uint2    g_vc[B_ * DV * (S_ / 2)];// V^T pairs (attention), row=(b,d)

// ---------------- helpers ------------------------------------------------------
__device__ __forceinline__ uint32_t packsplit(float x, float y, uint32_t &lo) {
    __nv_bfloat162 h = __floats2bfloat162_rn(x, y);
    float hx = __bfloat162float(__low2bfloat16(h));
    float hy = __bfloat162float(__high2bfloat16(h));
    __nv_bfloat162 l2 = __floats2bfloat162_rn(x - hx, y - hy);
    lo = *reinterpret_cast<uint32_t*>(&l2);
    return *reinterpret_cast<uint32_t*>(&h);
}

__device__ __forceinline__ void cp_async16(void* smem, const void* gmem) {
    uint32_t s = (uint32_t)__cvta_generic_to_shared(smem);
    asm volatile("cp.async.cg.shared.global [%0], [%1], 16;" :: "r"(s), "l"(gmem));
}

__device__ __forceinline__ uint32_t smem_u32(const void* p) {
    return (uint32_t)__cvta_generic_to_shared(p);
}

__device__ __forceinline__ float ex2f(float x) {
    float y;
    asm("ex2.approx.f32 %0, %1;" : "=f"(y) : "f"(x));
    return y;
}

__device__ __forceinline__ void mma_bf16(float* d, const uint32_t* a, const uint32_t* b) {
    asm volatile(
        "mma.sync.aligned.m16n8k16.row.col.f32.bf16.bf16.f32 "
        "{%0,%1,%2,%3},{%4,%5,%6,%7},{%8,%9},{%0,%1,%2,%3};"
        : "+f"(d[0]), "+f"(d[1]), "+f"(d[2]), "+f"(d[3])
        : "r"(a[0]), "r"(a[1]), "r"(a[2]), "r"(a[3]), "r"(b[0]), "r"(b[1]));
}

__device__ __forceinline__ void ldsm_x4(uint32_t* r, uint32_t addr) {
    asm volatile("ldmatrix.sync.aligned.m8n8.x4.shared.b16 {%0,%1,%2,%3}, [%4];"
                 : "=r"(r[0]), "=r"(r[1]), "=r"(r[2]), "=r"(r[3]) : "r"(addr));
}

// ---------------- conversion kernels --------------------------------------------
__global__ __launch_bounds__(256)
void conv_planes(const float* __restrict__ A, uint32_t* __restrict__ Hi,
                 uint32_t* __restrict__ Lo, int npairs)
{
    int idx = blockIdx.x * blockDim.x + threadIdx.x;
    if (idx >= npairs) return;
    float2 p = ((const float2*)A)[idx];
    uint32_t lo;
    uint32_t hi = packsplit(p.x, p.y, lo);
    Hi[idx] = hi;
    Lo[idx] = lo;
}

// W [K][N] fp32 -> W^T planes [N][K] (bf16x2 along K)
__global__ __launch_bounds__(256)
void conv_wt_planes(const float* __restrict__ W, uint32_t* __restrict__ Hi,
                    uint32_t* __restrict__ Lo, int K, int N)
{
    int idx = blockIdx.x * blockDim.x + threadIdx.x;   // p * N + n
    if (idx >= N * (K / 2)) return;
    int p = idx / N;
    int n = idx - p * N;
    float x = W[(size_t)(2 * p)     * N + n];
    float y = W[(size_t)(2 * p + 1) * N + n];
    uint32_t lo;
    uint32_t hi = packsplit(x, y, lo);
    Hi[(size_t)n * (K / 2) + p] = hi;
    Lo[(size_t)n * (K / 2) + p] = lo;
}

// ---------------- bf16x3 GEMM with ldmatrix (unchanged) --------------------------
#define GSM_TOT 98304

__global__ __launch_bounds__(128)
void gemm_ldsm(const uint4* __restrict__ Ah, const uint4* __restrict__ Al,
               const uint4* __restrict__ Bh, const uint4* __restrict__ Bl,
               float* __restrict__ C, int M, int Ntot, int K)
{
    extern __shared__ __align__(128) char dsm[];
    const uint32_t sb = smem_u32(dsm);

    const int tid = threadIdx.x;
    const int l   = tid & 31;
    const int w   = tid >> 5;
    const int bn  = blockIdx.x * 64;
    const int bm  = blockIdx.y * 128;
    const int K8  = K >> 3;

    const int e = l & 3;
    const int q = l >> 2;

    const int rA0 = w * 32 + (l & 7) + ((l >> 3) & 1) * 8;
    const int jAh = (l >> 4) & 1;
    const int rB0 = (l & 7) + ((l >> 4) & 1) * 8;
    const int jBh = (l >> 3) & 1;
    const int cA  = rA0 & 7;
    const int cB  = rB0 & 7;

    float acc[2][8][4];
    #pragma unroll
    for (int i = 0; i < 2; i++)
        #pragma unroll
        for (int j = 0; j < 8; j++)
            #pragma unroll
            for (int t = 0; t < 4; t++) acc[i][j][t] = 0.f;

    #define STAGE(buf, k0)                                                          \
    {                                                                               \
        const int kq = (k0) >> 3;                                                   \
        _Pragma("unroll")                                                           \
        for (int i = 0; i < 16; i++) {                                              \
            int id = tid + 128 * i;                                                 \
            int pl = id >> 10;                                                      \
            int rem = id & 1023;                                                    \
            int r = rem >> 3, j = rem & 7;                                          \
            cp_async16(dsm + (((buf) * 2 + pl) * 128 + r) * 128                     \
                           + ((j ^ (r & 7)) << 4),                                  \
                       (pl ? Al : Ah) + (size_t)(bm + r) * K8 + kq + j);            \
        }                                                                           \
        _Pragma("unroll")                                                           \
        for (int i = 0; i < 8; i++) {                                               \
            int id = tid + 128 * i;                                                 \
            int pl = id >> 9;                                                       \
            int rem = id & 511;                                                     \
            int r = rem >> 3, j = rem & 7;                                          \
            cp_async16(dsm + 65536 + (((buf) * 2 + pl) * 64 + r) * 128              \
                           + ((j ^ (r & 7)) << 4),                                  \
                       (pl ? Bl : Bh) + (size_t)(bn + r) * K8 + kq + j);            \
        }                                                                           \
        asm volatile("cp.async.commit_group;");                                     \
    }

    const int niter = K / 64;
    STAGE(0, 0);

    for (int it = 0; it < niter; it++) {
        if (it + 1 < niter) {
            STAGE((it + 1) & 1, (it + 1) * 64);
            asm volatile("cp.async.wait_group 1;");
        } else {
            asm volatile("cp.async.wait_group 0;");
        }
        __syncthreads();

        const int buf = it & 1;
        const uint32_t aBaseH = sb + ((buf * 2 + 0) * 128) * 128;
        const uint32_t aBaseL = sb + ((buf * 2 + 1) * 128) * 128;
        const uint32_t bBaseH = sb + 65536 + ((buf * 2 + 0) * 64) * 128;
        const uint32_t bBaseL = sb + 65536 + ((buf * 2 + 1) * 64) * 128;

        #pragma unroll
        for (int kk = 0; kk < 4; kk++) {
            const uint32_t offA = (uint32_t)(((2 * kk + jAh) ^ cA) << 4);
            const uint32_t offB = (uint32_t)(((2 * kk + jBh) ^ cB) << 4);

            uint32_t ah[2][4], al_[2][4];
            #pragma unroll
            for (int mi = 0; mi < 2; mi++) {
                uint32_t rb = (uint32_t)((rA0 + mi * 16) * 128);
                ldsm_x4(ah[mi],  aBaseH + rb + offA);
                ldsm_x4(al_[mi], aBaseL + rb + offA);
            }

            #pragma unroll
            for (int ni2 = 0; ni2 < 4; ni2++) {
                uint32_t rb = (uint32_t)((rB0 + ni2 * 16) * 128);
                uint32_t bh4[4], bl4[4];
                ldsm_x4(bh4, bBaseH + rb + offB);
                ldsm_x4(bl4, bBaseL + rb + offB);
                uint32_t bhE[2] = {bh4[0], bh4[1]};
                uint32_t bhO[2] = {bh4[2], bh4[3]};
                uint32_t blE[2] = {bl4[0], bl4[1]};
                uint32_t blO[2] = {bl4[2], bl4[3]};
                #pragma unroll
                for (int mi = 0; mi < 2; mi++) {
                    mma_bf16(acc[mi][2 * ni2],     ah[mi],  bhE);
                    mma_bf16(acc[mi][2 * ni2],     al_[mi], bhE);
                    mma_bf16(acc[mi][2 * ni2],     ah[mi],  blE);
                    mma_bf16(acc[mi][2 * ni2 + 1], ah[mi],  bhO);
                    mma_bf16(acc[mi][2 * ni2 + 1], al_[mi], bhO);
                    mma_bf16(acc[mi][2 * ni2 + 1], ah[mi],  blO);
                }
            }
        }
        __syncthreads();
    }
    #undef STAGE

    #pragma unroll
    for (int mi = 0; mi < 2; mi++) {
        int r = bm + w * 32 + mi * 16 + q;
        #pragma unroll
        for (int ni = 0; ni < 8; ni++) {
            int c = bn + ni * 8 + e * 2;
            *(float2*)(C + (size_t)r * Ntot + c)       = make_float2(acc[mi][ni][0], acc[mi][ni][1]);
            *(float2*)(C + (size_t)(r + 8) * Ntot + c) = make_float2(acc[mi][ni][2], acc[mi][ni][3]);
        }
    }
}

// ---------------- fused K/V projection (fp32, N=64) -----------------------------
__global__ __launch_bounds__(256)
void sgemm_kv(const float* __restrict__ Kin, const float* __restrict__ Wk,
              const float* __restrict__ Vin, const float* __restrict__ Wv,
              float* __restrict__ Ck, float* __restrict__ Cv)
{
    __shared__ float As[16][68];
    __shared__ float Bs[16][64];

    const float* A = blockIdx.z ? Vin : Kin;
    const float* W = blockIdx.z ? Wv  : Wk;
    float*       C = blockIdx.z ? Cv  : Ck;
    const int N = 64, K = DM;

    const int tid = threadIdx.x;
    const int tx  = tid & 15;
    const int ty  = tid >> 4;
    const int bm  = blockIdx.y * 64;

    const int arow = tid >> 2;
    const int acol = (tid & 3) * 4;
    const int brow = tid >> 4;
    const int bcol = (tid & 15) * 4;

    float acc[4][4] = {};

    for (int k0 = 0; k0 < K; k0 += 16) {
        float4 a4 = *(const float4*)(A + (size_t)(bm + arow) * K + k0 + acol);
        As[acol + 0][arow] = a4.x;
        As[acol + 1][arow] = a4.y;
        As[acol + 2][arow] = a4.z;
        As[acol + 3][arow] = a4.w;
        *(float4*)&Bs[brow][bcol] =
            *(const float4*)(W + (size_t)(k0 + brow) * N + bcol);
        __syncthreads();

        #pragma unroll
        for (int k = 0; k < 16; k++) {
            float4 av = *(const float4*)&As[k][ty * 4];
            float4 bv = *(const float4*)&Bs[k][tx * 4];
            float a_[4] = {av.x, av.y, av.z, av.w};
            float b_[4] = {bv.x, bv.y, bv.z, bv.w};
            #pragma unroll
            for (int i = 0; i < 4; i++)
                #pragma unroll
                for (int j = 0; j < 4; j++)
                    acc[i][j] += a_[i] * b_[j];
        }
        __syncthreads();
    }

    #pragma unroll
    for (int i = 0; i < 4; i++) {
        float4 o = make_float4(acc[i][0], acc[i][1], acc[i][2], acc[i][3]);
        *(float4*)(C + (size_t)(bm + ty * 4 + i) * N + tx * 4) = o;
    }
}

// ---------------- K/V bf16 hi/lo prep (V transposed), for attention -------------
__global__ __launch_bounds__(256)
void conv_kv(const float* __restrict__ gk, const float* __restrict__ gv,
             uint2* __restrict__ kc, uint2* __restrict__ vc)
{
    int idx = blockIdx.x * blockDim.x + threadIdx.x;
    if (idx >= BS * DK / 2) return;

    float2 kp = ((const float2*)gk)[idx];
    uint32_t klo;
    uint32_t khi = packsplit(kp.x, kp.y, klo);
    kc[idx] = make_uint2(khi, klo);

    int b = idx >> 16;
    int r = idx & 65535;
    int d = r >> 10;
    int p = r & 1023;
    int s0 = 2 * p;
    float vx = gv[((size_t)(b * S_ + s0))     * DV + d];
    float vy = gv[((size_t)(b * S_ + s0 + 1)) * DV + d];
    uint32_t vlo;
    uint32_t vhi = packsplit(vx, vy, vlo);
    vc[idx] = make_uint2(vhi, vlo);
}

// ---------------- mma flash attention: QB=64, 4 warps, 3 CTAs/SM -----------------
// Fixed-max softmax (log2e folded into Q scale). KV tiles of 64 double-buffered.
#define QB 64
#define KB 64
#define QSCALE 0.1803368801111f   // (1/8) * log2(e)

__global__ __launch_bounds__(128, 3)
void mqa_attn_mma(const float* __restrict__ gq,
                  uint32_t* __restrict__ aoh, uint32_t* __restrict__ aol)
{
    extern __shared__ __align__(16) uint2 dsma[];
    uint2* sK = dsma;          // [2][2048]
    uint2* sV = dsma + 4096;   // [2][2048]

    const int tid = threadIdx.x;
    const int l   = tid & 31;
    const int w   = tid >> 5;                  // 0..3
    const int qb  = (S_ / QB - 1) - blockIdx.x;   // big workloads first
    const int h   = blockIdx.y;
    const int b   = blockIdx.z;

    const int rowbase = qb * QB + w * 16;
    const int r0 = rowbase + (l >> 2);
    const int r1 = r0 + 8;
    const int e  = l & 3;
    const int Xl = (l >> 2) << 2;

    int fidx[4][2];
    #pragma unroll
    for (int ck = 0; ck < 4; ck++) {
        fidx[ck][0] = (8 * ck + e)     ^ Xl;
        fidx[ck][1] = (8 * ck + 4 + e) ^ Xl;
    }

    uint32_t qh[4][4], ql[4][4];
    {
        const float* qbase = gq + ((size_t)(b * S_)) * DM + h * DK;
        #pragma unroll
        for (int ck = 0; ck < 4; ck++) {
            int d0 = 16 * ck + e * 2;
            float2 v00 = *(const float2*)(qbase + (size_t)r0 * DM + d0);
            float2 v10 = *(const float2*)(qbase + (size_t)r1 * DM + d0);
            float2 v01 = *(const float2*)(qbase + (size_t)r0 * DM + d0 + 8);
            float2 v11 = *(const float2*)(qbase + (size_t)r1 * DM + d0 + 8);
            qh[ck][0] = packsplit(v00.x * QSCALE, v00.y * QSCALE, ql[ck][0]);
            qh[ck][1] = packsplit(v10.x * QSCALE, v10.y * QSCALE, ql[ck][1]);
            qh[ck][2] = packsplit(v01.x * QSCALE, v01.y * QSCALE, ql[ck][2]);
            qh[ck][3] = packsplit(v11.x * QSCALE, v11.y * QSCALE, ql[ck][3]);
        }
    }

    float O[8][4];
    #pragma unroll
    for (int t = 0; t < 8; t++)
        #pragma unroll
        for (int i = 0; i < 4; i++) O[t][i] = 0.f;
    float l0 = 0.f, l1 = 0.f;

    const uint4* ksrc = (const uint4*)g_kc;
    const uint4* vsrc = (const uint4*)g_vc;

    #define ASTAGE(buf, kb_)                                                          \
    {                                                                                 \
        _Pragma("unroll")                                                             \
        for (int i = 0; i < 8; i++) {                                                 \
            int id = tid + 128 * i;          /* 0..1023 */                            \
            int r  = id >> 4;                                                         \
            int j  = id & 15;                                                         \
            int dg = (2 * j) ^ ((r & 7) << 2);                                        \
            cp_async16(&sK[(buf) * 2048 + r * 32 + dg],                               \
                       &ksrc[((size_t)(b * S_ + (kb_) * KB + r)) * 16 + j]);          \
            cp_async16(&sV[(buf) * 2048 + r * 32 + dg],                               \
                       &vsrc[((size_t)(b * DV + r)) * (S_ / 4) + (kb_) * 16 + j]);    \
        }                                                                             \
        asm volatile("cp.async.commit_group;");                                       \
    }

    const int nkb = qb + 1;
    ASTAGE(0, 0);

    for (int kb = 0; kb < nkb; kb++) {
        if (kb + 1 < nkb) {
            ASTAGE((kb + 1) & 1, kb + 1);
            asm volatile("cp.async.wait_group 1;");
        } else {
            asm volatile("cp.async.wait_group 0;");
        }
        __syncthreads();

        const uint2* sKb = sK + (kb & 1) * 2048;
        const uint2* sVb = sV + (kb & 1) * 2048;

        float Sf[8][4];
        #pragma unroll
        for (int t = 0; t < 8; t++)
            #pragma unroll
            for (int i = 0; i < 4; i++) Sf[t][i] = 0.f;

        #pragma unroll
        for (int ck = 0; ck < 4; ck++) {
            #pragma unroll
            for (int t = 0; t < 8; t++) {
                int kv = 8 * t + (l >> 2);
                uint2 u0 = sKb[kv * 32 + fidx[ck][0]];
                uint2 u1 = sKb[kv * 32 + fidx[ck][1]];
                uint32_t bh[2] = {u0.x, u1.x};
                uint32_t bl[2] = {u0.y, u1.y};
                mma_bf16(Sf[t], qh[ck], bh);
                mma_bf16(Sf[t], ql[ck], bh);
                mma_bf16(Sf[t], qh[ck], bl);
            }
        }

        if (kb >= qb) {          // diagonal tile
            #pragma unroll
            for (int t = 0; t < 8; t++) {
                int c0 = kb * KB + 8 * t + e * 2;
                if (c0     > r0) Sf[t][0] = -1e9f;
                if (c0 + 1 > r0) Sf[t][1] = -1e9f;
                if (c0     > r1) Sf[t][2] = -1e9f;
                if (c0 + 1 > r1) Sf[t][3] = -1e9f;
            }
        }

        #pragma unroll
        for (int t = 0; t < 8; t++) {
            Sf[t][0] = ex2f(Sf[t][0]);
            Sf[t][1] = ex2f(Sf[t][1]);
            Sf[t][2] = ex2f(Sf[t][2]);
            Sf[t][3] = ex2f(Sf[t][3]);
            l0 += Sf[t][0] + Sf[t][1];
            l1 += Sf[t][2] + Sf[t][3];
        }

        uint32_t ph[4][4], pl[4][4];
        #pragma unroll
        for (int ck = 0; ck < 4; ck++) {
            ph[ck][0] = packsplit(Sf[2*ck][0],   Sf[2*ck][1],   pl[ck][0]);
            ph[ck][1] = packsplit(Sf[2*ck][2],   Sf[2*ck][3],   pl[ck][1]);
            ph[ck][2] = packsplit(Sf[2*ck+1][0], Sf[2*ck+1][1], pl[ck][2]);
            ph[ck][3] = packsplit(Sf[2*ck+1][2], Sf[2*ck+1][3], pl[ck][3]);
        }

        #pragma unroll
        for (int ck = 0; ck < 4; ck++) {
            #pragma unroll
            for (int td = 0; td < 8; td++) {
                int d = 8 * td + (l >> 2);
                uint2 u0 = sVb[d * 32 + fidx[ck][0]];
                uint2 u1 = sVb[d * 32 + fidx[ck][1]];
                uint32_t vh[2] = {u0.x, u1.x};
                uint32_t vl[2] = {u0.y, u1.y};
                mma_bf16(O[td], ph[ck], vh);
                mma_bf16(O[td], pl[ck], vh);
                mma_bf16(O[td], ph[ck], vl);
            }
        }
        __syncthreads();
    }
    #undef ASTAGE

    l0 += __shfl_xor_sync(0xffffffffu, l0, 1);
    l0 += __shfl_xor_sync(0xffffffffu, l0, 2);
    l1 += __shfl_xor_sync(0xffffffffu, l1, 1);
    l1 += __shfl_xor_sync(0xffffffffu, l1, 2);

    const float inv0 = 1.f / l0, inv1 = 1.f / l1;
    #pragma unroll
    for (int td = 0; td < 8; td++) {
        int d0 = 8 * td + e * 2;
        int cp = (h * DV + d0) >> 1;
        uint32_t lo0, lo1;
        uint32_t hi0 = packsplit(O[td][0] * inv0, O[td][1] * inv0, lo0);
        uint32_t hi1 = packsplit(O[td][2] * inv1, O[td][3] * inv1, lo1);
        aoh[(size_t)(b * S_ + r0) * (DM / 2) + cp] = hi0;
        aol[(size_t)(b * S_ + r0) * (DM / 2) + cp] = lo0;
        aoh[(size_t)(b * S_ + r1) * (DM / 2) + cp] = hi1;
        aol[(size_t)(b * S_ + r1) * (DM / 2) + cp] = lo1;
    }
}

// ---------------- launch -----------------------------------------------------------
extern "C" void kernel_launch(void* const* d_in, const int* in_sizes, int n_in,
                              void* d_out, int out_size)
{
    const float* Q  = (const float*)d_in[0];
    const float* K  = (const float*)d_in[1];
    const float* V  = (const float*)d_in[2];
    const float* Wq = (const float*)d_in[3];
    const float* Wk = (const float*)d_in[4];
    const float* Wv = (const float*)d_in[5];
    const float* Wo = (const float*)d_in[6];
    float* out = (float*)d_out;

    float *gq, *gk, *gv;
    uint32_t *qh, *ql, *wqh, *wql, *woh, *wol, *aoh, *aol;
    uint2 *kc, *vc;
    cudaGetSymbolAddress((void**)&gq,  g_q);
    cudaGetSymbolAddress((void**)&gk,  g_k);
    cudaGetSymbolAddress((void**)&gv,  g_v);
    cudaGetSymbolAddress((void**)&qh,  g_qh);
    cudaGetSymbolAddress((void**)&ql,  g_ql);
    cudaGetSymbolAddress((void**)&wqh, g_wqh);
    cudaGetSymbolAddress((void**)&wql, g_wql);
    cudaGetSymbolAddress((void**)&woh, g_woh);
    cudaGetSymbolAddress((void**)&wol, g_wol);
    cudaGetSymbolAddress((void**)&aoh, g_aoh);
    cudaGetSymbolAddress((void**)&aol, g_aol);
    cudaGetSymbolAddress((void**)&kc,  g_kc);
    cudaGetSymbolAddress((void**)&vc,  g_vc);

    cudaFuncSetAttribute(mqa_attn_mma,
                         cudaFuncAttributeMaxDynamicSharedMemorySize, 65536);
    cudaFuncSetAttribute(gemm_ldsm,
                         cudaFuncAttributeMaxDynamicSharedMemorySize, GSM_TOT);

    // conversions to bf16 planes
    conv_planes   <<<(BS * DM / 2 + 255) / 256, 256>>>(Q, qh, ql, BS * DM / 2);
    conv_wt_planes<<<(DM * DM / 2 + 255) / 256, 256>>>(Wq, wqh, wql, DM, DM);
    conv_wt_planes<<<(DM * DM / 2 + 255) / 256, 256>>>(Wo, woh, wol, DM, DM);

    // Q projection (ldmatrix + mma.sync bf16x3)
    gemm_ldsm<<<dim3(DM / 64, BS / 128), 128, GSM_TOT>>>(
        (const uint4*)qh, (const uint4*)ql, (const uint4*)wqh, (const uint4*)wql,
        gq, BS, DM, DM);

    // K/V projections (fused, fp32) + attention-format conversion
    sgemm_kv<<<dim3(1, BS / 64, 2), 256>>>(K, Wk, V, Wv, gk, gv);
    conv_kv<<<(BS * DK / 2 + 255) / 256, 256>>>(gk, gv, kc, vc);

    // attention (QB=64, 3 CTAs/SM, writes bf16 planes)
    mqa_attn_mma<<<dim3(S_ / QB, H_, B_), 128, 65536>>>(gq, aoh, aol);

    // output projection (ldmatrix + mma.sync bf16x3)
    gemm_ldsm<<<dim3(DM / 64, BS / 128), 128, GSM_TOT>>>(
        (const uint4*)aoh, (const uint4*)aol, (const uint4*)woh, (const uint4*)wol,
        out, BS, DM, DM);
}

// round 12
// speedup vs baseline: 4.7353x; 1.0753x over previous
#include <cuda_runtime.h>
#include <cuda_bf16.h>
#include <cuda_fp16.h>
#include <cstdint>

#define B_  2
#define S_  2048
#define DM  1024
#define H_  16
#define DK  64
#define DV  64
#define BS  (B_*S_)   // 4096

// ---------------- scratch ----------------------------------------------------
__device__ float    g_q  [BS * DM];          // Q-proj output (fp32, read by attn)
__device__ uint32_t g_qh [BS * DM / 2];      // input Q hi plane (bf16x2)
__device__ uint32_t g_ql [BS * DM / 2];      // input Q lo plane
__device__ uint32_t g_wqh[DM * DM / 2];      // W_q^T [N][K] hi plane
__device__ uint32_t g_wql[DM * DM / 2];
__device__ uint32_t g_woh[DM * DM / 2];      // W_o^T [N][K] hi plane
__device__ uint32_t g_wol[DM * DM / 2];
__device__ uint32_t g_aoh[BS * DM / 2];      // attention out hi plane
__device__ uint32_t g_aol[BS * DM / 2];
__device__ uint2    g_kc[BS * DK / 2];       // K bf16 pairs, row=(b,s)
__device__ uint2    g_vc[B_ * DV * (S_ / 2)];// V^T fp16 pairs, row=(b,d)

// ---------------- helpers ------------------------------------------------------
__device__ __forceinline__ uint32_t packsplit(float x, float y, uint32_t &lo) {
    __nv_bfloat162 h = __floats2bfloat162_rn(x, y);
    float hx = __bfloat162float(__low2bfloat16(h));
    float hy = __bfloat162float(__high2bfloat16(h));
    __nv_bfloat162 l2 = __floats2bfloat162_rn(x - hx, y - hy);
    lo = *reinterpret_cast<uint32_t*>(&l2);
    return *reinterpret_cast<uint32_t*>(&h);
}

// fp16 hi/lo split (for V)
__device__ __forceinline__ uint32_t packsplit_h(float x, float y, uint32_t &lo) {
    __half2 h = __floats2half2_rn(x, y);
    float hx = __half2float(__low2half(h));
    float hy = __half2float(__high2half(h));
    __half2 l2 = __floats2half2_rn(x - hx, y - hy);
    lo = *reinterpret_cast<uint32_t*>(&l2);
    return *reinterpret_cast<uint32_t*>(&h);
}

__device__ __forceinline__ uint32_t packh2(float x, float y) {
    __half2 h = __floats2half2_rn(x, y);
    return *reinterpret_cast<uint32_t*>(&h);
}

__device__ __forceinline__ void cp_async16(void* smem, const void* gmem) {
    uint32_t s = (uint32_t)__cvta_generic_to_shared(smem);
    asm volatile("cp.async.cg.shared.global [%0], [%1], 16;" :: "r"(s), "l"(gmem));
}

__device__ __forceinline__ uint32_t smem_u32(const void* p) {
    return (uint32_t)__cvta_generic_to_shared(p);
}

__device__ __forceinline__ float ex2f(float x) {
    float y;
    asm("ex2.approx.f32 %0, %1;" : "=f"(y) : "f"(x));
    return y;
}

__device__ __forceinline__ void mma_bf16(float* d, const uint32_t* a, const uint32_t* b) {
    asm volatile(
        "mma.sync.aligned.m16n8k16.row.col.f32.bf16.bf16.f32 "
        "{%0,%1,%2,%3},{%4,%5,%6,%7},{%8,%9},{%0,%1,%2,%3};"
        : "+f"(d[0]), "+f"(d[1]), "+f"(d[2]), "+f"(d[3])
        : "r"(a[0]), "r"(a[1]), "r"(a[2]), "r"(a[3]), "r"(b[0]), "r"(b[1]));
}

__device__ __forceinline__ void mma_f16(float* d, const uint32_t* a, const uint32_t* b) {
    asm volatile(
        "mma.sync.aligned.m16n8k16.row.col.f32.f16.f16.f32 "
        "{%0,%1,%2,%3},{%4,%5,%6,%7},{%8,%9},{%0,%1,%2,%3};"
        : "+f"(d[0]), "+f"(d[1]), "+f"(d[2]), "+f"(d[3])
        : "r"(a[0]), "r"(a[1]), "r"(a[2]), "r"(a[3]), "r"(b[0]), "r"(b[1]));
}

__device__ __forceinline__ void ldsm_x4(uint32_t* r, uint32_t addr) {
    asm volatile("ldmatrix.sync.aligned.m8n8.x4.shared.b16 {%0,%1,%2,%3}, [%4];"
                 : "=r"(r[0]), "=r"(r[1]), "=r"(r[2]), "=r"(r[3]) : "r"(addr));
}

// ---------------- conversion kernels --------------------------------------------
__global__ __launch_bounds__(256)
void conv_planes(const float* __restrict__ A, uint32_t* __restrict__ Hi,
                 uint32_t* __restrict__ Lo, int npairs)
{
    int idx = blockIdx.x * blockDim.x + threadIdx.x;
    if (idx >= npairs) return;
    float2 p = ((const float2*)A)[idx];
    uint32_t lo;
    uint32_t hi = packsplit(p.x, p.y, lo);
    Hi[idx] = hi;
    Lo[idx] = lo;
}

// W [K][N] fp32 -> W^T planes [N][K] (bf16x2 along K)
__global__ __launch_bounds__(256)
void conv_wt_planes(const float* __restrict__ W, uint32_t* __restrict__ Hi,
                    uint32_t* __restrict__ Lo, int K, int N)
{
    int idx = blockIdx.x * blockDim.x + threadIdx.x;   // p * N + n
    if (idx >= N * (K / 2)) return;
    int p = idx / N;
    int n = idx - p * N;
    float x = W[(size_t)(2 * p)     * N + n];
    float y = W[(size_t)(2 * p + 1) * N + n];
    uint32_t lo;
    uint32_t hi = packsplit(x, y, lo);
    Hi[(size_t)n * (K / 2) + p] = hi;
    Lo[(size_t)n * (K / 2) + p] = lo;
}

// ---------------- bf16x3 GEMM with ldmatrix (unchanged) --------------------------
#define GSM_TOT 98304

__global__ __launch_bounds__(128)
void gemm_ldsm(const uint4* __restrict__ Ah, const uint4* __restrict__ Al,
               const uint4* __restrict__ Bh, const uint4* __restrict__ Bl,
               float* __restrict__ C, int M, int Ntot, int K)
{
    extern __shared__ __align__(128) char dsm[];
    const uint32_t sb = smem_u32(dsm);

    const int tid = threadIdx.x;
    const int l   = tid & 31;
    const int w   = tid >> 5;
    const int bn  = blockIdx.x * 64;
    const int bm  = blockIdx.y * 128;
    const int K8  = K >> 3;

    const int e = l & 3;
    const int q = l >> 2;

    const int rA0 = w * 32 + (l & 7) + ((l >> 3) & 1) * 8;
    const int jAh = (l >> 4) & 1;
    const int rB0 = (l & 7) + ((l >> 4) & 1) * 8;
    const int jBh = (l >> 3) & 1;
    const int cA  = rA0 & 7;
    const int cB  = rB0 & 7;

    float acc[2][8][4];
    #pragma unroll
    for (int i = 0; i < 2; i++)
        #pragma unroll
        for (int j = 0; j < 8; j++)
            #pragma unroll
            for (int t = 0; t < 4; t++) acc[i][j][t] = 0.f;

    #define STAGE(buf, k0)                                                          \
    {                                                                               \
        const int kq = (k0) >> 3;                                                   \
        _Pragma("unroll")                                                           \
        for (int i = 0; i < 16; i++) {                                              \
            int id = tid + 128 * i;                                                 \
            int pl = id >> 10;                                                      \
            int rem = id & 1023;                                                    \
            int r = rem >> 3, j = rem & 7;                                          \
            cp_async16(dsm + (((buf) * 2 + pl) * 128 + r) * 128                     \
                           + ((j ^ (r & 7)) << 4),                                  \
                       (pl ? Al : Ah) + (size_t)(bm + r) * K8 + kq + j);            \
        }                                                                           \
        _Pragma("unroll")                                                           \
        for (int i = 0; i < 8; i++) {                                               \
            int id = tid + 128 * i;                                                 \
            int pl = id >> 9;                                                       \
            int rem = id & 511;                                                     \
            int r = rem >> 3, j = rem & 7;                                          \
            cp_async16(dsm + 65536 + (((buf) * 2 + pl) * 64 + r) * 128              \
                           + ((j ^ (r & 7)) << 4),                                  \
                       (pl ? Bl : Bh) + (size_t)(bn + r) * K8 + kq + j);            \
        }                                                                           \
        asm volatile("cp.async.commit_group;");                                     \
    }

    const int niter = K / 64;
    STAGE(0, 0);

    for (int it = 0; it < niter; it++) {
        if (it + 1 < niter) {
            STAGE((it + 1) & 1, (it + 1) * 64);
            asm volatile("cp.async.wait_group 1;");
        } else {
            asm volatile("cp.async.wait_group 0;");
        }
        __syncthreads();

        const int buf = it & 1;
        const uint32_t aBaseH = sb + ((buf * 2 + 0) * 128) * 128;
        const uint32_t aBaseL = sb + ((buf * 2 + 1) * 128) * 128;
        const uint32_t bBaseH = sb + 65536 + ((buf * 2 + 0) * 64) * 128;
        const uint32_t bBaseL = sb + 65536 + ((buf * 2 + 1) * 64) * 128;

        #pragma unroll
        for (int kk = 0; kk < 4; kk++) {
            const uint32_t offA = (uint32_t)(((2 * kk + jAh) ^ cA) << 4);
            const uint32_t offB = (uint32_t)(((2 * kk + jBh) ^ cB) << 4);

            uint32_t ah[2][4], al_[2][4];
            #pragma unroll
            for (int mi = 0; mi < 2; mi++) {
                uint32_t rb = (uint32_t)((rA0 + mi * 16) * 128);
                ldsm_x4(ah[mi],  aBaseH + rb + offA);
                ldsm_x4(al_[mi], aBaseL + rb + offA);
            }

            #pragma unroll
            for (int ni2 = 0; ni2 < 4; ni2++) {
                uint32_t rb = (uint32_t)((rB0 + ni2 * 16) * 128);
                uint32_t bh4[4], bl4[4];
                ldsm_x4(bh4, bBaseH + rb + offB);
                ldsm_x4(bl4, bBaseL + rb + offB);
                uint32_t bhE[2] = {bh4[0], bh4[1]};
                uint32_t bhO[2] = {bh4[2], bh4[3]};
                uint32_t blE[2] = {bl4[0], bl4[1]};
                uint32_t blO[2] = {bl4[2], bl4[3]};
                #pragma unroll
                for (int mi = 0; mi < 2; mi++) {
                    mma_bf16(acc[mi][2 * ni2],     ah[mi],  bhE);
                    mma_bf16(acc[mi][2 * ni2],     al_[mi], bhE);
                    mma_bf16(acc[mi][2 * ni2],     ah[mi],  blE);
                    mma_bf16(acc[mi][2 * ni2 + 1], ah[mi],  bhO);
                    mma_bf16(acc[mi][2 * ni2 + 1], al_[mi], bhO);
                    mma_bf16(acc[mi][2 * ni2 + 1], ah[mi],  blO);
                }
            }
        }
        __syncthreads();
    }
    #undef STAGE

    #pragma unroll
    for (int mi = 0; mi < 2; mi++) {
        int r = bm + w * 32 + mi * 16 + q;
        #pragma unroll
        for (int ni = 0; ni < 8; ni++) {
            int c = bn + ni * 8 + e * 2;
            *(float2*)(C + (size_t)r * Ntot + c)       = make_float2(acc[mi][ni][0], acc[mi][ni][1]);
            *(float2*)(C + (size_t)(r + 8) * Ntot + c) = make_float2(acc[mi][ni][2], acc[mi][ni][3]);
        }
    }
}

// ---------------- fused K/V projection -> attention-format pairs ----------------
// z=0: K -> g_kc bf16 pairs [row][kpair]; z=1: V -> g_vc fp16 pairs [(b,d)][spair].
__global__ __launch_bounds__(256)
void sgemm_kv(const float* __restrict__ Kin, const float* __restrict__ Wk,
              const float* __restrict__ Vin, const float* __restrict__ Wv,
              uint2* __restrict__ kc, uint2* __restrict__ vc)
{
    __shared__ float As[16][68];
    __shared__ float Bs[16][64];

    const int isV = blockIdx.z;
    const float* A = isV ? Vin : Kin;
    const float* W = isV ? Wv  : Wk;
    const int N = 64, K = DM;

    const int tid = threadIdx.x;
    const int tx  = tid & 15;
    const int ty  = tid >> 4;
    const int bm  = blockIdx.y * 64;

    const int arow = tid >> 2;
    const int acol = (tid & 3) * 4;
    const int brow = tid >> 4;
    const int bcol = (tid & 15) * 4;

    float acc[4][4] = {};

    for (int k0 = 0; k0 < K; k0 += 16) {
        float4 a4 = *(const float4*)(A + (size_t)(bm + arow) * K + k0 + acol);
        As[acol + 0][arow] = a4.x;
        As[acol + 1][arow] = a4.y;
        As[acol + 2][arow] = a4.z;
        As[acol + 3][arow] = a4.w;
        *(float4*)&Bs[brow][bcol] =
            *(const float4*)(W + (size_t)(k0 + brow) * N + bcol);
        __syncthreads();

        #pragma unroll
        for (int k = 0; k < 16; k++) {
            float4 av = *(const float4*)&As[k][ty * 4];
            float4 bv = *(const float4*)&Bs[k][tx * 4];
            float a_[4] = {av.x, av.y, av.z, av.w};
            float b_[4] = {bv.x, bv.y, bv.z, bv.w};
            #pragma unroll
            for (int i = 0; i < 4; i++)
                #pragma unroll
                for (int j = 0; j < 4; j++)
                    acc[i][j] += a_[i] * b_[j];
        }
        __syncthreads();
    }

    const int r = bm + ty * 4;          // global row (4 consecutive)
    if (!isV) {
        // K: bf16 pairs along d
        #pragma unroll
        for (int i = 0; i < 4; i++) {
            uint32_t lo0, lo1;
            uint32_t hi0 = packsplit(acc[i][0], acc[i][1], lo0);
            uint32_t hi1 = packsplit(acc[i][2], acc[i][3], lo1);
            kc[(size_t)(r + i) * 32 + tx * 2 + 0] = make_uint2(hi0, lo0);
            kc[(size_t)(r + i) * 32 + tx * 2 + 1] = make_uint2(hi1, lo1);
        }
    } else {
        // V^T: fp16 pairs along s; row = (b*DV + d), col = s/2
        const int b = r >> 11;
        const int s = r & 2047;
        #pragma unroll
        for (int j = 0; j < 4; j++) {
            int d = tx * 4 + j;
            uint32_t lo0, lo1;
            uint32_t hi0 = packsplit_h(acc[0][j], acc[1][j], lo0);
            uint32_t hi1 = packsplit_h(acc[2][j], acc[3][j], lo1);
            size_t base = (size_t)(b * DV + d) * (S_ / 2) + (s >> 1);
            vc[base + 0] = make_uint2(hi0, lo0);
            vc[base + 1] = make_uint2(hi1, lo1);
        }
    }
}

// ---------------- mma flash attention: fp16 single-plane P -----------------------
// Fixed-max softmax; QK in bf16x3 (exponent-sensitive), PV in fp16 (P single
// plane, 2^-12 per-element rounding -> ~2e-4 output error; V hi+lo corrected).
#define QB 64
#define KB 64
#define QSCALE 0.1803368801111f   // (1/8) * log2(e)

__global__ __launch_bounds__(128, 3)
void mqa_attn_mma(const float* __restrict__ gq,
                  uint32_t* __restrict__ aoh, uint32_t* __restrict__ aol)
{
    extern __shared__ __align__(16) uint2 dsma[];
    uint2* sK = dsma;          // [2][2048]
    uint2* sV = dsma + 4096;   // [2][2048]

    const int tid = threadIdx.x;
    const int l   = tid & 31;
    const int w   = tid >> 5;
    const int qb  = (S_ / QB - 1) - blockIdx.x;   // big workloads first
    const int h   = blockIdx.y;
    const int b   = blockIdx.z;

    const int rowbase = qb * QB + w * 16;
    const int r0 = rowbase + (l >> 2);
    const int r1 = r0 + 8;
    const int e  = l & 3;
    const int Xl = (l >> 2) << 2;

    int fidx[4][2];
    #pragma unroll
    for (int ck = 0; ck < 4; ck++) {
        fidx[ck][0] = (8 * ck + e)     ^ Xl;
        fidx[ck][1] = (8 * ck + 4 + e) ^ Xl;
    }

    uint32_t qh[4][4], ql[4][4];
    {
        const float* qbase = gq + ((size_t)(b * S_)) * DM + h * DK;
        #pragma unroll
        for (int ck = 0; ck < 4; ck++) {
            int d0 = 16 * ck + e * 2;
            float2 v00 = *(const float2*)(qbase + (size_t)r0 * DM + d0);
            float2 v10 = *(const float2*)(qbase + (size_t)r1 * DM + d0);
            float2 v01 = *(const float2*)(qbase + (size_t)r0 * DM + d0 + 8);
            float2 v11 = *(const float2*)(qbase + (size_t)r1 * DM + d0 + 8);
            qh[ck][0] = packsplit(v00.x * QSCALE, v00.y * QSCALE, ql[ck][0]);
            qh[ck][1] = packsplit(v10.x * QSCALE, v10.y * QSCALE, ql[ck][1]);
            qh[ck][2] = packsplit(v01.x * QSCALE, v01.y * QSCALE, ql[ck][2]);
            qh[ck][3] = packsplit(v11.x * QSCALE, v11.y * QSCALE, ql[ck][3]);
        }
    }

    float O[8][4];
    #pragma unroll
    for (int t = 0; t < 8; t++)
        #pragma unroll
        for (int i = 0; i < 4; i++) O[t][i] = 0.f;
    float l0 = 0.f, l1 = 0.f;

    const uint4* ksrc = (const uint4*)g_kc;
    const uint4* vsrc = (const uint4*)g_vc;

    #define ASTAGE(buf, kb_)                                                          \
    {                                                                                 \
        _Pragma("unroll")                                                             \
        for (int i = 0; i < 8; i++) {                                                 \
            int id = tid + 128 * i;                                                   \
            int r  = id >> 4;                                                         \
            int j  = id & 15;                                                         \
            int dg = (2 * j) ^ ((r & 7) << 2);                                        \
            cp_async16(&sK[(buf) * 2048 + r * 32 + dg],                               \
                       &ksrc[((size_t)(b * S_ + (kb_) * KB + r)) * 16 + j]);          \
            cp_async16(&sV[(buf) * 2048 + r * 32 + dg],                               \
                       &vsrc[((size_t)(b * DV + r)) * (S_ / 4) + (kb_) * 16 + j]);    \
        }                                                                             \
        asm volatile("cp.async.commit_group;");                                       \
    }

    const int nkb = qb + 1;
    ASTAGE(0, 0);

    for (int kb = 0; kb < nkb; kb++) {
        if (kb + 1 < nkb) {
            ASTAGE((kb + 1) & 1, kb + 1);
            asm volatile("cp.async.wait_group 1;");
        } else {
            asm volatile("cp.async.wait_group 0;");
        }
        __syncthreads();

        const uint2* sKb = sK + (kb & 1) * 2048;
        const uint2* sVb = sV + (kb & 1) * 2048;

        float Sf[8][4];
        #pragma unroll
        for (int t = 0; t < 8; t++)
            #pragma unroll
            for (int i = 0; i < 4; i++) Sf[t][i] = 0.f;

        #pragma unroll
        for (int ck = 0; ck < 4; ck++) {
            #pragma unroll
            for (int t = 0; t < 8; t++) {
                int kv = 8 * t + (l >> 2);
                uint2 u0 = sKb[kv * 32 + fidx[ck][0]];
                uint2 u1 = sKb[kv * 32 + fidx[ck][1]];
                uint32_t bh[2] = {u0.x, u1.x};
                uint32_t bl[2] = {u0.y, u1.y};
                mma_bf16(Sf[t], qh[ck], bh);
                mma_bf16(Sf[t], ql[ck], bh);
                mma_bf16(Sf[t], qh[ck], bl);
            }
        }

        if (kb >= qb) {          // diagonal tile
            #pragma unroll
            for (int t = 0; t < 8; t++) {
                int c0 = kb * KB + 8 * t + e * 2;
                if (c0     > r0) Sf[t][0] = -1e9f;
                if (c0 + 1 > r0) Sf[t][1] = -1e9f;
                if (c0     > r1) Sf[t][2] = -1e9f;
                if (c0 + 1 > r1) Sf[t][3] = -1e9f;
            }
        }

        // p = exp2(s); single fp16 P plane; l accumulated in fp32
        uint32_t ph[4][4];
        #pragma unroll
        for (int t = 0; t < 8; t++) {
            float p0 = ex2f(Sf[t][0]);
            float p1 = ex2f(Sf[t][1]);
            float p2 = ex2f(Sf[t][2]);
            float p3 = ex2f(Sf[t][3]);
            l0 += p0 + p1;
            l1 += p2 + p3;
            ph[t >> 1][(t & 1) * 2 + 0] = packh2(p0, p1);
            ph[t >> 1][(t & 1) * 2 + 1] = packh2(p2, p3);
        }

        // O += P (V_hi + V_lo)   (fp16 MMAs, 2 per pair)
        #pragma unroll
        for (int ck = 0; ck < 4; ck++) {
            #pragma unroll
            for (int td = 0; td < 8; td++) {
                int d = 8 * td + (l >> 2);
                uint2 u0 = sVb[d * 32 + fidx[ck][0]];
                uint2 u1 = sVb[d * 32 + fidx[ck][1]];
                uint32_t vh[2] = {u0.x, u1.x};
                uint32_t vl[2] = {u0.y, u1.y};
                mma_f16(O[td], ph[ck], vh);
                mma_f16(O[td], ph[ck], vl);
            }
        }
        __syncthreads();
    }
    #undef ASTAGE

    l0 += __shfl_xor_sync(0xffffffffu, l0, 1);
    l0 += __shfl_xor_sync(0xffffffffu, l0, 2);
    l1 += __shfl_xor_sync(0xffffffffu, l1, 1);
    l1 += __shfl_xor_sync(0xffffffffu, l1, 2);

    const float inv0 = 1.f / l0, inv1 = 1.f / l1;
    #pragma unroll
    for (int td = 0; td < 8; td++) {
        int d0 = 8 * td + e * 2;
        int cp = (h * DV + d0) >> 1;
        uint32_t lo0, lo1;
        uint32_t hi0 = packsplit(O[td][0] * inv0, O[td][1] * inv0, lo0);
        uint32_t hi1 = packsplit(O[td][2] * inv1, O[td][3] * inv1, lo1);
        aoh[(size_t)(b * S_ + r0) * (DM / 2) + cp] = hi0;
        aol[(size_t)(b * S_ + r0) * (DM / 2) + cp] = lo0;
        aoh[(size_t)(b * S_ + r1) * (DM / 2) + cp] = hi1;
        aol[(size_t)(b * S_ + r1) * (DM / 2) + cp] = lo1;
    }
}

// ---------------- launch -----------------------------------------------------------
extern "C" void kernel_launch(void* const* d_in, const int* in_sizes, int n_in,
                              void* d_out, int out_size)
{
    const float* Q  = (const float*)d_in[0];
    const float* K  = (const float*)d_in[1];
    const float* V  = (const float*)d_in[2];
    const float* Wq = (const float*)d_in[3];
    const float* Wk = (const float*)d_in[4];
    const float* Wv = (const float*)d_in[5];
    const float* Wo = (const float*)d_in[6];
    float* out = (float*)d_out;

    float *gq;
    uint32_t *qh, *ql, *wqh, *wql, *woh, *wol, *aoh, *aol;
    uint2 *kc, *vc;
    cudaGetSymbolAddress((void**)&gq,  g_q);
    cudaGetSymbolAddress((void**)&qh,  g_qh);
    cudaGetSymbolAddress((void**)&ql,  g_ql);
    cudaGetSymbolAddress((void**)&wqh, g_wqh);
    cudaGetSymbolAddress((void**)&wql, g_wql);
    cudaGetSymbolAddress((void**)&woh, g_woh);
    cudaGetSymbolAddress((void**)&wol, g_wol);
    cudaGetSymbolAddress((void**)&aoh, g_aoh);
    cudaGetSymbolAddress((void**)&aol, g_aol);
    cudaGetSymbolAddress((void**)&kc,  g_kc);
    cudaGetSymbolAddress((void**)&vc,  g_vc);

    cudaFuncSetAttribute(mqa_attn_mma,
                         cudaFuncAttributeMaxDynamicSharedMemorySize, 65536);
    cudaFuncSetAttribute(gemm_ldsm,
                         cudaFuncAttributeMaxDynamicSharedMemorySize, GSM_TOT);

    // conversions to bf16 planes
    conv_planes   <<<(BS * DM / 2 + 255) / 256, 256>>>(Q, qh, ql, BS * DM / 2);
    conv_wt_planes<<<(DM * DM / 2 + 255) / 256, 256>>>(Wq, wqh, wql, DM, DM);
    conv_wt_planes<<<(DM * DM / 2 + 255) / 256, 256>>>(Wo, woh, wol, DM, DM);

    // Q projection (ldmatrix + mma.sync bf16x3)
    gemm_ldsm<<<dim3(DM / 64, BS / 128), 128, GSM_TOT>>>(
        (const uint4*)qh, (const uint4*)ql, (const uint4*)wqh, (const uint4*)wql,
        gq, BS, DM, DM);

    // K/V projections -> attention-format pairs directly
    sgemm_kv<<<dim3(1, BS / 64, 2), 256>>>(K, Wk, V, Wv, kc, vc);

    // attention (fp16 single-plane P, writes bf16 planes)
    mqa_attn_mma<<<dim3(S_ / QB, H_, B_), 128, 65536>>>(gq, aoh, aol);

    // output projection (ldmatrix + mma.sync bf16x3)
    gemm_ldsm<<<dim3(DM / 64, BS / 128), 128, GSM_TOT>>>(
        (const uint4*)aoh, (const uint4*)aol, (const uint4*)woh, (const uint4*)wol,
        out, BS, DM, DM);
}

// round 13
// speedup vs baseline: 5.7375x; 1.2117x over previous
#include <cuda_runtime.h>
#include <cuda_bf16.h>
#include <cuda_fp16.h>
#include <cstdint>

#define B_  2
#define S_  2048
#define DM  1024
#define H_  16
#define DK  64
#define DV  64
#define BS  (B_*S_)   // 4096

// ---------------- scratch ----------------------------------------------------
__device__ float    g_q  [BS * DM];          // Q-proj output (fp32, read by attn)
__device__ uint32_t g_qh [BS * DM / 2];      // input Q hi plane (bf16x2)
__device__ uint32_t g_ql [BS * DM / 2];      // input Q lo plane
__device__ uint32_t g_wqh[DM * DM / 2];      // W_q^T [N][K] hi plane
__device__ uint32_t g_wql[DM * DM / 2];
__device__ uint32_t g_woh[DM * DM / 2];      // W_o^T [N][K] hi plane
__device__ uint32_t g_wol[DM * DM / 2];
__device__ uint32_t g_aoh[BS * DM / 2];      // attention out hi plane
__device__ uint32_t g_aol[BS * DM / 2];
__device__ uint32_t g_kc[BS * DK / 2];       // K fp16 pairs (single plane), row=(b,s)
__device__ uint32_t g_vc[B_ * DV * (S_ / 2)];// V^T fp16 pairs (single plane), row=(b,d)

// ---------------- helpers ------------------------------------------------------
__device__ __forceinline__ uint32_t packsplit(float x, float y, uint32_t &lo) {
    __nv_bfloat162 h = __floats2bfloat162_rn(x, y);
    float hx = __bfloat162float(__low2bfloat16(h));
    float hy = __bfloat162float(__high2bfloat16(h));
    __nv_bfloat162 l2 = __floats2bfloat162_rn(x - hx, y - hy);
    lo = *reinterpret_cast<uint32_t*>(&l2);
    return *reinterpret_cast<uint32_t*>(&h);
}

// fp16 hi/lo split (for Q in attention)
__device__ __forceinline__ uint32_t packsplit_h(float x, float y, uint32_t &lo) {
    __half2 h = __floats2half2_rn(x, y);
    float hx = __half2float(__low2half(h));
    float hy = __half2float(__high2half(h));
    __half2 l2 = __floats2half2_rn(x - hx, y - hy);
    lo = *reinterpret_cast<uint32_t*>(&l2);
    return *reinterpret_cast<uint32_t*>(&h);
}

__device__ __forceinline__ uint32_t packh2(float x, float y) {
    __half2 h = __floats2half2_rn(x, y);
    return *reinterpret_cast<uint32_t*>(&h);
}

__device__ __forceinline__ void cp_async16(void* smem, const void* gmem) {
    uint32_t s = (uint32_t)__cvta_generic_to_shared(smem);
    asm volatile("cp.async.cg.shared.global [%0], [%1], 16;" :: "r"(s), "l"(gmem));
}

__device__ __forceinline__ uint32_t smem_u32(const void* p) {
    return (uint32_t)__cvta_generic_to_shared(p);
}

__device__ __forceinline__ float ex2f(float x) {
    float y;
    asm("ex2.approx.f32 %0, %1;" : "=f"(y) : "f"(x));
    return y;
}

__device__ __forceinline__ void mma_bf16(float* d, const uint32_t* a, const uint32_t* b) {
    asm volatile(
        "mma.sync.aligned.m16n8k16.row.col.f32.bf16.bf16.f32 "
        "{%0,%1,%2,%3},{%4,%5,%6,%7},{%8,%9},{%0,%1,%2,%3};"
        : "+f"(d[0]), "+f"(d[1]), "+f"(d[2]), "+f"(d[3])
        : "r"(a[0]), "r"(a[1]), "r"(a[2]), "r"(a[3]), "r"(b[0]), "r"(b[1]));
}

__device__ __forceinline__ void mma_f16(float* d, const uint32_t* a, const uint32_t* b) {
    asm volatile(
        "mma.sync.aligned.m16n8k16.row.col.f32.f16.f16.f32 "
        "{%0,%1,%2,%3},{%4,%5,%6,%7},{%8,%9},{%0,%1,%2,%3};"
        : "+f"(d[0]), "+f"(d[1]), "+f"(d[2]), "+f"(d[3])
        : "r"(a[0]), "r"(a[1]), "r"(a[2]), "r"(a[3]), "r"(b[0]), "r"(b[1]));
}

__device__ __forceinline__ void ldsm_x4(uint32_t* r, uint32_t addr) {
    asm volatile("ldmatrix.sync.aligned.m8n8.x4.shared.b16 {%0,%1,%2,%3}, [%4];"
                 : "=r"(r[0]), "=r"(r[1]), "=r"(r[2]), "=r"(r[3]) : "r"(addr));
}

// ---------------- conversion kernels --------------------------------------------
__global__ __launch_bounds__(256)
void conv_planes(const float* __restrict__ A, uint32_t* __restrict__ Hi,
                 uint32_t* __restrict__ Lo, int npairs)
{
    int idx = blockIdx.x * blockDim.x + threadIdx.x;
    if (idx >= npairs) return;
    float2 p = ((const float2*)A)[idx];
    uint32_t lo;
    uint32_t hi = packsplit(p.x, p.y, lo);
    Hi[idx] = hi;
    Lo[idx] = lo;
}

// W [K][N] fp32 -> W^T planes [N][K] (bf16x2 along K)
__global__ __launch_bounds__(256)
void conv_wt_planes(const float* __restrict__ W, uint32_t* __restrict__ Hi,
                    uint32_t* __restrict__ Lo, int K, int N)
{
    int idx = blockIdx.x * blockDim.x + threadIdx.x;   // p * N + n
    if (idx >= N * (K / 2)) return;
    int p = idx / N;
    int n = idx - p * N;
    float x = W[(size_t)(2 * p)     * N + n];
    float y = W[(size_t)(2 * p + 1) * N + n];
    uint32_t lo;
    uint32_t hi = packsplit(x, y, lo);
    Hi[(size_t)n * (K / 2) + p] = hi;
    Lo[(size_t)n * (K / 2) + p] = lo;
}

// ---------------- bf16x3 GEMM with ldmatrix (unchanged) --------------------------
#define GSM_TOT 98304

__global__ __launch_bounds__(128)
void gemm_ldsm(const uint4* __restrict__ Ah, const uint4* __restrict__ Al,
               const uint4* __restrict__ Bh, const uint4* __restrict__ Bl,
               float* __restrict__ C, int M, int Ntot, int K)
{
    extern __shared__ __align__(128) char dsm[];
    const uint32_t sb = smem_u32(dsm);

    const int tid = threadIdx.x;
    const int l   = tid & 31;
    const int w   = tid >> 5;
    const int bn  = blockIdx.x * 64;
    const int bm  = blockIdx.y * 128;
    const int K8  = K >> 3;

    const int e = l & 3;
    const int q = l >> 2;

    const int rA0 = w * 32 + (l & 7) + ((l >> 3) & 1) * 8;
    const int jAh = (l >> 4) & 1;
    const int rB0 = (l & 7) + ((l >> 4) & 1) * 8;
    const int jBh = (l >> 3) & 1;
    const int cA  = rA0 & 7;
    const int cB  = rB0 & 7;

    float acc[2][8][4];
    #pragma unroll
    for (int i = 0; i < 2; i++)
        #pragma unroll
        for (int j = 0; j < 8; j++)
            #pragma unroll
            for (int t = 0; t < 4; t++) acc[i][j][t] = 0.f;

    #define STAGE(buf, k0)                                                          \
    {                                                                               \
        const int kq = (k0) >> 3;                                                   \
        _Pragma("unroll")                                                           \
        for (int i = 0; i < 16; i++) {                                              \
            int id = tid + 128 * i;                                                 \
            int pl = id >> 10;                                                      \
            int rem = id & 1023;                                                    \
            int r = rem >> 3, j = rem & 7;                                          \
            cp_async16(dsm + (((buf) * 2 + pl) * 128 + r) * 128                     \
                           + ((j ^ (r & 7)) << 4),                                  \
                       (pl ? Al : Ah) + (size_t)(bm + r) * K8 + kq + j);            \
        }                                                                           \
        _Pragma("unroll")                                                           \
        for (int i = 0; i < 8; i++) {                                               \
            int id = tid + 128 * i;                                                 \
            int pl = id >> 9;                                                       \
            int rem = id & 511;                                                     \
            int r = rem >> 3, j = rem & 7;                                          \
            cp_async16(dsm + 65536 + (((buf) * 2 + pl) * 64 + r) * 128              \
                           + ((j ^ (r & 7)) << 4),                                  \
                       (pl ? Bl : Bh) + (size_t)(bn + r) * K8 + kq + j);            \
        }                                                                           \
        asm volatile("cp.async.commit_group;");                                     \
    }

    const int niter = K / 64;
    STAGE(0, 0);

    for (int it = 0; it < niter; it++) {
        if (it + 1 < niter) {
            STAGE((it + 1) & 1, (it + 1) * 64);
            asm volatile("cp.async.wait_group 1;");
        } else {
            asm volatile("cp.async.wait_group 0;");
        }
        __syncthreads();

        const int buf = it & 1;
        const uint32_t aBaseH = sb + ((buf * 2 + 0) * 128) * 128;
        const uint32_t aBaseL = sb + ((buf * 2 + 1) * 128) * 128;
        const uint32_t bBaseH = sb + 65536 + ((buf * 2 + 0) * 64) * 128;
        const uint32_t bBaseL = sb + 65536 + ((buf * 2 + 1) * 64) * 128;

        #pragma unroll
        for (int kk = 0; kk < 4; kk++) {
            const uint32_t offA = (uint32_t)(((2 * kk + jAh) ^ cA) << 4);
            const uint32_t offB = (uint32_t)(((2 * kk + jBh) ^ cB) << 4);

            uint32_t ah[2][4], al_[2][4];
            #pragma unroll
            for (int mi = 0; mi < 2; mi++) {
                uint32_t rb = (uint32_t)((rA0 + mi * 16) * 128);
                ldsm_x4(ah[mi],  aBaseH + rb + offA);
                ldsm_x4(al_[mi], aBaseL + rb + offA);
            }

            #pragma unroll
            for (int ni2 = 0; ni2 < 4; ni2++) {
                uint32_t rb = (uint32_t)((rB0 + ni2 * 16) * 128);
                uint32_t bh4[4], bl4[4];
                ldsm_x4(bh4, bBaseH + rb + offB);
                ldsm_x4(bl4, bBaseL + rb + offB);
                uint32_t bhE[2] = {bh4[0], bh4[1]};
                uint32_t bhO[2] = {bh4[2], bh4[3]};
                uint32_t blE[2] = {bl4[0], bl4[1]};
                uint32_t blO[2] = {bl4[2], bl4[3]};
                #pragma unroll
                for (int mi = 0; mi < 2; mi++) {
                    mma_bf16(acc[mi][2 * ni2],     ah[mi],  bhE);
                    mma_bf16(acc[mi][2 * ni2],     al_[mi], bhE);
                    mma_bf16(acc[mi][2 * ni2],     ah[mi],  blE);
                    mma_bf16(acc[mi][2 * ni2 + 1], ah[mi],  bhO);
                    mma_bf16(acc[mi][2 * ni2 + 1], al_[mi], bhO);
                    mma_bf16(acc[mi][2 * ni2 + 1], ah[mi],  blO);
                }
            }
        }
        __syncthreads();
    }
    #undef STAGE

    #pragma unroll
    for (int mi = 0; mi < 2; mi++) {
        int r = bm + w * 32 + mi * 16 + q;
        #pragma unroll
        for (int ni = 0; ni < 8; ni++) {
            int c = bn + ni * 8 + e * 2;
            *(float2*)(C + (size_t)r * Ntot + c)       = make_float2(acc[mi][ni][0], acc[mi][ni][1]);
            *(float2*)(C + (size_t)(r + 8) * Ntot + c) = make_float2(acc[mi][ni][2], acc[mi][ni][3]);
        }
    }
}

// ---------------- fused K/V projection -> attention-format fp16 pairs -----------
// z=0: K -> g_kc fp16 pairs [row][dpair]; z=1: V -> g_vc fp16 pairs [(b,d)][spair].
__global__ __launch_bounds__(256)
void sgemm_kv(const float* __restrict__ Kin, const float* __restrict__ Wk,
              const float* __restrict__ Vin, const float* __restrict__ Wv,
              uint32_t* __restrict__ kc, uint32_t* __restrict__ vc)
{
    __shared__ float As[16][68];
    __shared__ float Bs[16][64];

    const int isV = blockIdx.z;
    const float* A = isV ? Vin : Kin;
    const float* W = isV ? Wv  : Wk;
    const int N = 64, K = DM;

    const int tid = threadIdx.x;
    const int tx  = tid & 15;
    const int ty  = tid >> 4;
    const int bm  = blockIdx.y * 64;

    const int arow = tid >> 2;
    const int acol = (tid & 3) * 4;
    const int brow = tid >> 4;
    const int bcol = (tid & 15) * 4;

    float acc[4][4] = {};

    for (int k0 = 0; k0 < K; k0 += 16) {
        float4 a4 = *(const float4*)(A + (size_t)(bm + arow) * K + k0 + acol);
        As[acol + 0][arow] = a4.x;
        As[acol + 1][arow] = a4.y;
        As[acol + 2][arow] = a4.z;
        As[acol + 3][arow] = a4.w;
        *(float4*)&Bs[brow][bcol] =
            *(const float4*)(W + (size_t)(k0 + brow) * N + bcol);
        __syncthreads();

        #pragma unroll
        for (int k = 0; k < 16; k++) {
            float4 av = *(const float4*)&As[k][ty * 4];
            float4 bv = *(const float4*)&Bs[k][tx * 4];
            float a_[4] = {av.x, av.y, av.z, av.w};
            float b_[4] = {bv.x, bv.y, bv.z, bv.w};
            #pragma unroll
            for (int i = 0; i < 4; i++)
                #pragma unroll
                for (int j = 0; j < 4; j++)
                    acc[i][j] += a_[i] * b_[j];
        }
        __syncthreads();
    }

    const int r = bm + ty * 4;          // global row (4 consecutive)
    if (!isV) {
        // K: fp16 pairs along d
        #pragma unroll
        for (int i = 0; i < 4; i++) {
            kc[(size_t)(r + i) * 32 + tx * 2 + 0] = packh2(acc[i][0], acc[i][1]);
            kc[(size_t)(r + i) * 32 + tx * 2 + 1] = packh2(acc[i][2], acc[i][3]);
        }
    } else {
        // V^T: fp16 pairs along s; row = (b*DV + d), col = s/2
        const int b = r >> 11;
        const int s = r & 2047;
        #pragma unroll
        for (int j = 0; j < 4; j++) {
            int d = tx * 4 + j;
            size_t base = (size_t)(b * DV + d) * (S_ / 2) + (s >> 1);
            vc[base + 0] = packh2(acc[0][j], acc[1][j]);
            vc[base + 1] = packh2(acc[2][j], acc[3][j]);
        }
    }
}

// ---------------- mma flash attention: all-fp16 single planes --------------------
// QK: Q 2-plane fp16 x K 1-plane fp16 (2 MMAs); PV: P 1-plane x V 1-plane (1 MMA).
// Fixed-max softmax, log2e folded into Q scale. 32KB smem (2-stage K+V).
#define QB 64
#define KB 64
#define QSCALE 0.1803368801111f   // (1/8) * log2(e)
#define ASM_TOT 32768

__global__ __launch_bounds__(128, 3)
void mqa_attn_mma(const float* __restrict__ gq,
                  uint32_t* __restrict__ aoh, uint32_t* __restrict__ aol)
{
    extern __shared__ __align__(16) uint32_t dsma[];
    uint32_t* sK = dsma;          // [2][64*32]  (uint32 = fp16 pair)
    uint32_t* sV = dsma + 4096;   // [2][64*32]

    const int tid = threadIdx.x;
    const int l   = tid & 31;
    const int w   = tid >> 5;
    const int qb  = (S_ / QB - 1) - blockIdx.x;   // big workloads first
    const int h   = blockIdx.y;
    const int b   = blockIdx.z;

    const int rowbase = qb * QB + w * 16;
    const int r0 = rowbase + (l >> 2);
    const int r1 = r0 + 8;
    const int e  = l & 3;
    const int Xl = (l >> 2) << 2;

    int fidx[4][2];
    #pragma unroll
    for (int ck = 0; ck < 4; ck++) {
        fidx[ck][0] = (8 * ck + e)     ^ Xl;
        fidx[ck][1] = (8 * ck + 4 + e) ^ Xl;
    }

    // Q fragments: fp16 hi/lo planes (scaled by QSCALE)
    uint32_t qh[4][4], ql[4][4];
    {
        const float* qbase = gq + ((size_t)(b * S_)) * DM + h * DK;
        #pragma unroll
        for (int ck = 0; ck < 4; ck++) {
            int d0 = 16 * ck + e * 2;
            float2 v00 = *(const float2*)(qbase + (size_t)r0 * DM + d0);
            float2 v10 = *(const float2*)(qbase + (size_t)r1 * DM + d0);
            float2 v01 = *(const float2*)(qbase + (size_t)r0 * DM + d0 + 8);
            float2 v11 = *(const float2*)(qbase + (size_t)r1 * DM + d0 + 8);
            qh[ck][0] = packsplit_h(v00.x * QSCALE, v00.y * QSCALE, ql[ck][0]);
            qh[ck][1] = packsplit_h(v10.x * QSCALE, v10.y * QSCALE, ql[ck][1]);
            qh[ck][2] = packsplit_h(v01.x * QSCALE, v01.y * QSCALE, ql[ck][2]);
            qh[ck][3] = packsplit_h(v11.x * QSCALE, v11.y * QSCALE, ql[ck][3]);
        }
    }

    float O[8][4];
    #pragma unroll
    for (int t = 0; t < 8; t++)
        #pragma unroll
        for (int i = 0; i < 4; i++) O[t][i] = 0.f;
    float l0 = 0.f, l1 = 0.f;

    const uint4* ksrc = (const uint4*)g_kc;
    const uint4* vsrc = (const uint4*)g_vc;

    // stage one 64-row K tile + 64-row V^T tile (single fp16 planes)
    #define ASTAGE(buf, kb_)                                                          \
    {                                                                                 \
        _Pragma("unroll")                                                             \
        for (int i = 0; i < 4; i++) {                                                 \
            int id = tid + 128 * i;          /* 0..511 */                             \
            int r  = id >> 3;                                                         \
            int j  = id & 7;                                                          \
            int dg = ((j ^ (r & 7)) << 2);                                            \
            cp_async16(&sK[(buf) * 2048 + r * 32 + dg],                               \
                       &ksrc[((size_t)(b * S_ + (kb_) * KB + r)) * 8 + j]);           \
            cp_async16(&sV[(buf) * 2048 + r * 32 + dg],                               \
                       &vsrc[((size_t)(b * DV + r)) * (S_ / 8) + (kb_) * 8 + j]);     \
        }                                                                             \
        asm volatile("cp.async.commit_group;");                                       \
    }

    const int nkb = qb + 1;
    ASTAGE(0, 0);

    for (int kb = 0; kb < nkb; kb++) {
        if (kb + 1 < nkb) {
            ASTAGE((kb + 1) & 1, kb + 1);
            asm volatile("cp.async.wait_group 1;");
        } else {
            asm volatile("cp.async.wait_group 0;");
        }
        __syncthreads();

        const uint32_t* sKb = sK + (kb & 1) * 2048;
        const uint32_t* sVb = sV + (kb & 1) * 2048;

        float Sf[8][4];
        #pragma unroll
        for (int t = 0; t < 8; t++)
            #pragma unroll
            for (int i = 0; i < 4; i++) Sf[t][i] = 0.f;

        // S = Q K^T  (2 fp16 MMAs per fragment pair)
        #pragma unroll
        for (int ck = 0; ck < 4; ck++) {
            #pragma unroll
            for (int t = 0; t < 8; t++) {
                int kv = 8 * t + (l >> 2);
                uint32_t bh[2];
                bh[0] = sKb[kv * 32 + fidx[ck][0]];
                bh[1] = sKb[kv * 32 + fidx[ck][1]];
                mma_f16(Sf[t], qh[ck], bh);
                mma_f16(Sf[t], ql[ck], bh);
            }
        }

        if (kb >= qb) {          // diagonal tile
            #pragma unroll
            for (int t = 0; t < 8; t++) {
                int c0 = kb * KB + 8 * t + e * 2;
                if (c0     > r0) Sf[t][0] = -1e9f;
                if (c0 + 1 > r0) Sf[t][1] = -1e9f;
                if (c0     > r1) Sf[t][2] = -1e9f;
                if (c0 + 1 > r1) Sf[t][3] = -1e9f;
            }
        }

        // p = exp2(s); single fp16 P plane; l accumulated in fp32
        uint32_t ph[4][4];
        #pragma unroll
        for (int t = 0; t < 8; t++) {
            float p0 = ex2f(Sf[t][0]);
            float p1 = ex2f(Sf[t][1]);
            float p2 = ex2f(Sf[t][2]);
            float p3 = ex2f(Sf[t][3]);
            l0 += p0 + p1;
            l1 += p2 + p3;
            ph[t >> 1][(t & 1) * 2 + 0] = packh2(p0, p1);
            ph[t >> 1][(t & 1) * 2 + 1] = packh2(p2, p3);
        }

        // O += P V  (1 fp16 MMA per fragment pair)
        #pragma unroll
        for (int ck = 0; ck < 4; ck++) {
            #pragma unroll
            for (int td = 0; td < 8; td++) {
                int d = 8 * td + (l >> 2);
                uint32_t vh[2];
                vh[0] = sVb[d * 32 + fidx[ck][0]];
                vh[1] = sVb[d * 32 + fidx[ck][1]];
                mma_f16(O[td], ph[ck], vh);
            }
        }
        __syncthreads();
    }
    #undef ASTAGE

    l0 += __shfl_xor_sync(0xffffffffu, l0, 1);
    l0 += __shfl_xor_sync(0xffffffffu, l0, 2);
    l1 += __shfl_xor_sync(0xffffffffu, l1, 1);
    l1 += __shfl_xor_sync(0xffffffffu, l1, 2);

    const float inv0 = 1.f / l0, inv1 = 1.f / l1;
    #pragma unroll
    for (int td = 0; td < 8; td++) {
        int d0 = 8 * td + e * 2;
        int cp = (h * DV + d0) >> 1;
        uint32_t lo0, lo1;
        uint32_t hi0 = packsplit(O[td][0] * inv0, O[td][1] * inv0, lo0);
        uint32_t hi1 = packsplit(O[td][2] * inv1, O[td][3] * inv1, lo1);
        aoh[(size_t)(b * S_ + r0) * (DM / 2) + cp] = hi0;
        aol[(size_t)(b * S_ + r0) * (DM / 2) + cp] = lo0;
        aoh[(size_t)(b * S_ + r1) * (DM / 2) + cp] = hi1;
        aol[(size_t)(b * S_ + r1) * (DM / 2) + cp] = lo1;
    }
}

// ---------------- launch -----------------------------------------------------------
extern "C" void kernel_launch(void* const* d_in, const int* in_sizes, int n_in,
                              void* d_out, int out_size)
{
    const float* Q  = (const float*)d_in[0];
    const float* K  = (const float*)d_in[1];
    const float* V  = (const float*)d_in[2];
    const float* Wq = (const float*)d_in[3];
    const float* Wk = (const float*)d_in[4];
    const float* Wv = (const float*)d_in[5];
    const float* Wo = (const float*)d_in[6];
    float* out = (float*)d_out;

    float *gq;
    uint32_t *qh, *ql, *wqh, *wql, *woh, *wol, *aoh, *aol, *kc, *vc;
    cudaGetSymbolAddress((void**)&gq,  g_q);
    cudaGetSymbolAddress((void**)&qh,  g_qh);
    cudaGetSymbolAddress((void**)&ql,  g_ql);
    cudaGetSymbolAddress((void**)&wqh, g_wqh);
    cudaGetSymbolAddress((void**)&wql, g_wql);
    cudaGetSymbolAddress((void**)&woh, g_woh);
    cudaGetSymbolAddress((void**)&wol, g_wol);
    cudaGetSymbolAddress((void**)&aoh, g_aoh);
    cudaGetSymbolAddress((void**)&aol, g_aol);
    cudaGetSymbolAddress((void**)&kc,  g_kc);
    cudaGetSymbolAddress((void**)&vc,  g_vc);

    cudaFuncSetAttribute(mqa_attn_mma,
                         cudaFuncAttributeMaxDynamicSharedMemorySize, ASM_TOT);
    cudaFuncSetAttribute(gemm_ldsm,
                         cudaFuncAttributeMaxDynamicSharedMemorySize, GSM_TOT);

    // conversions to bf16 planes
    conv_planes   <<<(BS * DM / 2 + 255) / 256, 256>>>(Q, qh, ql, BS * DM / 2);
    conv_wt_planes<<<(DM * DM / 2 + 255) / 256, 256>>>(Wq, wqh, wql, DM, DM);
    conv_wt_planes<<<(DM * DM / 2 + 255) / 256, 256>>>(Wo, woh, wol, DM, DM);

    // Q projection (ldmatrix + mma.sync bf16x3)
    gemm_ldsm<<<dim3(DM / 64, BS / 128), 128, GSM_TOT>>>(
        (const uint4*)qh, (const uint4*)ql, (const uint4*)wqh, (const uint4*)wql,
        gq, BS, DM, DM);

    // K/V projections -> attention-format fp16 pairs directly
    sgemm_kv<<<dim3(1, BS / 64, 2), 256>>>(K, Wk, V, Wv, kc, vc);

    // attention (all-fp16 single planes, writes bf16 planes)
    mqa_attn_mma<<<dim3(S_ / QB, H_, B_), 128, ASM_TOT>>>(gq, aoh, aol);

    // output projection (ldmatrix + mma.sync bf16x3)
    gemm_ldsm<<<dim3(DM / 64, BS / 128), 128, GSM_TOT>>>(
        (const uint4*)aoh, (const uint4*)aol, (const uint4*)woh, (const uint4*)wol,
        out, BS, DM, DM);
}

// round 14
// speedup vs baseline: 8.0490x; 1.4029x over previous
#include <cuda_runtime.h>
#include <cuda_fp16.h>
#include <cstdint>

#define B_  2
#define S_  2048
#define DM  1024
#define H_  16
#define DK  64
#define DV  64
#define BS  (B_*S_)   // 4096

// ---------------- scratch ----------------------------------------------------
__device__ float    g_q  [BS * DM];          // Q-proj output (fp32, read by attn)
__device__ uint32_t g_qc [BS * DM / 2];      // input Q fp16 pairs
__device__ uint32_t g_wq [DM * DM / 2];      // W_q^T [N][K] fp16 pairs
__device__ uint32_t g_wo [DM * DM / 2];      // W_o^T [N][K] fp16 pairs
__device__ uint32_t g_ao [BS * DM / 2];      // attention out fp16 pairs
__device__ uint32_t g_kc [BS * DK / 2];      // K fp16 pairs, row=(b,s)
__device__ uint32_t g_vc [B_ * DV * (S_ / 2)]; // V^T fp16 pairs, row=(b,d)

// ---------------- helpers ------------------------------------------------------
__device__ __forceinline__ uint32_t packh2(float x, float y) {
    __half2 h = __floats2half2_rn(x, y);
    return *reinterpret_cast<uint32_t*>(&h);
}

// fp16 hi/lo split (for Q in attention)
__device__ __forceinline__ uint32_t packsplit_h(float x, float y, uint32_t &lo) {
    __half2 h = __floats2half2_rn(x, y);
    float hx = __half2float(__low2half(h));
    float hy = __half2float(__high2half(h));
    __half2 l2 = __floats2half2_rn(x - hx, y - hy);
    lo = *reinterpret_cast<uint32_t*>(&l2);
    return *reinterpret_cast<uint32_t*>(&h);
}

__device__ __forceinline__ void cp_async16(void* smem, const void* gmem) {
    uint32_t s = (uint32_t)__cvta_generic_to_shared(smem);
    asm volatile("cp.async.cg.shared.global [%0], [%1], 16;" :: "r"(s), "l"(gmem));
}

__device__ __forceinline__ uint32_t smem_u32(const void* p) {
    return (uint32_t)__cvta_generic_to_shared(p);
}

__device__ __forceinline__ float ex2f(float x) {
    float y;
    asm("ex2.approx.f32 %0, %1;" : "=f"(y) : "f"(x));
    return y;
}

__device__ __forceinline__ void mma_f16(float* d, const uint32_t* a, const uint32_t* b) {
    asm volatile(
        "mma.sync.aligned.m16n8k16.row.col.f32.f16.f16.f32 "
        "{%0,%1,%2,%3},{%4,%5,%6,%7},{%8,%9},{%0,%1,%2,%3};"
        : "+f"(d[0]), "+f"(d[1]), "+f"(d[2]), "+f"(d[3])
        : "r"(a[0]), "r"(a[1]), "r"(a[2]), "r"(a[3]), "r"(b[0]), "r"(b[1]));
}

__device__ __forceinline__ void ldsm_x4(uint32_t* r, uint32_t addr) {
    asm volatile("ldmatrix.sync.aligned.m8n8.x4.shared.b16 {%0,%1,%2,%3}, [%4];"
                 : "=r"(r[0]), "=r"(r[1]), "=r"(r[2]), "=r"(r[3]) : "r"(addr));
}

// ---------------- conversion kernels --------------------------------------------
// fp32 row-major -> fp16 pairs
__global__ __launch_bounds__(256)
void conv_h(const float* __restrict__ A, uint32_t* __restrict__ Ac, int npairs)
{
    int idx = blockIdx.x * blockDim.x + threadIdx.x;
    if (idx >= npairs) return;
    float2 p = ((const float2*)A)[idx];
    Ac[idx] = packh2(p.x, p.y);
}

// W [K][N] fp32 -> W^T fp16 pairs [N][K/2]
__global__ __launch_bounds__(256)
void conv_wt_h(const float* __restrict__ W, uint32_t* __restrict__ Wt, int K, int N)
{
    int idx = blockIdx.x * blockDim.x + threadIdx.x;   // p * N + n
    if (idx >= N * (K / 2)) return;
    int p = idx / N;
    int n = idx - p * N;
    float x = W[(size_t)(2 * p)     * N + n];
    float y = W[(size_t)(2 * p + 1) * N + n];
    Wt[(size_t)n * (K / 2) + p] = packh2(x, y);
}

// ---------------- fp16 GEMM with ldmatrix ----------------------------------------
// C[M,Ntot] = A @ W; A fp16 pairs [M][K/2], Bt fp16 pairs [Ntot][K/2] (= W^T).
// BM=128, BN=64, BK=64; 128 threads / 4 warps, warp tile 32x64; 2-stage cp.async.
// smem: sA [buf][128][128B] (32KB), sB at 32768 [buf][64][128B] (16KB). 48KB.
#define GSM_TOT 49152

__global__ __launch_bounds__(128, 3)
void gemm_f16(const uint4* __restrict__ A16, const uint4* __restrict__ B16,
              float* __restrict__ C, int M, int Ntot, int K)
{
    extern __shared__ __align__(128) char dsm[];
    const uint32_t sb = smem_u32(dsm);

    const int tid = threadIdx.x;
    const int l   = tid & 31;
    const int w   = tid >> 5;
    const int bn  = blockIdx.x * 64;
    const int bm  = blockIdx.y * 128;
    const int K8  = K >> 3;            // uint4 per row

    const int e = l & 3;
    const int q = l >> 2;

    const int rA0 = w * 32 + (l & 7) + ((l >> 3) & 1) * 8;
    const int jAh = (l >> 4) & 1;
    const int rB0 = (l & 7) + ((l >> 4) & 1) * 8;
    const int jBh = (l >> 3) & 1;
    const int cA  = rA0 & 7;
    const int cB  = rB0 & 7;

    float acc[2][8][4];
    #pragma unroll
    for (int i = 0; i < 2; i++)
        #pragma unroll
        for (int j = 0; j < 8; j++)
            #pragma unroll
            for (int t = 0; t < 4; t++) acc[i][j][t] = 0.f;

    #define STAGE(buf, k0)                                                          \
    {                                                                               \
        const int kq = (k0) >> 3;                                                   \
        _Pragma("unroll")                                                           \
        for (int i = 0; i < 8; i++) {                                               \
            int id = tid + 128 * i;              /* 0..1023 */                      \
            int r = id >> 3, j = id & 7;                                            \
            cp_async16(dsm + (buf) * 16384 + r * 128 + ((j ^ (r & 7)) << 4),        \
                       A16 + (size_t)(bm + r) * K8 + kq + j);                       \
        }                                                                           \
        _Pragma("unroll")                                                           \
        for (int i = 0; i < 4; i++) {                                               \
            int id = tid + 128 * i;              /* 0..511 */                       \
            int r = id >> 3, j = id & 7;                                            \
            cp_async16(dsm + 32768 + (buf) * 8192 + r * 128                         \
                           + ((j ^ (r & 7)) << 4),                                  \
                       B16 + (size_t)(bn + r) * K8 + kq + j);                       \
        }                                                                           \
        asm volatile("cp.async.commit_group;");                                     \
    }

    const int niter = K / 64;
    STAGE(0, 0);

    for (int it = 0; it < niter; it++) {
        if (it + 1 < niter) {
            STAGE((it + 1) & 1, (it + 1) * 64);
            asm volatile("cp.async.wait_group 1;");
        } else {
            asm volatile("cp.async.wait_group 0;");
        }
        __syncthreads();

        const int buf = it & 1;
        const uint32_t aBase = sb + buf * 16384;
        const uint32_t bBase = sb + 32768 + buf * 8192;

        #pragma unroll
        for (int kk = 0; kk < 4; kk++) {
            const uint32_t offA = (uint32_t)(((2 * kk + jAh) ^ cA) << 4);
            const uint32_t offB = (uint32_t)(((2 * kk + jBh) ^ cB) << 4);

            uint32_t ah[2][4];
            #pragma unroll
            for (int mi = 0; mi < 2; mi++)
                ldsm_x4(ah[mi], aBase + (uint32_t)((rA0 + mi * 16) * 128) + offA);

            #pragma unroll
            for (int ni2 = 0; ni2 < 4; ni2++) {
                uint32_t bh4[4];
                ldsm_x4(bh4, bBase + (uint32_t)((rB0 + ni2 * 16) * 128) + offB);
                uint32_t bhE[2] = {bh4[0], bh4[1]};
                uint32_t bhO[2] = {bh4[2], bh4[3]};
                #pragma unroll
                for (int mi = 0; mi < 2; mi++) {
                    mma_f16(acc[mi][2 * ni2],     ah[mi], bhE);
                    mma_f16(acc[mi][2 * ni2 + 1], ah[mi], bhO);
                }
            }
        }
        __syncthreads();
    }
    #undef STAGE

    #pragma unroll
    for (int mi = 0; mi < 2; mi++) {
        int r = bm + w * 32 + mi * 16 + q;
        #pragma unroll
        for (int ni = 0; ni < 8; ni++) {
            int c = bn + ni * 8 + e * 2;
            *(float2*)(C + (size_t)r * Ntot + c)       = make_float2(acc[mi][ni][0], acc[mi][ni][1]);
            *(float2*)(C + (size_t)(r + 8) * Ntot + c) = make_float2(acc[mi][ni][2], acc[mi][ni][3]);
        }
    }
}

// ---------------- fused K/V projection -> attention-format fp16 pairs -----------
__global__ __launch_bounds__(256)
void sgemm_kv(const float* __restrict__ Kin, const float* __restrict__ Wk,
              const float* __restrict__ Vin, const float* __restrict__ Wv,
              uint32_t* __restrict__ kc, uint32_t* __restrict__ vc)
{
    __shared__ float As[16][68];
    __shared__ float Bs[16][64];

    const int isV = blockIdx.z;
    const float* A = isV ? Vin : Kin;
    const float* W = isV ? Wv  : Wk;
    const int N = 64, K = DM;

    const int tid = threadIdx.x;
    const int tx  = tid & 15;
    const int ty  = tid >> 4;
    const int bm  = blockIdx.y * 64;

    const int arow = tid >> 2;
    const int acol = (tid & 3) * 4;
    const int brow = tid >> 4;
    const int bcol = (tid & 15) * 4;

    float acc[4][4] = {};

    for (int k0 = 0; k0 < K; k0 += 16) {
        float4 a4 = *(const float4*)(A + (size_t)(bm + arow) * K + k0 + acol);
        As[acol + 0][arow] = a4.x;
        As[acol + 1][arow] = a4.y;
        As[acol + 2][arow] = a4.z;
        As[acol + 3][arow] = a4.w;
        *(float4*)&Bs[brow][bcol] =
            *(const float4*)(W + (size_t)(k0 + brow) * N + bcol);
        __syncthreads();

        #pragma unroll
        for (int k = 0; k < 16; k++) {
            float4 av = *(const float4*)&As[k][ty * 4];
            float4 bv = *(const float4*)&Bs[k][tx * 4];
            float a_[4] = {av.x, av.y, av.z, av.w};
            float b_[4] = {bv.x, bv.y, bv.z, bv.w};
            #pragma unroll
            for (int i = 0; i < 4; i++)
                #pragma unroll
                for (int j = 0; j < 4; j++)
                    acc[i][j] += a_[i] * b_[j];
        }
        __syncthreads();
    }

    const int r = bm + ty * 4;
    if (!isV) {
        #pragma unroll
        for (int i = 0; i < 4; i++) {
            kc[(size_t)(r + i) * 32 + tx * 2 + 0] = packh2(acc[i][0], acc[i][1]);
            kc[(size_t)(r + i) * 32 + tx * 2 + 1] = packh2(acc[i][2], acc[i][3]);
        }
    } else {
        const int b = r >> 11;
        const int s = r & 2047;
        #pragma unroll
        for (int j = 0; j < 4; j++) {
            int d = tx * 4 + j;
            size_t base = (size_t)(b * DV + d) * (S_ / 2) + (s >> 1);
            vc[base + 0] = packh2(acc[0][j], acc[1][j]);
            vc[base + 1] = packh2(acc[2][j], acc[3][j]);
        }
    }
}

// ---------------- mma flash attention (unchanged from R13 core) -------------------
#define QB 64
#define KB 64
#define QSCALE 0.1803368801111f   // (1/8) * log2(e)
#define ASM_TOT 32768

__global__ __launch_bounds__(128, 3)
void mqa_attn_mma(const float* __restrict__ gq, uint32_t* __restrict__ ao)
{
    extern __shared__ __align__(16) uint32_t dsma[];
    uint32_t* sK = dsma;          // [2][64*32]
    uint32_t* sV = dsma + 4096;   // [2][64*32]

    const int tid = threadIdx.x;
    const int l   = tid & 31;
    const int w   = tid >> 5;
    const int qb  = (S_ / QB - 1) - blockIdx.x;
    const int h   = blockIdx.y;
    const int b   = blockIdx.z;

    const int rowbase = qb * QB + w * 16;
    const int r0 = rowbase + (l >> 2);
    const int r1 = r0 + 8;
    const int e  = l & 3;
    const int Xl = (l >> 2) << 2;

    int fidx[4][2];
    #pragma unroll
    for (int ck = 0; ck < 4; ck++) {
        fidx[ck][0] = (8 * ck + e)     ^ Xl;
        fidx[ck][1] = (8 * ck + 4 + e) ^ Xl;
    }

    uint32_t qh[4][4], ql[4][4];
    {
        const float* qbase = gq + ((size_t)(b * S_)) * DM + h * DK;
        #pragma unroll
        for (int ck = 0; ck < 4; ck++) {
            int d0 = 16 * ck + e * 2;
            float2 v00 = *(const float2*)(qbase + (size_t)r0 * DM + d0);
            float2 v10 = *(const float2*)(qbase + (size_t)r1 * DM + d0);
            float2 v01 = *(const float2*)(qbase + (size_t)r0 * DM + d0 + 8);
            float2 v11 = *(const float2*)(qbase + (size_t)r1 * DM + d0 + 8);
            qh[ck][0] = packsplit_h(v00.x * QSCALE, v00.y * QSCALE, ql[ck][0]);
            qh[ck][1] = packsplit_h(v10.x * QSCALE, v10.y * QSCALE, ql[ck][1]);
            qh[ck][2] = packsplit_h(v01.x * QSCALE, v01.y * QSCALE, ql[ck][2]);
            qh[ck][3] = packsplit_h(v11.x * QSCALE, v11.y * QSCALE, ql[ck][3]);
        }
    }

    float O[8][4];
    #pragma unroll
    for (int t = 0; t < 8; t++)
        #pragma unroll
        for (int i = 0; i < 4; i++) O[t][i] = 0.f;
    float l0 = 0.f, l1 = 0.f;

    const uint4* ksrc = (const uint4*)g_kc;
    const uint4* vsrc = (const uint4*)g_vc;

    #define ASTAGE(buf, kb_)                                                          \
    {                                                                                 \
        _Pragma("unroll")                                                             \
        for (int i = 0; i < 4; i++) {                                                 \
            int id = tid + 128 * i;                                                   \
            int r  = id >> 3;                                                         \
            int j  = id & 7;                                                          \
            int dg = ((j ^ (r & 7)) << 2);                                            \
            cp_async16(&sK[(buf) * 2048 + r * 32 + dg],                               \
                       &ksrc[((size_t)(b * S_ + (kb_) * KB + r)) * 8 + j]);           \
            cp_async16(&sV[(buf) * 2048 + r * 32 + dg],                               \
                       &vsrc[((size_t)(b * DV + r)) * (S_ / 8) + (kb_) * 8 + j]);     \
        }                                                                             \
        asm volatile("cp.async.commit_group;");                                       \
    }

    const int nkb = qb + 1;
    ASTAGE(0, 0);

    for (int kb = 0; kb < nkb; kb++) {
        if (kb + 1 < nkb) {
            ASTAGE((kb + 1) & 1, kb + 1);
            asm volatile("cp.async.wait_group 1;");
        } else {
            asm volatile("cp.async.wait_group 0;");
        }
        __syncthreads();

        const uint32_t* sKb = sK + (kb & 1) * 2048;
        const uint32_t* sVb = sV + (kb & 1) * 2048;

        float Sf[8][4];
        #pragma unroll
        for (int t = 0; t < 8; t++)
            #pragma unroll
            for (int i = 0; i < 4; i++) Sf[t][i] = 0.f;

        #pragma unroll
        for (int ck = 0; ck < 4; ck++) {
            #pragma unroll
            for (int t = 0; t < 8; t++) {
                int kv = 8 * t + (l >> 2);
                uint32_t bh[2];
                bh[0] = sKb[kv * 32 + fidx[ck][0]];
                bh[1] = sKb[kv * 32 + fidx[ck][1]];
                mma_f16(Sf[t], qh[ck], bh);
                mma_f16(Sf[t], ql[ck], bh);
            }
        }

        if (kb >= qb) {
            #pragma unroll
            for (int t = 0; t < 8; t++) {
                int c0 = kb * KB + 8 * t + e * 2;
                if (c0     > r0) Sf[t][0] = -1e9f;
                if (c0 + 1 > r0) Sf[t][1] = -1e9f;
                if (c0     > r1) Sf[t][2] = -1e9f;
                if (c0 + 1 > r1) Sf[t][3] = -1e9f;
            }
        }

        uint32_t ph[4][4];
        #pragma unroll
        for (int t = 0; t < 8; t++) {
            float p0 = ex2f(Sf[t][0]);
            float p1 = ex2f(Sf[t][1]);
            float p2 = ex2f(Sf[t][2]);
            float p3 = ex2f(Sf[t][3]);
            l0 += p0 + p1;
            l1 += p2 + p3;
            ph[t >> 1][(t & 1) * 2 + 0] = packh2(p0, p1);
            ph[t >> 1][(t & 1) * 2 + 1] = packh2(p2, p3);
        }

        #pragma unroll
        for (int ck = 0; ck < 4; ck++) {
            #pragma unroll
            for (int td = 0; td < 8; td++) {
                int d = 8 * td + (l >> 2);
                uint32_t vh[2];
                vh[0] = sVb[d * 32 + fidx[ck][0]];
                vh[1] = sVb[d * 32 + fidx[ck][1]];
                mma_f16(O[td], ph[ck], vh);
            }
        }
        __syncthreads();
    }
    #undef ASTAGE

    l0 += __shfl_xor_sync(0xffffffffu, l0, 1);
    l0 += __shfl_xor_sync(0xffffffffu, l0, 2);
    l1 += __shfl_xor_sync(0xffffffffu, l1, 1);
    l1 += __shfl_xor_sync(0xffffffffu, l1, 2);

    const float inv0 = 1.f / l0, inv1 = 1.f / l1;
    #pragma unroll
    for (int td = 0; td < 8; td++) {
        int d0 = 8 * td + e * 2;
        int cp = (h * DV + d0) >> 1;
        ao[(size_t)(b * S_ + r0) * (DM / 2) + cp] = packh2(O[td][0] * inv0, O[td][1] * inv0);
        ao[(size_t)(b * S_ + r1) * (DM / 2) + cp] = packh2(O[td][2] * inv1, O[td][3] * inv1);
    }
}

// ---------------- launch -----------------------------------------------------------
extern "C" void kernel_launch(void* const* d_in, const int* in_sizes, int n_in,
                              void* d_out, int out_size)
{
    const float* Q  = (const float*)d_in[0];
    const float* K  = (const float*)d_in[1];
    const float* V  = (const float*)d_in[2];
    const float* Wq = (const float*)d_in[3];
    const float* Wk = (const float*)d_in[4];
    const float* Wv = (const float*)d_in[5];
    const float* Wo = (const float*)d_in[6];
    float* out = (float*)d_out;

    float *gq;
    uint32_t *qc, *wq, *wo, *ao, *kc, *vc;
    cudaGetSymbolAddress((void**)&gq, g_q);
    cudaGetSymbolAddress((void**)&qc, g_qc);
    cudaGetSymbolAddress((void**)&wq, g_wq);
    cudaGetSymbolAddress((void**)&wo, g_wo);
    cudaGetSymbolAddress((void**)&ao, g_ao);
    cudaGetSymbolAddress((void**)&kc, g_kc);
    cudaGetSymbolAddress((void**)&vc, g_vc);

    cudaFuncSetAttribute(mqa_attn_mma,
                         cudaFuncAttributeMaxDynamicSharedMemorySize, ASM_TOT);
    cudaFuncSetAttribute(gemm_f16,
                         cudaFuncAttributeMaxDynamicSharedMemorySize, GSM_TOT);

    // conversions to fp16 pairs
    conv_h   <<<(BS * DM / 2 + 255) / 256, 256>>>(Q, qc, BS * DM / 2);
    conv_wt_h<<<(DM * DM / 2 + 255) / 256, 256>>>(Wq, wq, DM, DM);
    conv_wt_h<<<(DM * DM / 2 + 255) / 256, 256>>>(Wo, wo, DM, DM);

    // Q projection (fp16 single-plane GEMM)
    gemm_f16<<<dim3(DM / 64, BS / 128), 128, GSM_TOT>>>(
        (const uint4*)qc, (const uint4*)wq, gq, BS, DM, DM);

    // K/V projections -> attention-format fp16 pairs
    sgemm_kv<<<dim3(1, BS / 64, 2), 256>>>(K, Wk, V, Wv, kc, vc);

    // attention (all-fp16, writes single fp16 plane)
    mqa_attn_mma<<<dim3(S_ / QB, H_, B_), 128, ASM_TOT>>>(gq, ao);

    // output projection (fp16 single-plane GEMM)
    gemm_f16<<<dim3(DM / 64, BS / 128), 128, GSM_TOT>>>(
        (const uint4*)ao, (const uint4*)wo, out, BS, DM, DM);
}

// round 15
// speedup vs baseline: 8.7015x; 1.0811x over previous
#include <cuda_runtime.h>
#include <cuda_fp16.h>
#include <cstdint>

#define B_  2
#define S_  2048
#define DM  1024
#define H_  16
#define DK  64
#define DV  64
#define BS  (B_*S_)   // 4096

// ---------------- scratch ----------------------------------------------------
__device__ uint32_t g_qc [BS * DM / 2];      // input Q fp16 pairs (GEMM A)
__device__ uint32_t g_q16[BS * DM / 2];      // Q-proj output fp16 pairs (attn Q)
__device__ uint32_t g_wq [DM * DM / 2];      // W_q^T [N][K] fp16 pairs (pre-scaled)
__device__ uint32_t g_wo [DM * DM / 2];      // W_o^T [N][K] fp16 pairs
__device__ uint32_t g_ao [BS * DM / 2];      // attention out fp16 pairs
__device__ uint32_t g_kc [BS * DK / 2];      // K fp16 pairs, row=(b,s)
__device__ uint32_t g_vc [B_ * DV * (S_ / 2)]; // V^T fp16 pairs, row=(b,d)

// ---------------- helpers ------------------------------------------------------
__device__ __forceinline__ uint32_t packh2(float x, float y) {
    __half2 h = __floats2half2_rn(x, y);
    return *reinterpret_cast<uint32_t*>(&h);
}

__device__ __forceinline__ void cp_async16(void* smem, const void* gmem) {
    uint32_t s = (uint32_t)__cvta_generic_to_shared(smem);
    asm volatile("cp.async.cg.shared.global [%0], [%1], 16;" :: "r"(s), "l"(gmem));
}

__device__ __forceinline__ uint32_t smem_u32(const void* p) {
    return (uint32_t)__cvta_generic_to_shared(p);
}

__device__ __forceinline__ float ex2f(float x) {
    float y;
    asm("ex2.approx.f32 %0, %1;" : "=f"(y) : "f"(x));
    return y;
}

__device__ __forceinline__ void mma_f16(float* d, const uint32_t* a, const uint32_t* b) {
    asm volatile(
        "mma.sync.aligned.m16n8k16.row.col.f32.f16.f16.f32 "
        "{%0,%1,%2,%3},{%4,%5,%6,%7},{%8,%9},{%0,%1,%2,%3};"
        : "+f"(d[0]), "+f"(d[1]), "+f"(d[2]), "+f"(d[3])
        : "r"(a[0]), "r"(a[1]), "r"(a[2]), "r"(a[3]), "r"(b[0]), "r"(b[1]));
}

__device__ __forceinline__ void ldsm_x4(uint32_t* r, uint32_t addr) {
    asm volatile("ldmatrix.sync.aligned.m8n8.x4.shared.b16 {%0,%1,%2,%3}, [%4];"
                 : "=r"(r[0]), "=r"(r[1]), "=r"(r[2]), "=r"(r[3]) : "r"(addr));
}

// ---------------- conversion kernels --------------------------------------------
__global__ __launch_bounds__(256)
void conv_h(const float* __restrict__ A, uint32_t* __restrict__ Ac, int npairs)
{
    int idx = blockIdx.x * blockDim.x + threadIdx.x;
    if (idx >= npairs) return;
    float2 p = ((const float2*)A)[idx];
    Ac[idx] = packh2(p.x, p.y);
}

// W [K][N] fp32 -> W^T fp16 pairs [N][K/2], optionally scaled
__global__ __launch_bounds__(256)
void conv_wt_h(const float* __restrict__ W, uint32_t* __restrict__ Wt,
               int K, int N, float scale)
{
    int idx = blockIdx.x * blockDim.x + threadIdx.x;
    if (idx >= N * (K / 2)) return;
    int p = idx / N;
    int n = idx - p * N;
    float x = W[(size_t)(2 * p)     * N + n] * scale;
    float y = W[(size_t)(2 * p + 1) * N + n] * scale;
    Wt[(size_t)n * (K / 2) + p] = packh2(x, y);
}

// ---------------- fp16 GEMM with ldmatrix ----------------------------------------
// C fp32 (half_out=0) or Ch fp16 pairs (half_out=1).
#define GSM_TOT 49152

__global__ __launch_bounds__(128, 3)
void gemm_f16(const uint4* __restrict__ A16, const uint4* __restrict__ B16,
              float* __restrict__ C, uint32_t* __restrict__ Ch, int half_out,
              int M, int Ntot, int K)
{
    extern __shared__ __align__(128) char dsm[];
    const uint32_t sb = smem_u32(dsm);

    const int tid = threadIdx.x;
    const int l   = tid & 31;
    const int w   = tid >> 5;
    const int bn  = blockIdx.x * 64;
    const int bm  = blockIdx.y * 128;
    const int K8  = K >> 3;

    const int e = l & 3;
    const int q = l >> 2;

    const int rA0 = w * 32 + (l & 7) + ((l >> 3) & 1) * 8;
    const int jAh = (l >> 4) & 1;
    const int rB0 = (l & 7) + ((l >> 4) & 1) * 8;
    const int jBh = (l >> 3) & 1;
    const int cA  = rA0 & 7;
    const int cB  = rB0 & 7;

    float acc[2][8][4];
    #pragma unroll
    for (int i = 0; i < 2; i++)
        #pragma unroll
        for (int j = 0; j < 8; j++)
            #pragma unroll
            for (int t = 0; t < 4; t++) acc[i][j][t] = 0.f;

    #define STAGE(buf, k0)                                                          \
    {                                                                               \
        const int kq = (k0) >> 3;                                                   \
        _Pragma("unroll")                                                           \
        for (int i = 0; i < 8; i++) {                                               \
            int id = tid + 128 * i;                                                 \
            int r = id >> 3, j = id & 7;                                            \
            cp_async16(dsm + (buf) * 16384 + r * 128 + ((j ^ (r & 7)) << 4),        \
                       A16 + (size_t)(bm + r) * K8 + kq + j);                       \
        }                                                                           \
        _Pragma("unroll")                                                           \
        for (int i = 0; i < 4; i++) {                                               \
            int id = tid + 128 * i;                                                 \
            int r = id >> 3, j = id & 7;                                            \
            cp_async16(dsm + 32768 + (buf) * 8192 + r * 128                         \
                           + ((j ^ (r & 7)) << 4),                                  \
                       B16 + (size_t)(bn + r) * K8 + kq + j);                       \
        }                                                                           \
        asm volatile("cp.async.commit_group;");                                     \
    }

    const int niter = K / 64;
    STAGE(0, 0);

    for (int it = 0; it < niter; it++) {
        if (it + 1 < niter) {
            STAGE((it + 1) & 1, (it + 1) * 64);
            asm volatile("cp.async.wait_group 1;");
        } else {
            asm volatile("cp.async.wait_group 0;");
        }
        __syncthreads();

        const int buf = it & 1;
        const uint32_t aBase = sb + buf * 16384;
        const uint32_t bBase = sb + 32768 + buf * 8192;

        #pragma unroll
        for (int kk = 0; kk < 4; kk++) {
            const uint32_t offA = (uint32_t)(((2 * kk + jAh) ^ cA) << 4);
            const uint32_t offB = (uint32_t)(((2 * kk + jBh) ^ cB) << 4);

            uint32_t ah[2][4];
            #pragma unroll
            for (int mi = 0; mi < 2; mi++)
                ldsm_x4(ah[mi], aBase + (uint32_t)((rA0 + mi * 16) * 128) + offA);

            #pragma unroll
            for (int ni2 = 0; ni2 < 4; ni2++) {
                uint32_t bh4[4];
                ldsm_x4(bh4, bBase + (uint32_t)((rB0 + ni2 * 16) * 128) + offB);
                uint32_t bhE[2] = {bh4[0], bh4[1]};
                uint32_t bhO[2] = {bh4[2], bh4[3]};
                #pragma unroll
                for (int mi = 0; mi < 2; mi++) {
                    mma_f16(acc[mi][2 * ni2],     ah[mi], bhE);
                    mma_f16(acc[mi][2 * ni2 + 1], ah[mi], bhO);
                }
            }
        }
        __syncthreads();
    }
    #undef STAGE

    if (!half_out) {
        #pragma unroll
        for (int mi = 0; mi < 2; mi++) {
            int r = bm + w * 32 + mi * 16 + q;
            #pragma unroll
            for (int ni = 0; ni < 8; ni++) {
                int c = bn + ni * 8 + e * 2;
                *(float2*)(C + (size_t)r * Ntot + c)       = make_float2(acc[mi][ni][0], acc[mi][ni][1]);
                *(float2*)(C + (size_t)(r + 8) * Ntot + c) = make_float2(acc[mi][ni][2], acc[mi][ni][3]);
            }
        }
    } else {
        const int Np = Ntot >> 1;
        #pragma unroll
        for (int mi = 0; mi < 2; mi++) {
            int r = bm + w * 32 + mi * 16 + q;
            #pragma unroll
            for (int ni = 0; ni < 8; ni++) {
                int cp = (bn + ni * 8 + e * 2) >> 1;
                Ch[(size_t)r * Np + cp]       = packh2(acc[mi][ni][0], acc[mi][ni][1]);
                Ch[(size_t)(r + 8) * Np + cp] = packh2(acc[mi][ni][2], acc[mi][ni][3]);
            }
        }
    }
}

// ---------------- fused K/V projection -> attention-format fp16 pairs -----------
__global__ __launch_bounds__(256)
void sgemm_kv(const float* __restrict__ Kin, const float* __restrict__ Wk,
              const float* __restrict__ Vin, const float* __restrict__ Wv,
              uint32_t* __restrict__ kc, uint32_t* __restrict__ vc)
{
    __shared__ float As[16][68];
    __shared__ float Bs[16][64];

    const int isV = blockIdx.z;
    const float* A = isV ? Vin : Kin;
    const float* W = isV ? Wv  : Wk;
    const int N = 64, K = DM;

    const int tid = threadIdx.x;
    const int tx  = tid & 15;
    const int ty  = tid >> 4;
    const int bm  = blockIdx.y * 64;

    const int arow = tid >> 2;
    const int acol = (tid & 3) * 4;
    const int brow = tid >> 4;
    const int bcol = (tid & 15) * 4;

    float acc[4][4] = {};

    for (int k0 = 0; k0 < K; k0 += 16) {
        float4 a4 = *(const float4*)(A + (size_t)(bm + arow) * K + k0 + acol);
        As[acol + 0][arow] = a4.x;
        As[acol + 1][arow] = a4.y;
        As[acol + 2][arow] = a4.z;
        As[acol + 3][arow] = a4.w;
        *(float4*)&Bs[brow][bcol] =
            *(const float4*)(W + (size_t)(k0 + brow) * N + bcol);
        __syncthreads();

        #pragma unroll
        for (int k = 0; k < 16; k++) {
            float4 av = *(const float4*)&As[k][ty * 4];
            float4 bv = *(const float4*)&Bs[k][tx * 4];
            float a_[4] = {av.x, av.y, av.z, av.w};
            float b_[4] = {bv.x, bv.y, bv.z, bv.w};
            #pragma unroll
            for (int i = 0; i < 4; i++)
                #pragma unroll
                for (int j = 0; j < 4; j++)
                    acc[i][j] += a_[i] * b_[j];
        }
        __syncthreads();
    }

    const int r = bm + ty * 4;
    if (!isV) {
        #pragma unroll
        for (int i = 0; i < 4; i++) {
            kc[(size_t)(r + i) * 32 + tx * 2 + 0] = packh2(acc[i][0], acc[i][1]);
            kc[(size_t)(r + i) * 32 + tx * 2 + 1] = packh2(acc[i][2], acc[i][3]);
        }
    } else {
        const int b = r >> 11;
        const int s = r & 2047;
        #pragma unroll
        for (int j = 0; j < 4; j++) {
            int d = tx * 4 + j;
            size_t base = (size_t)(b * DV + d) * (S_ / 2) + (s >> 1);
            vc[base + 0] = packh2(acc[0][j], acc[1][j]);
            vc[base + 1] = packh2(acc[2][j], acc[3][j]);
        }
    }
}

// ---------------- mma flash attention: single-plane everything -------------------
// Q pre-scaled by (1/8)*log2(e) via W_q; all operands single fp16 planes.
// 64 MMA per warp-tile (32 QK + 32 PV).
#define QB 64
#define KB 64
#define ASM_TOT 32768

__global__ __launch_bounds__(128, 3)
void mqa_attn_mma(const uint32_t* __restrict__ q16, uint32_t* __restrict__ ao)
{
    extern __shared__ __align__(16) uint32_t dsma[];
    uint32_t* sK = dsma;          // [2][64*32]
    uint32_t* sV = dsma + 4096;   // [2][64*32]

    const int tid = threadIdx.x;
    const int l   = tid & 31;
    const int w   = tid >> 5;
    const int qb  = (S_ / QB - 1) - blockIdx.x;
    const int h   = blockIdx.y;
    const int b   = blockIdx.z;

    const int rowbase = qb * QB + w * 16;
    const int r0 = rowbase + (l >> 2);
    const int r1 = r0 + 8;
    const int e  = l & 3;
    const int Xl = (l >> 2) << 2;

    int fidx[4][2];
    #pragma unroll
    for (int ck = 0; ck < 4; ck++) {
        fidx[ck][0] = (8 * ck + e)     ^ Xl;
        fidx[ck][1] = (8 * ck + 4 + e) ^ Xl;
    }

    // Q fragments: direct fp16-pair loads (pre-scaled)
    uint32_t qh[4][4];
    {
        const uint32_t* qb0 = q16 + (size_t)(b * S_ + r0) * (DM / 2) + h * 32;
        const uint32_t* qb1 = q16 + (size_t)(b * S_ + r1) * (DM / 2) + h * 32;
        #pragma unroll
        for (int ck = 0; ck < 4; ck++) {
            qh[ck][0] = qb0[8 * ck + e];
            qh[ck][1] = qb1[8 * ck + e];
            qh[ck][2] = qb0[8 * ck + 4 + e];
            qh[ck][3] = qb1[8 * ck + 4 + e];
        }
    }

    float O[8][4];
    #pragma unroll
    for (int t = 0; t < 8; t++)
        #pragma unroll
        for (int i = 0; i < 4; i++) O[t][i] = 0.f;
    float l0 = 0.f, l1 = 0.f;

    const uint4* ksrc = (const uint4*)g_kc;
    const uint4* vsrc = (const uint4*)g_vc;

    #define ASTAGE(buf, kb_)                                                          \
    {                                                                                 \
        _Pragma("unroll")                                                             \
        for (int i = 0; i < 4; i++) {                                                 \
            int id = tid + 128 * i;                                                   \
            int r  = id >> 3;                                                         \
            int j  = id & 7;                                                          \
            int dg = ((j ^ (r & 7)) << 2);                                            \
            cp_async16(&sK[(buf) * 2048 + r * 32 + dg],                               \
                       &ksrc[((size_t)(b * S_ + (kb_) * KB + r)) * 8 + j]);           \
            cp_async16(&sV[(buf) * 2048 + r * 32 + dg],                               \
                       &vsrc[((size_t)(b * DV + r)) * (S_ / 8) + (kb_) * 8 + j]);     \
        }                                                                             \
        asm volatile("cp.async.commit_group;");                                       \
    }

    const int nkb = qb + 1;
    ASTAGE(0, 0);

    for (int kb = 0; kb < nkb; kb++) {
        if (kb + 1 < nkb) {
            ASTAGE((kb + 1) & 1, kb + 1);
            asm volatile("cp.async.wait_group 1;");
        } else {
            asm volatile("cp.async.wait_group 0;");
        }
        __syncthreads();

        const uint32_t* sKb = sK + (kb & 1) * 2048;
        const uint32_t* sVb = sV + (kb & 1) * 2048;

        float Sf[8][4];
        #pragma unroll
        for (int t = 0; t < 8; t++)
            #pragma unroll
            for (int i = 0; i < 4; i++) Sf[t][i] = 0.f;

        // S = Q K^T (single fp16 MMA per fragment pair)
        #pragma unroll
        for (int ck = 0; ck < 4; ck++) {
            #pragma unroll
            for (int t = 0; t < 8; t++) {
                int kv = 8 * t + (l >> 2);
                uint32_t bh[2];
                bh[0] = sKb[kv * 32 + fidx[ck][0]];
                bh[1] = sKb[kv * 32 + fidx[ck][1]];
                mma_f16(Sf[t], qh[ck], bh);
            }
        }

        if (kb >= qb) {
            #pragma unroll
            for (int t = 0; t < 8; t++) {
                int c0 = kb * KB + 8 * t + e * 2;
                if (c0     > r0) Sf[t][0] = -1e9f;
                if (c0 + 1 > r0) Sf[t][1] = -1e9f;
                if (c0     > r1) Sf[t][2] = -1e9f;
                if (c0 + 1 > r1) Sf[t][3] = -1e9f;
            }
        }

        uint32_t ph[4][4];
        #pragma unroll
        for (int t = 0; t < 8; t++) {
            float p0 = ex2f(Sf[t][0]);
            float p1 = ex2f(Sf[t][1]);
            float p2 = ex2f(Sf[t][2]);
            float p3 = ex2f(Sf[t][3]);
            l0 += p0 + p1;
            l1 += p2 + p3;
            ph[t >> 1][(t & 1) * 2 + 0] = packh2(p0, p1);
            ph[t >> 1][(t & 1) * 2 + 1] = packh2(p2, p3);
        }

        #pragma unroll
        for (int ck = 0; ck < 4; ck++) {
            #pragma unroll
            for (int td = 0; td < 8; td++) {
                int d = 8 * td + (l >> 2);
                uint32_t vh[2];
                vh[0] = sVb[d * 32 + fidx[ck][0]];
                vh[1] = sVb[d * 32 + fidx[ck][1]];
                mma_f16(O[td], ph[ck], vh);
            }
        }
        __syncthreads();
    }
    #undef ASTAGE

    l0 += __shfl_xor_sync(0xffffffffu, l0, 1);
    l0 += __shfl_xor_sync(0xffffffffu, l0, 2);
    l1 += __shfl_xor_sync(0xffffffffu, l1, 1);
    l1 += __shfl_xor_sync(0xffffffffu, l1, 2);

    const float inv0 = 1.f / l0, inv1 = 1.f / l1;
    #pragma unroll
    for (int td = 0; td < 8; td++) {
        int d0 = 8 * td + e * 2;
        int cp = (h * DV + d0) >> 1;
        ao[(size_t)(b * S_ + r0) * (DM / 2) + cp] = packh2(O[td][0] * inv0, O[td][1] * inv0);
        ao[(size_t)(b * S_ + r1) * (DM / 2) + cp] = packh2(O[td][2] * inv1, O[td][3] * inv1);
    }
}

// ---------------- launch -----------------------------------------------------------
#define QSCALE 0.1803368801111f   // (1/8) * log2(e)

extern "C" void kernel_launch(void* const* d_in, const int* in_sizes, int n_in,
                              void* d_out, int out_size)
{
    const float* Q  = (const float*)d_in[0];
    const float* K  = (const float*)d_in[1];
    const float* V  = (const float*)d_in[2];
    const float* Wq = (const float*)d_in[3];
    const float* Wk = (const float*)d_in[4];
    const float* Wv = (const float*)d_in[5];
    const float* Wo = (const float*)d_in[6];
    float* out = (float*)d_out;

    uint32_t *qc, *q16, *wq, *wo, *ao, *kc, *vc;
    cudaGetSymbolAddress((void**)&qc,  g_qc);
    cudaGetSymbolAddress((void**)&q16, g_q16);
    cudaGetSymbolAddress((void**)&wq,  g_wq);
    cudaGetSymbolAddress((void**)&wo,  g_wo);
    cudaGetSymbolAddress((void**)&ao,  g_ao);
    cudaGetSymbolAddress((void**)&kc,  g_kc);
    cudaGetSymbolAddress((void**)&vc,  g_vc);

    cudaFuncSetAttribute(mqa_attn_mma,
                         cudaFuncAttributeMaxDynamicSharedMemorySize, ASM_TOT);
    cudaFuncSetAttribute(gemm_f16,
                         cudaFuncAttributeMaxDynamicSharedMemorySize, GSM_TOT);

    // conversions (W_q pre-scaled by (1/8)*log2(e) for the exp2 softmax)
    conv_h   <<<(BS * DM / 2 + 255) / 256, 256>>>(Q, qc, BS * DM / 2);
    conv_wt_h<<<(DM * DM / 2 + 255) / 256, 256>>>(Wq, wq, DM, DM, QSCALE);
    conv_wt_h<<<(DM * DM / 2 + 255) / 256, 256>>>(Wo, wo, DM, DM, 1.0f);

    // Q projection -> fp16 pairs directly (attention A operand)
    gemm_f16<<<dim3(DM / 64, BS / 128), 128, GSM_TOT>>>(
        (const uint4*)qc, (const uint4*)wq, nullptr, q16, 1, BS, DM, DM);

    // K/V projections -> attention-format fp16 pairs
    sgemm_kv<<<dim3(1, BS / 64, 2), 256>>>(K, Wk, V, Wv, kc, vc);

    // attention (all single-plane fp16)
    mqa_attn_mma<<<dim3(S_ / QB, H_, B_), 128, ASM_TOT>>>(q16, ao);

    // output projection -> fp32
    gemm_f16<<<dim3(DM / 64, BS / 128), 128, GSM_TOT>>>(
        (const uint4*)ao, (const uint4*)wo, out, nullptr, 0, BS, DM, DM);
}

// round 16
// speedup vs baseline: 10.3996x; 1.1952x over previous
#include <cuda_runtime.h>
#include <cuda_fp16.h>
#include <cstdint>

#define B_  2
#define S_  2048
#define DM  1024
#define H_  16
#define DK  64
#define DV  64
#define BS  (B_*S_)   // 4096

// ---------------- scratch ----------------------------------------------------
__device__ uint32_t g_qc  [BS * DM / 2];     // input Q fp16 pairs
__device__ uint32_t g_kin [BS * DM / 2];     // input K fp16 pairs
__device__ uint32_t g_vin [BS * DM / 2];     // input V fp16 pairs
__device__ uint32_t g_q16 [BS * DM / 2];     // Q-proj out fp16 pairs (attn Q)
__device__ uint32_t g_wq  [DM * DM / 2];     // W_q^T fp16 pairs (pre-scaled)
__device__ uint32_t g_wo  [DM * DM / 2];     // W_o^T fp16 pairs
__device__ uint32_t g_wk  [DK * DM / 2];     // W_k^T fp16 pairs
__device__ uint32_t g_wv  [DV * DM / 2];     // W_v^T fp16 pairs
__device__ uint32_t g_ao  [BS * DM / 2];     // attention out fp16 pairs
__device__ uint32_t g_kc  [BS * DK / 2];     // K fp16 pairs, row=(b,s)
__device__ uint32_t g_vc  [B_ * DV * (S_ / 2)]; // V^T fp16 pairs, row=(b,d)

// ---------------- helpers ------------------------------------------------------
__device__ __forceinline__ uint32_t packh2(float x, float y) {
    __half2 h = __floats2half2_rn(x, y);
    return *reinterpret_cast<uint32_t*>(&h);
}

__device__ __forceinline__ void cp_async16(void* smem, const void* gmem) {
    uint32_t s = (uint32_t)__cvta_generic_to_shared(smem);
    asm volatile("cp.async.cg.shared.global [%0], [%1], 16;" :: "r"(s), "l"(gmem));
}

__device__ __forceinline__ uint32_t smem_u32(const void* p) {
    return (uint32_t)__cvta_generic_to_shared(p);
}

__device__ __forceinline__ float ex2f(float x) {
    float y;
    asm("ex2.approx.f32 %0, %1;" : "=f"(y) : "f"(x));
    return y;
}

__device__ __forceinline__ void mma_f16(float* d, const uint32_t* a, const uint32_t* b) {
    asm volatile(
        "mma.sync.aligned.m16n8k16.row.col.f32.f16.f16.f32 "
        "{%0,%1,%2,%3},{%4,%5,%6,%7},{%8,%9},{%0,%1,%2,%3};"
        : "+f"(d[0]), "+f"(d[1]), "+f"(d[2]), "+f"(d[3])
        : "r"(a[0]), "r"(a[1]), "r"(a[2]), "r"(a[3]), "r"(b[0]), "r"(b[1]));
}

__device__ __forceinline__ void ldsm_x4(uint32_t* r, uint32_t addr) {
    asm volatile("ldmatrix.sync.aligned.m8n8.x4.shared.b16 {%0,%1,%2,%3}, [%4];"
                 : "=r"(r[0]), "=r"(r[1]), "=r"(r[2]), "=r"(r[3]) : "r"(addr));
}

// ---------------- conversion kernels --------------------------------------------
__global__ __launch_bounds__(256)
void conv_h(const float* __restrict__ A, uint32_t* __restrict__ Ac, int npairs)
{
    int idx = blockIdx.x * blockDim.x + threadIdx.x;
    if (idx >= npairs) return;
    float2 p = ((const float2*)A)[idx];
    Ac[idx] = packh2(p.x, p.y);
}

__global__ __launch_bounds__(256)
void conv_wt_h(const float* __restrict__ W, uint32_t* __restrict__ Wt,
               int K, int N, float scale)
{
    int idx = blockIdx.x * blockDim.x + threadIdx.x;
    if (idx >= N * (K / 2)) return;
    int p = idx / N;
    int n = idx - p * N;
    float x = W[(size_t)(2 * p)     * N + n] * scale;
    float y = W[(size_t)(2 * p + 1) * N + n] * scale;
    Wt[(size_t)n * (K / 2) + p] = packh2(x, y);
}

// ---------------- fp16 GEMM with ldmatrix ----------------------------------------
// out_mode: 0 = fp32 C; 1 = fp16 pairs row-major; 2 = fp16 pairs TRANSPOSED
//           (V^T layout: Ch[(b*DV + n)*(S_/2) + s/2], requires Ntot == 64).
#define GSM_TOT 49152

__global__ __launch_bounds__(128, 3)
void gemm_f16(const uint4* __restrict__ A16, const uint4* __restrict__ B16,
              float* __restrict__ C, uint32_t* __restrict__ Ch, int out_mode,
              int M, int Ntot, int K)
{
    extern __shared__ __align__(128) char dsm[];
    const uint32_t sb = smem_u32(dsm);

    const int tid = threadIdx.x;
    const int l   = tid & 31;
    const int w   = tid >> 5;
    const int bn  = blockIdx.x * 64;
    const int bm  = blockIdx.y * 128;
    const int K8  = K >> 3;

    const int e = l & 3;
    const int q = l >> 2;

    const int rA0 = w * 32 + (l & 7) + ((l >> 3) & 1) * 8;
    const int jAh = (l >> 4) & 1;
    const int rB0 = (l & 7) + ((l >> 4) & 1) * 8;
    const int jBh = (l >> 3) & 1;
    const int cA  = rA0 & 7;
    const int cB  = rB0 & 7;

    float acc[2][8][4];
    #pragma unroll
    for (int i = 0; i < 2; i++)
        #pragma unroll
        for (int j = 0; j < 8; j++)
            #pragma unroll
            for (int t = 0; t < 4; t++) acc[i][j][t] = 0.f;

    #define STAGE(buf, k0)                                                          \
    {                                                                               \
        const int kq = (k0) >> 3;                                                   \
        _Pragma("unroll")                                                           \
        for (int i = 0; i < 8; i++) {                                               \
            int id = tid + 128 * i;                                                 \
            int r = id >> 3, j = id & 7;                                            \
            cp_async16(dsm + (buf) * 16384 + r * 128 + ((j ^ (r & 7)) << 4),        \
                       A16 + (size_t)(bm + r) * K8 + kq + j);                       \
        }                                                                           \
        _Pragma("unroll")                                                           \
        for (int i = 0; i < 4; i++) {                                               \
            int id = tid + 128 * i;                                                 \
            int r = id >> 3, j = id & 7;                                            \
            cp_async16(dsm + 32768 + (buf) * 8192 + r * 128                         \
                           + ((j ^ (r & 7)) << 4),                                  \
                       B16 + (size_t)(bn + r) * K8 + kq + j);                       \
        }                                                                           \
        asm volatile("cp.async.commit_group;");                                     \
    }

    const int niter = K / 64;
    STAGE(0, 0);

    for (int it = 0; it < niter; it++) {
        if (it + 1 < niter) {
            STAGE((it + 1) & 1, (it + 1) * 64);
            asm volatile("cp.async.wait_group 1;");
        } else {
            asm volatile("cp.async.wait_group 0;");
        }
        __syncthreads();

        const int buf = it & 1;
        const uint32_t aBase = sb + buf * 16384;
        const uint32_t bBase = sb + 32768 + buf * 8192;

        #pragma unroll
        for (int kk = 0; kk < 4; kk++) {
            const uint32_t offA = (uint32_t)(((2 * kk + jAh) ^ cA) << 4);
            const uint32_t offB = (uint32_t)(((2 * kk + jBh) ^ cB) << 4);

            uint32_t ah[2][4];
            #pragma unroll
            for (int mi = 0; mi < 2; mi++)
                ldsm_x4(ah[mi], aBase + (uint32_t)((rA0 + mi * 16) * 128) + offA);

            #pragma unroll
            for (int ni2 = 0; ni2 < 4; ni2++) {
                uint32_t bh4[4];
                ldsm_x4(bh4, bBase + (uint32_t)((rB0 + ni2 * 16) * 128) + offB);
                uint32_t bhE[2] = {bh4[0], bh4[1]};
                uint32_t bhO[2] = {bh4[2], bh4[3]};
                #pragma unroll
                for (int mi = 0; mi < 2; mi++) {
                    mma_f16(acc[mi][2 * ni2],     ah[mi], bhE);
                    mma_f16(acc[mi][2 * ni2 + 1], ah[mi], bhO);
                }
            }
        }
        __syncthreads();
    }
    #undef STAGE

    if (out_mode == 0) {
        #pragma unroll
        for (int mi = 0; mi < 2; mi++) {
            int r = bm + w * 32 + mi * 16 + q;
            #pragma unroll
            for (int ni = 0; ni < 8; ni++) {
                int c = bn + ni * 8 + e * 2;
                *(float2*)(C + (size_t)r * Ntot + c)       = make_float2(acc[mi][ni][0], acc[mi][ni][1]);
                *(float2*)(C + (size_t)(r + 8) * Ntot + c) = make_float2(acc[mi][ni][2], acc[mi][ni][3]);
            }
        }
    } else if (out_mode == 1) {
        const int Np = Ntot >> 1;
        #pragma unroll
        for (int mi = 0; mi < 2; mi++) {
            int r = bm + w * 32 + mi * 16 + q;
            #pragma unroll
            for (int ni = 0; ni < 8; ni++) {
                int cp = (bn + ni * 8 + e * 2) >> 1;
                Ch[(size_t)r * Np + cp]       = packh2(acc[mi][ni][0], acc[mi][ni][1]);
                Ch[(size_t)(r + 8) * Np + cp] = packh2(acc[mi][ni][2], acc[mi][ni][3]);
            }
        }
    } else {
        // transposed fp16 pairs via smem: Ch[(b*64 + n)*(S_/2) + s/2]
        __half* sT = (__half*)dsm;        // [64][136] halves (17.4KB)
        #pragma unroll
        for (int mi = 0; mi < 2; mi++) {
            int rl = w * 32 + mi * 16 + q;
            #pragma unroll
            for (int ni = 0; ni < 8; ni++) {
                int c = ni * 8 + e * 2;
                sT[(c)     * 136 + rl]     = __float2half_rn(acc[mi][ni][0]);
                sT[(c + 1) * 136 + rl]     = __float2half_rn(acc[mi][ni][1]);
                sT[(c)     * 136 + rl + 8] = __float2half_rn(acc[mi][ni][2]);
                sT[(c + 1) * 136 + rl + 8] = __float2half_rn(acc[mi][ni][3]);
            }
        }
        __syncthreads();
        const int bglob  = bm >> 11;           // batch (2048 rows per batch)
        const int spair0 = (bm & 2047) >> 1;
        #pragma unroll
        for (int i = 0; i < 32; i++) {
            int idx = tid + 128 * i;            // 0..4095
            int d = idx >> 6;
            int p = idx & 63;
            __half2 hv = __halves2half2(sT[d * 136 + 2 * p], sT[d * 136 + 2 * p + 1]);
            Ch[(size_t)(bglob * 64 + d) * (S_ / 2) + spair0 + p] =
                *reinterpret_cast<uint32_t*>(&hv);
        }
    }
}

// ---------------- mma flash attention: ldmatrix fragments -------------------------
// All operands single fp16 planes; Q pre-scaled by (1/8)*log2(e) via W_q.
// Per warp-tile: 32 LDSM.x4 + 64 MMA (was 128 LDS.32 + 64 MMA).
#define QB 64
#define KB 64
#define ASM_TOT 32768

__global__ __launch_bounds__(128, 3)
void mqa_attn_mma(const uint32_t* __restrict__ q16, uint32_t* __restrict__ ao)
{
    extern __shared__ __align__(16) uint32_t dsma[];
    // sK bytes [buf*8192, ...), sV bytes at +16384
    const uint32_t sbA = smem_u32(dsma);

    const int tid = threadIdx.x;
    const int l   = tid & 31;
    const int w   = tid >> 5;
    const int qb  = (S_ / QB - 1) - blockIdx.x;
    const int h   = blockIdx.y;
    const int b   = blockIdx.z;

    const int rowbase = qb * QB + w * 16;
    const int r0 = rowbase + (l >> 2);
    const int r1 = r0 + 8;
    const int e  = l & 3;

    // ldmatrix B-fragment geometry (same as GEMM, verified)
    const int rB0 = (l & 7) + ((l >> 4) & 1) * 8;
    const int jBh = (l >> 3) & 1;
    const int cB  = rB0 & 7;

    // Q fragments: direct fp16-pair loads (pre-scaled)
    uint32_t qh[4][4];
    {
        const uint32_t* qb0 = q16 + (size_t)(b * S_ + r0) * (DM / 2) + h * 32;
        const uint32_t* qb1 = q16 + (size_t)(b * S_ + r1) * (DM / 2) + h * 32;
        #pragma unroll
        for (int ck = 0; ck < 4; ck++) {
            qh[ck][0] = qb0[8 * ck + e];
            qh[ck][1] = qb1[8 * ck + e];
            qh[ck][2] = qb0[8 * ck + 4 + e];
            qh[ck][3] = qb1[8 * ck + 4 + e];
        }
    }

    float O[8][4];
    #pragma unroll
    for (int t = 0; t < 8; t++)
        #pragma unroll
        for (int i = 0; i < 4; i++) O[t][i] = 0.f;
    float l0 = 0.f, l1 = 0.f;

    const uint4* ksrc = (const uint4*)g_kc;
    const uint4* vsrc = (const uint4*)g_vc;
    uint32_t* sK = dsma;
    uint32_t* sV = dsma + 4096;

    #define ASTAGE(buf, kb_)                                                          \
    {                                                                                 \
        _Pragma("unroll")                                                             \
        for (int i = 0; i < 4; i++) {                                                 \
            int id = tid + 128 * i;                                                   \
            int r  = id >> 3;                                                         \
            int j  = id & 7;                                                          \
            int dg = ((j ^ (r & 7)) << 2);                                            \
            cp_async16(&sK[(buf) * 2048 + r * 32 + dg],                               \
                       &ksrc[((size_t)(b * S_ + (kb_) * KB + r)) * 8 + j]);           \
            cp_async16(&sV[(buf) * 2048 + r * 32 + dg],                               \
                       &vsrc[((size_t)(b * DV + r)) * (S_ / 8) + (kb_) * 8 + j]);     \
        }                                                                             \
        asm volatile("cp.async.commit_group;");                                       \
    }

    const int nkb = qb + 1;
    ASTAGE(0, 0);

    for (int kb = 0; kb < nkb; kb++) {
        if (kb + 1 < nkb) {
            ASTAGE((kb + 1) & 1, kb + 1);
            asm volatile("cp.async.wait_group 1;");
        } else {
            asm volatile("cp.async.wait_group 0;");
        }
        __syncthreads();

        const uint32_t kBase = sbA + (kb & 1) * 8192;
        const uint32_t vBase = sbA + 16384 + (kb & 1) * 8192;

        float Sf[8][4];
        #pragma unroll
        for (int t = 0; t < 8; t++)
            #pragma unroll
            for (int i = 0; i < 4; i++) Sf[t][i] = 0.f;

        // S = Q K^T : B-frags from sK via ldmatrix
        #pragma unroll
        for (int kk = 0; kk < 4; kk++) {
            const uint32_t offB = (uint32_t)(((2 * kk + jBh) ^ cB) << 4);
            #pragma unroll
            for (int ni2 = 0; ni2 < 4; ni2++) {
                uint32_t b4[4];
                ldsm_x4(b4, kBase + (uint32_t)((rB0 + ni2 * 16) * 128) + offB);
                uint32_t bE[2] = {b4[0], b4[1]};
                uint32_t bO[2] = {b4[2], b4[3]};
                mma_f16(Sf[2 * ni2],     qh[kk], bE);
                mma_f16(Sf[2 * ni2 + 1], qh[kk], bO);
            }
        }

        if (kb >= qb) {          // diagonal tile
            #pragma unroll
            for (int t = 0; t < 8; t++) {
                int c0 = kb * KB + 8 * t + e * 2;
                if (c0     > r0) Sf[t][0] = -1e9f;
                if (c0 + 1 > r0) Sf[t][1] = -1e9f;
                if (c0     > r1) Sf[t][2] = -1e9f;
                if (c0 + 1 > r1) Sf[t][3] = -1e9f;
            }
        }

        uint32_t ph[4][4];
        #pragma unroll
        for (int t = 0; t < 8; t++) {
            float p0 = ex2f(Sf[t][0]);
            float p1 = ex2f(Sf[t][1]);
            float p2 = ex2f(Sf[t][2]);
            float p3 = ex2f(Sf[t][3]);
            l0 += p0 + p1;
            l1 += p2 + p3;
            ph[t >> 1][(t & 1) * 2 + 0] = packh2(p0, p1);
            ph[t >> 1][(t & 1) * 2 + 1] = packh2(p2, p3);
        }

        // O += P V : B-frags from sV via ldmatrix (k-dim = kv -> ck)
        #pragma unroll
        for (int ck = 0; ck < 4; ck++) {
            const uint32_t offB = (uint32_t)(((2 * ck + jBh) ^ cB) << 4);
            #pragma unroll
            for (int ni2 = 0; ni2 < 4; ni2++) {
                uint32_t b4[4];
                ldsm_x4(b4, vBase + (uint32_t)((rB0 + ni2 * 16) * 128) + offB);
                uint32_t bE[2] = {b4[0], b4[1]};
                uint32_t bO[2] = {b4[2], b4[3]};
                mma_f16(O[2 * ni2],     ph[ck], bE);
                mma_f16(O[2 * ni2 + 1], ph[ck], bO);
            }
        }
        __syncthreads();
    }
    #undef ASTAGE

    l0 += __shfl_xor_sync(0xffffffffu, l0, 1);
    l0 += __shfl_xor_sync(0xffffffffu, l0, 2);
    l1 += __shfl_xor_sync(0xffffffffu, l1, 1);
    l1 += __shfl_xor_sync(0xffffffffu, l1, 2);

    const float inv0 = 1.f / l0, inv1 = 1.f / l1;
    #pragma unroll
    for (int td = 0; td < 8; td++) {
        int d0 = 8 * td + e * 2;
        int cp = (h * DV + d0) >> 1;
        ao[(size_t)(b * S_ + r0) * (DM / 2) + cp] = packh2(O[td][0] * inv0, O[td][1] * inv0);
        ao[(size_t)(b * S_ + r1) * (DM / 2) + cp] = packh2(O[td][2] * inv1, O[td][3] * inv1);
    }
}

// ---------------- launch -----------------------------------------------------------
#define QSCALE 0.1803368801111f   // (1/8) * log2(e)

extern "C" void kernel_launch(void* const* d_in, const int* in_sizes, int n_in,
                              void* d_out, int out_size)
{
    const float* Q  = (const float*)d_in[0];
    const float* K  = (const float*)d_in[1];
    const float* V  = (const float*)d_in[2];
    const float* Wq = (const float*)d_in[3];
    const float* Wk = (const float*)d_in[4];
    const float* Wv = (const float*)d_in[5];
    const float* Wo = (const float*)d_in[6];
    float* out = (float*)d_out;

    uint32_t *qc, *kin, *vin, *q16, *wq, *wo, *wk, *wv, *ao, *kc, *vc;
    cudaGetSymbolAddress((void**)&qc,  g_qc);
    cudaGetSymbolAddress((void**)&kin, g_kin);
    cudaGetSymbolAddress((void**)&vin, g_vin);
    cudaGetSymbolAddress((void**)&q16, g_q16);
    cudaGetSymbolAddress((void**)&wq,  g_wq);
    cudaGetSymbolAddress((void**)&wo,  g_wo);
    cudaGetSymbolAddress((void**)&wk,  g_wk);
    cudaGetSymbolAddress((void**)&wv,  g_wv);
    cudaGetSymbolAddress((void**)&ao,  g_ao);
    cudaGetSymbolAddress((void**)&kc,  g_kc);
    cudaGetSymbolAddress((void**)&vc,  g_vc);

    cudaFuncSetAttribute(mqa_attn_mma,
                         cudaFuncAttributeMaxDynamicSharedMemorySize, ASM_TOT);
    cudaFuncSetAttribute(gemm_f16,
                         cudaFuncAttributeMaxDynamicSharedMemorySize, GSM_TOT);

    // conversions
    conv_h   <<<(BS * DM / 2 + 255) / 256, 256>>>(Q, qc,  BS * DM / 2);
    conv_h   <<<(BS * DM / 2 + 255) / 256, 256>>>(K, kin, BS * DM / 2);
    conv_h   <<<(BS * DM / 2 + 255) / 256, 256>>>(V, vin, BS * DM / 2);
    conv_wt_h<<<(DM * DM / 2 + 255) / 256, 256>>>(Wq, wq, DM, DM, QSCALE);
    conv_wt_h<<<(DM * DM / 2 + 255) / 256, 256>>>(Wo, wo, DM, DM, 1.0f);
    conv_wt_h<<<(DK * DM / 2 + 255) / 256, 256>>>(Wk, wk, DM, DK, 1.0f);
    conv_wt_h<<<(DV * DM / 2 + 255) / 256, 256>>>(Wv, wv, DM, DV, 1.0f);

    // Q projection -> fp16 pairs (attention A operand)
    gemm_f16<<<dim3(DM / 64, BS / 128), 128, GSM_TOT>>>(
        (const uint4*)qc, (const uint4*)wq, nullptr, q16, 1, BS, DM, DM);

    // K projection -> kc (row-major fp16 pairs)
    gemm_f16<<<dim3(1, BS / 128), 128, GSM_TOT>>>(
        (const uint4*)kin, (const uint4*)wk, nullptr, kc, 1, BS, DK, DM);

    // V projection -> vc (transposed fp16 pairs)
    gemm_f16<<<dim3(1, BS / 128), 128, GSM_TOT>>>(
        (const uint4*)vin, (const uint4*)wv, nullptr, vc, 2, BS, DV, DM);

    // attention (ldmatrix fragments, all single-plane fp16)
    mqa_attn_mma<<<dim3(S_ / QB, H_, B_), 128, ASM_TOT>>>(q16, ao);

    // output projection -> fp32
    gemm_f16<<<dim3(DM / 64, BS / 128), 128, GSM_TOT>>>(
        (const uint4*)ao, (const uint4*)wo, out, nullptr, 0, BS, DM, DM);
}

// round 17
// speedup vs baseline: 11.0844x; 1.0658x over previous
#include <cuda_runtime.h>
#include <cuda_fp16.h>
#include <cstdint>

#define B_  2
#define S_  2048
#define DM  1024
#define H_  16
#define DK  64
#define DV  64
#define BS  (B_*S_)   // 4096

// ---------------- scratch ----------------------------------------------------
__device__ uint32_t g_qc  [BS * DM / 2];     // input Q fp16 pairs
__device__ uint32_t g_kin [BS * DM / 2];     // input K fp16 pairs
__device__ uint32_t g_vin [BS * DM / 2];     // input V fp16 pairs
__device__ uint32_t g_q16 [BS * DM / 2];     // Q-proj out fp16 pairs (attn Q)
__device__ uint32_t g_wq  [DM * DM / 2];     // W_q^T fp16 pairs (pre-scaled)
__device__ uint32_t g_wo  [DM * DM / 2];     // W_o^T fp16 pairs
__device__ uint32_t g_wk  [DK * DM / 2];     // W_k^T fp16 pairs
__device__ uint32_t g_wv  [DV * DM / 2];     // W_v^T fp16 pairs
__device__ uint32_t g_ao  [BS * DM / 2];     // attention out fp16 pairs
__device__ uint32_t g_kc  [BS * DK / 2];     // K fp16 pairs, row=(b,s)
__device__ uint32_t g_vc  [B_ * DV * (S_ / 2)]; // V^T fp16 pairs, row=(b,d)

// ---------------- helpers ------------------------------------------------------
__device__ __forceinline__ uint32_t packh2(float x, float y) {
    __half2 h = __floats2half2_rn(x, y);
    return *reinterpret_cast<uint32_t*>(&h);
}

__device__ __forceinline__ void cp_async16(void* smem, const void* gmem) {
    uint32_t s = (uint32_t)__cvta_generic_to_shared(smem);
    asm volatile("cp.async.cg.shared.global [%0], [%1], 16;" :: "r"(s), "l"(gmem));
}

__device__ __forceinline__ uint32_t smem_u32(const void* p) {
    return (uint32_t)__cvta_generic_to_shared(p);
}

__device__ __forceinline__ float ex2f(float x) {
    float y;
    asm("ex2.approx.f32 %0, %1;" : "=f"(y) : "f"(x));
    return y;
}

__device__ __forceinline__ void mma_f16(float* d, const uint32_t* a, const uint32_t* b) {
    asm volatile(
        "mma.sync.aligned.m16n8k16.row.col.f32.f16.f16.f32 "
        "{%0,%1,%2,%3},{%4,%5,%6,%7},{%8,%9},{%0,%1,%2,%3};"
        : "+f"(d[0]), "+f"(d[1]), "+f"(d[2]), "+f"(d[3])
        : "r"(a[0]), "r"(a[1]), "r"(a[2]), "r"(a[3]), "r"(b[0]), "r"(b[1]));
}

__device__ __forceinline__ void ldsm_x4(uint32_t* r, uint32_t addr) {
    asm volatile("ldmatrix.sync.aligned.m8n8.x4.shared.b16 {%0,%1,%2,%3}, [%4];"
                 : "=r"(r[0]), "=r"(r[1]), "=r"(r[2]), "=r"(r[3]) : "r"(addr));
}

#define QSCALE 0.1803368801111f   // (1/8) * log2(e)

// ---------------- fused conversion kernels ----------------------------------------
// Q, K, V inputs -> fp16 pairs, one launch (z selects tensor)
__global__ __launch_bounds__(256)
void conv3_h(const float* __restrict__ Q, const float* __restrict__ K,
             const float* __restrict__ V, uint32_t* __restrict__ qc,
             uint32_t* __restrict__ kin, uint32_t* __restrict__ vin, int npairs)
{
    int idx = blockIdx.x * blockDim.x + threadIdx.x;
    if (idx >= npairs) return;
    const float* src = (blockIdx.z == 0) ? Q : (blockIdx.z == 1) ? K : V;
    uint32_t*    dst = (blockIdx.z == 0) ? qc : (blockIdx.z == 1) ? kin : vin;
    float2 p = ((const float2*)src)[idx];
    dst[idx] = packh2(p.x, p.y);
}

// All 4 weights W [K=DM][N] -> W^T fp16 pairs [N][K/2], tiled smem transpose.
// z: 0=Wq(scaled) 1=Wo 2=Wk 3=Wv. grid (K/64, max(N)/64, 4); small-N blocks exit.
__global__ __launch_bounds__(256)
void conv_wt_all(const float* __restrict__ Wq, const float* __restrict__ Wo,
                 const float* __restrict__ Wk, const float* __restrict__ Wv,
                 uint32_t* __restrict__ wq, uint32_t* __restrict__ wo,
                 uint32_t* __restrict__ wk, uint32_t* __restrict__ wv)
{
    __shared__ float sm[64][65];

    const int z = blockIdx.z;
    const float* W  = (z == 0) ? Wq : (z == 1) ? Wo : (z == 2) ? Wk : Wv;
    uint32_t*    Wt = (z == 0) ? wq : (z == 1) ? wo : (z == 2) ? wk : wv;
    const int    N  = (z < 2) ? DM : 64;
    const float  sc = (z == 0) ? QSCALE : 1.0f;
    if ((int)(blockIdx.y * 64) >= N) return;

    const int tid = threadIdx.x;
    const int k0  = blockIdx.x * 64;
    const int n0  = blockIdx.y * 64;

    // coalesced read: 64x64 tile of W [K][N]
    #pragma unroll
    for (int i = 0; i < 16; i++) {
        int idx = tid + 256 * i;       // 0..4095
        int kr  = idx >> 6;
        int c   = idx & 63;
        sm[kr][c] = W[(size_t)(k0 + kr) * N + n0 + c];
    }
    __syncthreads();

    // coalesced write: 64 n-rows x 32 kpairs
    #pragma unroll
    for (int j = 0; j < 8; j++) {
        int nl = j * 8 + (tid >> 5);
        int p  = tid & 31;
        uint32_t v = packh2(sm[2 * p][nl] * sc, sm[2 * p + 1][nl] * sc);
        Wt[(size_t)(n0 + nl) * (DM / 2) + (k0 >> 1) + p] = v;
    }
}

// ---------------- fp16 GEMM with ldmatrix ----------------------------------------
// out_mode: 0 = fp32 C; 1 = fp16 pairs row-major; 2 = fp16 pairs TRANSPOSED
//           (V^T layout: Ch[(b*DV + n)*(S_/2) + s/2], requires Ntot == 64).
#define GSM_TOT 49152

__global__ __launch_bounds__(128, 3)
void gemm_f16(const uint4* __restrict__ A16, const uint4* __restrict__ B16,
              float* __restrict__ C, uint32_t* __restrict__ Ch, int out_mode,
              int M, int Ntot, int K)
{
    extern __shared__ __align__(128) char dsm[];
    const uint32_t sb = smem_u32(dsm);

    const int tid = threadIdx.x;
    const int l   = tid & 31;
    const int w   = tid >> 5;
    const int bn  = blockIdx.x * 64;
    const int bm  = blockIdx.y * 128;
    const int K8  = K >> 3;

    const int e = l & 3;
    const int q = l >> 2;

    const int rA0 = w * 32 + (l & 7) + ((l >> 3) & 1) * 8;
    const int jAh = (l >> 4) & 1;
    const int rB0 = (l & 7) + ((l >> 4) & 1) * 8;
    const int jBh = (l >> 3) & 1;
    const int cA  = rA0 & 7;
    const int cB  = rB0 & 7;

    float acc[2][8][4];
    #pragma unroll
    for (int i = 0; i < 2; i++)
        #pragma unroll
        for (int j = 0; j < 8; j++)
            #pragma unroll
            for (int t = 0; t < 4; t++) acc[i][j][t] = 0.f;

    #define STAGE(buf, k0)                                                          \
    {                                                                               \
        const int kq = (k0) >> 3;                                                   \
        _Pragma("unroll")                                                           \
        for (int i = 0; i < 8; i++) {                                               \
            int id = tid + 128 * i;                                                 \
            int r = id >> 3, j = id & 7;                                            \
            cp_async16(dsm + (buf) * 16384 + r * 128 + ((j ^ (r & 7)) << 4),        \
                       A16 + (size_t)(bm + r) * K8 + kq + j);                       \
        }                                                                           \
        _Pragma("unroll")                                                           \
        for (int i = 0; i < 4; i++) {                                               \
            int id = tid + 128 * i;                                                 \
            int r = id >> 3, j = id & 7;                                            \
            cp_async16(dsm + 32768 + (buf) * 8192 + r * 128                         \
                           + ((j ^ (r & 7)) << 4),                                  \
                       B16 + (size_t)(bn + r) * K8 + kq + j);                       \
        }                                                                           \
        asm volatile("cp.async.commit_group;");                                     \
    }

    const int niter = K / 64;
    STAGE(0, 0);

    for (int it = 0; it < niter; it++) {
        if (it + 1 < niter) {
            STAGE((it + 1) & 1, (it + 1) * 64);
            asm volatile("cp.async.wait_group 1;");
        } else {
            asm volatile("cp.async.wait_group 0;");
        }
        __syncthreads();

        const int buf = it & 1;
        const uint32_t aBase = sb + buf * 16384;
        const uint32_t bBase = sb + 32768 + buf * 8192;

        #pragma unroll
        for (int kk = 0; kk < 4; kk++) {
            const uint32_t offA = (uint32_t)(((2 * kk + jAh) ^ cA) << 4);
            const uint32_t offB = (uint32_t)(((2 * kk + jBh) ^ cB) << 4);

            uint32_t ah[2][4];
            #pragma unroll
            for (int mi = 0; mi < 2; mi++)
                ldsm_x4(ah[mi], aBase + (uint32_t)((rA0 + mi * 16) * 128) + offA);

            #pragma unroll
            for (int ni2 = 0; ni2 < 4; ni2++) {
                uint32_t bh4[4];
                ldsm_x4(bh4, bBase + (uint32_t)((rB0 + ni2 * 16) * 128) + offB);
                uint32_t bhE[2] = {bh4[0], bh4[1]};
                uint32_t bhO[2] = {bh4[2], bh4[3]};
                #pragma unroll
                for (int mi = 0; mi < 2; mi++) {
                    mma_f16(acc[mi][2 * ni2],     ah[mi], bhE);
                    mma_f16(acc[mi][2 * ni2 + 1], ah[mi], bhO);
                }
            }
        }
        __syncthreads();
    }
    #undef STAGE

    if (out_mode == 0) {
        #pragma unroll
        for (int mi = 0; mi < 2; mi++) {
            int r = bm + w * 32 + mi * 16 + q;
            #pragma unroll
            for (int ni = 0; ni < 8; ni++) {
                int c = bn + ni * 8 + e * 2;
                *(float2*)(C + (size_t)r * Ntot + c)       = make_float2(acc[mi][ni][0], acc[mi][ni][1]);
                *(float2*)(C + (size_t)(r + 8) * Ntot + c) = make_float2(acc[mi][ni][2], acc[mi][ni][3]);
            }
        }
    } else if (out_mode == 1) {
        const int Np = Ntot >> 1;
        #pragma unroll
        for (int mi = 0; mi < 2; mi++) {
            int r = bm + w * 32 + mi * 16 + q;
            #pragma unroll
            for (int ni = 0; ni < 8; ni++) {
                int cp = (bn + ni * 8 + e * 2) >> 1;
                Ch[(size_t)r * Np + cp]       = packh2(acc[mi][ni][0], acc[mi][ni][1]);
                Ch[(size_t)(r + 8) * Np + cp] = packh2(acc[mi][ni][2], acc[mi][ni][3]);
            }
        }
    } else {
        // transposed fp16 pairs via smem: Ch[(b*64 + n)*(S_/2) + s/2]
        __half* sT = (__half*)dsm;        // [64][136] halves
        #pragma unroll
        for (int mi = 0; mi < 2; mi++) {
            int rl = w * 32 + mi * 16 + q;
            #pragma unroll
            for (int ni = 0; ni < 8; ni++) {
                int c = ni * 8 + e * 2;
                sT[(c)     * 136 + rl]     = __float2half_rn(acc[mi][ni][0]);
                sT[(c + 1) * 136 + rl]     = __float2half_rn(acc[mi][ni][1]);
                sT[(c)     * 136 + rl + 8] = __float2half_rn(acc[mi][ni][2]);
                sT[(c + 1) * 136 + rl + 8] = __float2half_rn(acc[mi][ni][3]);
            }
        }
        __syncthreads();
        const int bglob  = bm >> 11;
        const int spair0 = (bm & 2047) >> 1;
        #pragma unroll
        for (int i = 0; i < 32; i++) {
            int idx = tid + 128 * i;
            int d = idx >> 6;
            int p = idx & 63;
            __half2 hv = __halves2half2(sT[d * 136 + 2 * p], sT[d * 136 + 2 * p + 1]);
            Ch[(size_t)(bglob * 64 + d) * (S_ / 2) + spair0 + p] =
                *reinterpret_cast<uint32_t*>(&hv);
        }
    }
}

// ---------------- mma flash attention (unchanged from R16) ------------------------
#define QB 64
#define KB 64
#define ASM_TOT 32768

__global__ __launch_bounds__(128, 3)
void mqa_attn_mma(const uint32_t* __restrict__ q16, uint32_t* __restrict__ ao)
{
    extern __shared__ __align__(16) uint32_t dsma[];
    const uint32_t sbA = smem_u32(dsma);

    const int tid = threadIdx.x;
    const int l   = tid & 31;
    const int w   = tid >> 5;
    const int qb  = (S_ / QB - 1) - blockIdx.x;
    const int h   = blockIdx.y;
    const int b   = blockIdx.z;

    const int rowbase = qb * QB + w * 16;
    const int r0 = rowbase + (l >> 2);
    const int r1 = r0 + 8;
    const int e  = l & 3;

    const int rB0 = (l & 7) + ((l >> 4) & 1) * 8;
    const int jBh = (l >> 3) & 1;
    const int cB  = rB0 & 7;

    uint32_t qh[4][4];
    {
        const uint32_t* qb0 = q16 + (size_t)(b * S_ + r0) * (DM / 2) + h * 32;
        const uint32_t* qb1 = q16 + (size_t)(b * S_ + r1) * (DM / 2) + h * 32;
        #pragma unroll
        for (int ck = 0; ck < 4; ck++) {
            qh[ck][0] = qb0[8 * ck + e];
            qh[ck][1] = qb1[8 * ck + e];
            qh[ck][2] = qb0[8 * ck + 4 + e];
            qh[ck][3] = qb1[8 * ck + 4 + e];
        }
    }

    float O[8][4];
    #pragma unroll
    for (int t = 0; t < 8; t++)
        #pragma unroll
        for (int i = 0; i < 4; i++) O[t][i] = 0.f;
    float l0 = 0.f, l1 = 0.f;

    const uint4* ksrc = (const uint4*)g_kc;
    const uint4* vsrc = (const uint4*)g_vc;
    uint32_t* sK = dsma;
    uint32_t* sV = dsma + 4096;

    #define ASTAGE(buf, kb_)                                                          \
    {                                                                                 \
        _Pragma("unroll")                                                             \
        for (int i = 0; i < 4; i++) {                                                 \
            int id = tid + 128 * i;                                                   \
            int r  = id >> 3;                                                         \
            int j  = id & 7;                                                          \
            int dg = ((j ^ (r & 7)) << 2);                                            \
            cp_async16(&sK[(buf) * 2048 + r * 32 + dg],                               \
                       &ksrc[((size_t)(b * S_ + (kb_) * KB + r)) * 8 + j]);           \
            cp_async16(&sV[(buf) * 2048 + r * 32 + dg],                               \
                       &vsrc[((size_t)(b * DV + r)) * (S_ / 8) + (kb_) * 8 + j]);     \
        }                                                                             \
        asm volatile("cp.async.commit_group;");                                       \
    }

    const int nkb = qb + 1;
    ASTAGE(0, 0);

    for (int kb = 0; kb < nkb; kb++) {
        if (kb + 1 < nkb) {
            ASTAGE((kb + 1) & 1, kb + 1);
            asm volatile("cp.async.wait_group 1;");
        } else {
            asm volatile("cp.async.wait_group 0;");
        }
        __syncthreads();

        const uint32_t kBase = sbA + (kb & 1) * 8192;
        const uint32_t vBase = sbA + 16384 + (kb & 1) * 8192;

        float Sf[8][4];
        #pragma unroll
        for (int t = 0; t < 8; t++)
            #pragma unroll
            for (int i = 0; i < 4; i++) Sf[t][i] = 0.f;

        #pragma unroll
        for (int kk = 0; kk < 4; kk++) {
            const uint32_t offB = (uint32_t)(((2 * kk + jBh) ^ cB) << 4);
            #pragma unroll
            for (int ni2 = 0; ni2 < 4; ni2++) {
                uint32_t b4[4];
                ldsm_x4(b4, kBase + (uint32_t)((rB0 + ni2 * 16) * 128) + offB);
                uint32_t bE[2] = {b4[0], b4[1]};
                uint32_t bO[2] = {b4[2], b4[3]};
                mma_f16(Sf[2 * ni2],     qh[kk], bE);
                mma_f16(Sf[2 * ni2 + 1], qh[kk], bO);
            }
        }

        if (kb >= qb) {
            #pragma unroll
            for (int t = 0; t < 8; t++) {
                int c0 = kb * KB + 8 * t + e * 2;
                if (c0     > r0) Sf[t][0] = -1e9f;
                if (c0 + 1 > r0) Sf[t][1] = -1e9f;
                if (c0     > r1) Sf[t][2] = -1e9f;
                if (c0 + 1 > r1) Sf[t][3] = -1e9f;
            }
        }

        uint32_t ph[4][4];
        #pragma unroll
        for (int t = 0; t < 8; t++) {
            float p0 = ex2f(Sf[t][0]);
            float p1 = ex2f(Sf[t][1]);
            float p2 = ex2f(Sf[t][2]);
            float p3 = ex2f(Sf[t][3]);
            l0 += p0 + p1;
            l1 += p2 + p3;
            ph[t >> 1][(t & 1) * 2 + 0] = packh2(p0, p1);
            ph[t >> 1][(t & 1) * 2 + 1] = packh2(p2, p3);
        }

        #pragma unroll
        for (int ck = 0; ck < 4; ck++) {
            const uint32_t offB = (uint32_t)(((2 * ck + jBh) ^ cB) << 4);
            #pragma unroll
            for (int ni2 = 0; ni2 < 4; ni2++) {
                uint32_t b4[4];
                ldsm_x4(b4, vBase + (uint32_t)((rB0 + ni2 * 16) * 128) + offB);
                uint32_t bE[2] = {b4[0], b4[1]};
                uint32_t bO[2] = {b4[2], b4[3]};
                mma_f16(O[2 * ni2],     ph[ck], bE);
                mma_f16(O[2 * ni2 + 1], ph[ck], bO);
            }
        }
        __syncthreads();
    }
    #undef ASTAGE

    l0 += __shfl_xor_sync(0xffffffffu, l0, 1);
    l0 += __shfl_xor_sync(0xffffffffu, l0, 2);
    l1 += __shfl_xor_sync(0xffffffffu, l1, 1);
    l1 += __shfl_xor_sync(0xffffffffu, l1, 2);

    const float inv0 = 1.f / l0, inv1 = 1.f / l1;
    #pragma unroll
    for (int td = 0; td < 8; td++) {
        int d0 = 8 * td + e * 2;
        int cp = (h * DV + d0) >> 1;
        ao[(size_t)(b * S_ + r0) * (DM / 2) + cp] = packh2(O[td][0] * inv0, O[td][1] * inv0);
        ao[(size_t)(b * S_ + r1) * (DM / 2) + cp] = packh2(O[td][2] * inv1, O[td][3] * inv1);
    }
}

// ---------------- launch -----------------------------------------------------------
extern "C" void kernel_launch(void* const* d_in, const int* in_sizes, int n_in,
                              void* d_out, int out_size)
{
    const float* Q  = (const float*)d_in[0];
    const float* K  = (const float*)d_in[1];
    const float* V  = (const float*)d_in[2];
    const float* Wq = (const float*)d_in[3];
    const float* Wk = (const float*)d_in[4];
    const float* Wv = (const float*)d_in[5];
    const float* Wo = (const float*)d_in[6];
    float* out = (float*)d_out;

    uint32_t *qc, *kin, *vin, *q16, *wq, *wo, *wk, *wv, *ao, *kc, *vc;
    cudaGetSymbolAddress((void**)&qc,  g_qc);
    cudaGetSymbolAddress((void**)&kin, g_kin);
    cudaGetSymbolAddress((void**)&vin, g_vin);
    cudaGetSymbolAddress((void**)&q16, g_q16);
    cudaGetSymbolAddress((void**)&wq,  g_wq);
    cudaGetSymbolAddress((void**)&wo,  g_wo);
    cudaGetSymbolAddress((void**)&wk,  g_wk);
    cudaGetSymbolAddress((void**)&wv,  g_wv);
    cudaGetSymbolAddress((void**)&ao,  g_ao);
    cudaGetSymbolAddress((void**)&kc,  g_kc);
    cudaGetSymbolAddress((void**)&vc,  g_vc);

    cudaFuncSetAttribute(mqa_attn_mma,
                         cudaFuncAttributeMaxDynamicSharedMemorySize, ASM_TOT);
    cudaFuncSetAttribute(gemm_f16,
                         cudaFuncAttributeMaxDynamicSharedMemorySize, GSM_TOT);

    // fused conversions: inputs (1 launch) + all weights (1 launch)
    conv3_h<<<dim3((BS * DM / 2 + 255) / 256, 1, 3), 256>>>(
        Q, K, V, qc, kin, vin, BS * DM / 2);
    conv_wt_all<<<dim3(DM / 64, DM / 64, 4), 256>>>(
        Wq, Wo, Wk, Wv, wq, wo, wk, wv);

    // Q projection -> fp16 pairs (attention A operand)
    gemm_f16<<<dim3(DM / 64, BS / 128), 128, GSM_TOT>>>(
        (const uint4*)qc, (const uint4*)wq, nullptr, q16, 1, BS, DM, DM);

    // K projection -> kc (row-major fp16 pairs)
    gemm_f16<<<dim3(1, BS / 128), 128, GSM_TOT>>>(
        (const uint4*)kin, (const uint4*)wk, nullptr, kc, 1, BS, DK, DM);

    // V projection -> vc (transposed fp16 pairs)
    gemm_f16<<<dim3(1, BS / 128), 128, GSM_TOT>>>(
        (const uint4*)vin, (const uint4*)wv, nullptr, vc, 2, BS, DV, DM);

    // attention (ldmatrix fragments, all single-plane fp16)
    mqa_attn_mma<<<dim3(S_ / QB, H_, B_), 128, ASM_TOT>>>(q16, ao);

    // output projection -> fp32
    gemm_f16<<<dim3(DM / 64, BS / 128), 128, GSM_TOT>>>(
        (const uint4*)ao, (const uint4*)wo, out, nullptr, 0, BS, DM, DM);
}